// round 5
// baseline (speedup 1.0000x reference)
#include <cuda_runtime.h>
#include <cuda_bf16.h>
#include <cstdint>
#include <math.h>

#define N_NODES 50000
#define N_EDGES 400000
#define E_TOT   450000
#define IN_CH   814
#define KP1     832          /* 814 padded to 13*64 */
#define HID     128
#define HEADS1  4
#define D1      (HEADS1*HID) /* 512 */
#define NUM_CLASSES 46
#define NUM_GRAPHS  64
#define NEG_SLOPE   0.2f

#if defined(__CUDA_ARCH_FEAT_SM103_ALL) || defined(__CUDA_ARCH_FEAT_SM100_ALL)
#define HAS_TC 1
#else
#define HAS_TC 0
#endif

// ---------------- scratch ------------------------------------------------------
__device__ float g_h1[N_NODES * D1];
__device__ float g_out1[N_NODES * D1];
__device__ float g_h2[N_NODES * HID];
__device__ float g_out2[N_NODES * HID];
__device__ __nv_bfloat16 g_b1h[D1 * KP1];   // W1^T hi
__device__ __nv_bfloat16 g_b1l[D1 * KP1];   // W1^T lo
__device__ __nv_bfloat16 g_b2h[HID * D1];   // W2^T hi
__device__ __nv_bfloat16 g_b2l[HID * D1];   // W2^T lo
__device__ float g_als1[N_NODES * HEADS1];
__device__ float g_ald1[N_NODES * HEADS1];
__device__ float g_als2[N_NODES];
__device__ float g_ald2[N_NODES];
__device__ int   g_counts[N_NODES];
__device__ int   g_offsets[N_NODES + 1];
__device__ int   g_cursor[N_NODES];
__device__ int   g_src_sorted[E_TOT];
__device__ float g_alpha1[E_TOT * HEADS1];
__device__ float g_alpha2[E_TOT];
__device__ float g_pool[NUM_GRAPHS * HID];
__device__ int   g_cnt[NUM_GRAPHS];

// ---------------- PTX helpers ----------------------------------------------------
#if HAS_TC
__device__ __forceinline__ uint32_t smem_u32(const void* p) {
    uint32_t a;
    asm("{ .reg .u64 t; cvta.to.shared.u64 t, %1; cvt.u32.u64 %0, t; }" : "=r"(a) : "l"(p));
    return a;
}
__device__ __forceinline__ uint32_t elect_one() {
    uint32_t pred;
    asm volatile("{ .reg .pred p; elect.sync _|p, 0xFFFFFFFF; selp.b32 %0, 1, 0, p; }" : "=r"(pred));
    return pred;
}
#define MBAR_INIT(a, n)  asm volatile("mbarrier.init.shared.b64 [%0], %1;" :: "r"(a), "r"((uint32_t)(n)) : "memory")
#define MBAR_WAIT(a, ph) do { \
    uint32_t _m = (a), _p = (ph), _d; \
    asm volatile("{ .reg .pred p; mbarrier.try_wait.parity.acquire.cta.shared::cta.b64 p, [%1], %2; selp.b32 %0,1,0,p; }" \
        : "=r"(_d) : "r"(_m), "r"(_p) : "memory"); \
    if (!_d) { \
        asm volatile("{ .reg .pred P1;\nWL_%=:\nmbarrier.try_wait.parity.acquire.cta.shared::cta.b64 P1, [%0], %1, 0x989680;\n@P1 bra.uni WD_%=;\nbra.uni WL_%=;\nWD_%=:\n}" \
            :: "r"(_m), "r"(_p) : "memory"); \
    } } while (0)
#define TC_ALLOC(sa, n)   asm volatile("tcgen05.alloc.cta_group::1.sync.aligned.shared::cta.b32 [%0], %1;" :: "r"(sa), "r"((uint32_t)(n)) : "memory")
#define TC_DEALLOC(t, n)  asm volatile("tcgen05.dealloc.cta_group::1.sync.aligned.b32 %0, %1;" :: "r"(t), "r"((uint32_t)(n)))
#define TC_RELINQ()       asm volatile("tcgen05.relinquish_alloc_permit.cta_group::1.sync.aligned;")
#define TC_COMMIT(a)      asm volatile("tcgen05.commit.cta_group::1.mbarrier::arrive::one.shared::cluster.b64 [%0];" :: "r"(a) : "memory")
#define TC_FENCE_AFTER()  asm volatile("tcgen05.fence::after_thread_sync;" ::: "memory")
#define TC_FENCE_BEFORE() asm volatile("tcgen05.fence::before_thread_sync;" ::: "memory")
#define TC_WAIT_LD()      asm volatile("tcgen05.wait::ld.sync.aligned;" ::: "memory")
#define FENCE_ASYNC()     asm volatile("fence.proxy.async.shared::cta;" ::: "memory")

__device__ __forceinline__ void mma_f16_ss(uint32_t d, uint64_t ad, uint64_t bd,
                                           uint32_t idesc, bool accum) {
    uint32_t en = accum ? 1u : 0u, z = 0u;
    asm volatile(
        "{ .reg .pred p; setp.ne.u32 p, %5, 0;\n\t"
        "tcgen05.mma.cta_group::1.kind::f16 [%0], %1, %2, %3, {%4,%4,%4,%4}, p; }"
        :: "r"(d), "l"(ad), "l"(bd), "r"(idesc), "r"(z), "r"(en) : "memory");
}
__device__ __forceinline__ void tmem_ld32(uint32_t* r, uint32_t addr) {
    asm volatile(
        "tcgen05.ld.sync.aligned.32x32b.x32.b32 "
        "{%0,%1,%2,%3,%4,%5,%6,%7,%8,%9,%10,%11,%12,%13,%14,%15,"
        "%16,%17,%18,%19,%20,%21,%22,%23,%24,%25,%26,%27,%28,%29,%30,%31}, [%32];"
        : "=r"(r[0]), "=r"(r[1]), "=r"(r[2]), "=r"(r[3]), "=r"(r[4]), "=r"(r[5]), "=r"(r[6]), "=r"(r[7]),
          "=r"(r[8]), "=r"(r[9]), "=r"(r[10]), "=r"(r[11]), "=r"(r[12]), "=r"(r[13]), "=r"(r[14]), "=r"(r[15]),
          "=r"(r[16]), "=r"(r[17]), "=r"(r[18]), "=r"(r[19]), "=r"(r[20]), "=r"(r[21]), "=r"(r[22]), "=r"(r[23]),
          "=r"(r[24]), "=r"(r[25]), "=r"(r[26]), "=r"(r[27]), "=r"(r[28]), "=r"(r[29]), "=r"(r[30]), "=r"(r[31])
        : "r"(addr));
}
#define DESC_SW128(addr) ((uint64_t(2) << 61) | (uint64_t(1) << 46) | (uint64_t(64) << 32) \
                          | (uint64_t(1) << 16) | ((uint64_t)((addr) >> 4) & 0x3FFF))

__device__ __forceinline__ uint32_t pack_bf2(float a, float b) {
    __nv_bfloat162 t;
    t.x = __float2bfloat16(a);
    t.y = __float2bfloat16(b);
    return *(uint32_t*)&t;
}
__device__ __forceinline__ void sts16(uint32_t a, uint32_t x, uint32_t y, uint32_t z, uint32_t w) {
    asm volatile("st.shared.v4.b32 [%0], {%1,%2,%3,%4};" :: "r"(a), "r"(x), "r"(y), "r"(z), "r"(w));
}

// load 64-col bf16 slice (one swizzle-atom row) into SW128 tile; row = tid
__device__ __forceinline__ void load_b_tile(uint32_t dstBase, const __nv_bfloat16* src, int tid) {
    const uint4* p = (const uint4*)src;
#pragma unroll
    for (int i = 0; i < 8; i++) {
        uint4 v = p[i];
        uint32_t byte = tid * 128 + i * 16;
        uint32_t a = dstBase + (byte ^ ((byte >> 3) & 0x70));
        sts16(a, v.x, v.y, v.z, v.w);
    }
}

// load 64 fp32 cols (base col kc) of row, split into hi/lo bf16 tiles
__device__ __forceinline__ void load_a_split(uint32_t ahBase, uint32_t alBase,
                                             const float* rowA, int kc, int kreal, int tid) {
#pragma unroll
    for (int g = 0; g < 8; g++) {
        int c0 = kc + g * 8;
        float f[8];
        if (c0 + 7 < kreal) {
            const float2* p = (const float2*)(rowA + c0);
            float2 v0 = p[0], v1 = p[1], v2 = p[2], v3 = p[3];
            f[0] = v0.x; f[1] = v0.y; f[2] = v1.x; f[3] = v1.y;
            f[4] = v2.x; f[5] = v2.y; f[6] = v3.x; f[7] = v3.y;
        } else {
#pragma unroll
            for (int j = 0; j < 8; j++) f[j] = (c0 + j < kreal) ? rowA[c0 + j] : 0.f;
        }
        float h[8], l[8];
#pragma unroll
        for (int j = 0; j < 8; j++) {
            h[j] = __bfloat162float(__float2bfloat16(f[j]));
            l[j] = f[j] - h[j];
        }
        uint32_t byte = tid * 128 + g * 16;
        uint32_t sw = byte ^ ((byte >> 3) & 0x70);
        sts16(ahBase + sw, pack_bf2(h[0], h[1]), pack_bf2(h[2], h[3]), pack_bf2(h[4], h[5]), pack_bf2(h[6], h[7]));
        sts16(alBase + sw, pack_bf2(l[0], l[1]), pack_bf2(l[2], l[3]), pack_bf2(l[4], l[5]), pack_bf2(l[6], l[7]));
    }
}
#endif // HAS_TC

// ------------- tcgen05 fused GEMM: C = A(fp32)[M,kreal] @ B^T, B split tables ------
// Per 64-K chunk: D += Ah*Bh + Al*Bh + Ah*Bl  (bf16x3, fp32 accumulate in TMEM)
__global__ void __launch_bounds__(128, 1)
gemm_tc(const float* __restrict__ A,
        const __nv_bfloat16* __restrict__ Bh, const __nv_bfloat16* __restrict__ Bl,
        float* __restrict__ C, int M, int lda, int kreal, int kp, int ldc)
{
#if HAS_TC
    extern __shared__ char dsm[];
    uint32_t sb = smem_u32(dsm);
    uint32_t base = (sb + 1023) & ~1023u;
    const uint32_t TM_PTR = base;
    const uint32_t MBAR   = base + 8;
    const uint32_t T0 = base + 1024;          // buffer 0: AH, AL, BH, BL each 16KB
    const uint32_t BUFSZ = 65536;

    int tid = threadIdx.x, wid = tid >> 5, lane = tid & 31;
    int m0 = blockIdx.y * 128, n0 = blockIdx.x * 128;

    if (wid == 0) { TC_ALLOC(TM_PTR, 128); TC_RELINQ(); }
    if (tid == 0) MBAR_INIT(MBAR, 1);
    __syncthreads();
    uint32_t tmem;
    asm volatile("ld.shared.b32 %0, [%1];" : "=r"(tmem) : "r"(TM_PTR));

    const int NC = kp >> 6;   // 64-wide K chunks

    int arow = m0 + tid; if (arow >= M) arow = M - 1;
    const float* rowA = A + (size_t)arow * lda;
    const __nv_bfloat16* rowBh = Bh + (size_t)(n0 + tid) * kp;
    const __nv_bfloat16* rowBl = Bl + (size_t)(n0 + tid) * kp;

    const uint32_t IDESC = 0x8200490u;  // fp32 acc, bf16 a/b, N=128, M=128

    // prologue: chunk 0 into buffer 0
    load_a_split(T0, T0 + 16384, rowA, 0, kreal, tid);
    load_b_tile(T0 + 32768, rowBh, tid);
    load_b_tile(T0 + 49152, rowBl, tid);
    FENCE_ASYNC();
    __syncthreads();

    for (int c = 0; c < NC; c++) {
        uint32_t buf = T0 + (c & 1) * BUFSZ;
        if (wid == 0 && elect_one()) {
            uint64_t dAH = DESC_SW128(buf);
            uint64_t dAL = DESC_SW128(buf + 16384);
            uint64_t dBH = DESC_SW128(buf + 32768);
            uint64_t dBL = DESC_SW128(buf + 49152);
#pragma unroll
            for (int k = 0; k < 4; k++) mma_f16_ss(tmem, dAH + 2 * k, dBH + 2 * k, IDESC, !(c == 0 && k == 0));
#pragma unroll
            for (int k = 0; k < 4; k++) mma_f16_ss(tmem, dAL + 2 * k, dBH + 2 * k, IDESC, true);
#pragma unroll
            for (int k = 0; k < 4; k++) mma_f16_ss(tmem, dAH + 2 * k, dBL + 2 * k, IDESC, true);
            TC_COMMIT(MBAR);
        }
        if (c + 1 < NC) {
            uint32_t nbuf = T0 + ((c + 1) & 1) * BUFSZ;
            int kc = (c + 1) << 6;
            load_a_split(nbuf, nbuf + 16384, rowA, kc, kreal, tid);
            load_b_tile(nbuf + 32768, rowBh + kc, tid);
            load_b_tile(nbuf + 49152, rowBl + kc, tid);
            FENCE_ASYNC();
        }
        MBAR_WAIT(MBAR, c & 1);
        __syncthreads();
    }

    TC_FENCE_AFTER();
#pragma unroll
    for (int nb = 0; nb < 4; nb++) {
        uint32_t r[32];
        tmem_ld32(r, tmem + nb * 32);
        TC_WAIT_LD();
        int row = m0 + wid * 32 + lane;
        if (row < M) {
            float4* dst = (float4*)(C + (size_t)row * ldc + n0 + nb * 32);
#pragma unroll
            for (int i = 0; i < 8; i++)
                dst[i] = make_float4(__uint_as_float(r[4 * i]), __uint_as_float(r[4 * i + 1]),
                                     __uint_as_float(r[4 * i + 2]), __uint_as_float(r[4 * i + 3]));
        }
    }
    TC_FENCE_BEFORE();
    __syncthreads();
    if (wid == 0) TC_DEALLOC(tmem, 128);
#endif
}

// ---------------- SIMT fallback (active only when !HAS_TC) ---------------------
__global__ __launch_bounds__(256) void gemm_simt(
    const float* __restrict__ A,
    const __nv_bfloat16* __restrict__ Bh, const __nv_bfloat16* __restrict__ Bl,
    float* __restrict__ C, int M, int lda, int kreal, int kp, int ldc)
{
#if !HAS_TC
    __shared__ float As[8][128];
    __shared__ float Bs[8][128];
    int tid = threadIdx.x;
    int tx = tid & 15, ty = tid >> 4;
    int rowBase = blockIdx.y * 128;
    int colBase = blockIdx.x * 128;

    float acc[8][8];
#pragma unroll
    for (int i = 0; i < 8; i++)
#pragma unroll
        for (int j = 0; j < 8; j++) acc[i][j] = 0.f;

    for (int k0 = 0; k0 < kp; k0 += 8) {
#pragma unroll
        for (int i = 0; i < 4; i++) {
            int idx = tid + 256 * i;
            int r = idx >> 3, c = idx & 7;
            int gr = rowBase + r, gc = k0 + c;
            float v = 0.f;
            if (gr < M && gc < kreal) v = A[(size_t)gr * lda + gc];
            As[c][r] = v;
        }
#pragma unroll
        for (int i = 0; i < 4; i++) {
            int idx = tid + 256 * i;
            int nl = idx >> 3, kk = idx & 7;
            size_t o = (size_t)(colBase + nl) * kp + k0 + kk;
            Bs[kk][nl] = __bfloat162float(Bh[o]) + __bfloat162float(Bl[o]);
        }
        __syncthreads();
#pragma unroll
        for (int kk = 0; kk < 8; kk++) {
            float a[8], b[8];
#pragma unroll
            for (int i = 0; i < 8; i++) a[i] = As[kk][ty * 8 + i];
#pragma unroll
            for (int j = 0; j < 8; j++) b[j] = Bs[kk][tx * 8 + j];
#pragma unroll
            for (int i = 0; i < 8; i++)
#pragma unroll
                for (int j = 0; j < 8; j++) acc[i][j] = fmaf(a[i], b[j], acc[i][j]);
        }
        __syncthreads();
    }
#pragma unroll
    for (int i = 0; i < 8; i++) {
        int gr = rowBase + ty * 8 + i;
        if (gr >= M) continue;
#pragma unroll
        for (int j = 0; j < 8; j++)
            C[(size_t)gr * ldc + colBase + tx * 8 + j] = acc[i][j];
    }
#endif
}

// ---------------- weight conversion (transpose + bf16 split) -------------------
__global__ void cvt_w_kernel(const float* __restrict__ W1, const float* __restrict__ W2) {
    int idx = blockIdx.x * blockDim.x + threadIdx.x;
    const int n1 = D1 * KP1;
    if (idx < n1) {
        int n = idx / KP1, k = idx - n * KP1;
        float v = (k < IN_CH) ? W1[(size_t)k * D1 + n] : 0.f;
        __nv_bfloat16 hi = __float2bfloat16(v);
        g_b1h[idx] = hi;
        g_b1l[idx] = __float2bfloat16(v - __bfloat162float(hi));
        return;
    }
    int j = idx - n1;
    if (j < HID * D1) {
        int n = j / D1, k = j - n * D1;
        float v = W2[(size_t)k * HID + n];
        __nv_bfloat16 hi = __float2bfloat16(v);
        g_b2h[j] = hi;
        g_b2l[j] = __float2bfloat16(v - __bfloat162float(hi));
    }
}

// ---------------- misc helpers ---------------------------------------------------
__device__ __forceinline__ float warpMax(float v) {
#pragma unroll
    for (int o = 16; o > 0; o >>= 1) v = fmaxf(v, __shfl_xor_sync(0xffffffffu, v, o));
    return v;
}
__device__ __forceinline__ float warpSum(float v) {
#pragma unroll
    for (int o = 16; o > 0; o >>= 1) v += __shfl_xor_sync(0xffffffffu, v, o);
    return v;
}
__device__ __forceinline__ float lrelu(float x) { return x > 0.f ? x : NEG_SLOPE * x; }

__global__ void zero_kernel() {
    int i = blockIdx.x * blockDim.x + threadIdx.x;
    if (i < N_NODES) g_counts[i] = 0;
    if (i < NUM_GRAPHS * HID) g_pool[i] = 0.f;
    if (i < NUM_GRAPHS) g_cnt[i] = 0;
}

__global__ void hist_kernel(const int* __restrict__ ei) {
    int e = blockIdx.x * blockDim.x + threadIdx.x;
    if (e >= E_TOT) return;
    int dst = (e < N_EDGES) ? ei[N_EDGES + e] : (e - N_EDGES);
    atomicAdd(&g_counts[dst], 1);
}

__global__ void scan_kernel() {
    __shared__ int sh[1024];
    const int n = N_NODES;
    const int chunk = (n + 1023) / 1024;
    int tid = threadIdx.x;
    int b = tid * chunk;
    int e = b + chunk; if (e > n) e = n; if (b > n) b = n;
    int s = 0;
    for (int i = b; i < e; i++) s += g_counts[i];
    sh[tid] = s;
    __syncthreads();
    for (int o = 1; o < 1024; o <<= 1) {
        int v = 0;
        if (tid >= o) v = sh[tid - o];
        __syncthreads();
        if (tid >= o) sh[tid] += v;
        __syncthreads();
    }
    int run = (tid == 0) ? 0 : sh[tid - 1];
    for (int i = b; i < e; i++) {
        g_offsets[i] = run;
        g_cursor[i]  = run;
        run += g_counts[i];
    }
    if (tid == 1023) g_offsets[n] = sh[1023];
}

__global__ void scatter_kernel(const int* __restrict__ ei) {
    int e = blockIdx.x * blockDim.x + threadIdx.x;
    if (e >= E_TOT) return;
    int src, dst;
    if (e < N_EDGES) { src = ei[e]; dst = ei[N_EDGES + e]; }
    else             { src = e - N_EDGES; dst = src; }
    int pos = atomicAdd(&g_cursor[dst], 1);
    g_src_sorted[pos] = src;
}

// ---------------- attention coefficients -----------------------------------------
__global__ void att_coef1(const float* __restrict__ a_src, const float* __restrict__ a_dst) {
    int gw = (blockIdx.x * blockDim.x + threadIdx.x) >> 5;
    int lane = threadIdx.x & 31;
    if (gw >= N_NODES) return;
    const float* row = g_h1 + (size_t)gw * D1;
    float s[4] = {0, 0, 0, 0}, d[4] = {0, 0, 0, 0};
#pragma unroll
    for (int j = 0; j < 16; j++) {
        int c = lane + 32 * j;
        float v = row[c];
        s[j >> 2] = fmaf(v, a_src[c], s[j >> 2]);
        d[j >> 2] = fmaf(v, a_dst[c], d[j >> 2]);
    }
#pragma unroll
    for (int h = 0; h < 4; h++) { s[h] = warpSum(s[h]); d[h] = warpSum(d[h]); }
    if (lane == 0) {
#pragma unroll
        for (int h = 0; h < 4; h++) {
            g_als1[gw * 4 + h] = s[h];
            g_ald1[gw * 4 + h] = d[h];
        }
    }
}

__global__ void att_coef2(const float* __restrict__ a_src, const float* __restrict__ a_dst) {
    int gw = (blockIdx.x * blockDim.x + threadIdx.x) >> 5;
    int lane = threadIdx.x & 31;
    if (gw >= N_NODES) return;
    const float* row = g_h2 + (size_t)gw * HID;
    float s = 0.f, d = 0.f;
#pragma unroll
    for (int j = 0; j < 4; j++) {
        int c = lane + 32 * j;
        float v = row[c];
        s = fmaf(v, a_src[c], s);
        d = fmaf(v, a_dst[c], d);
    }
    s = warpSum(s); d = warpSum(d);
    if (lane == 0) { g_als2[gw] = s; g_ald2[gw] = d; }
}

// ---------------- GAT layer 1 softmax + aggregate (warp per dst node) -----------
__global__ __launch_bounds__(256) void gat_agg1(const float* __restrict__ b1) {
    int gw = (blockIdx.x * blockDim.x + threadIdx.x) >> 5;
    int lane = threadIdx.x & 31;
    if (gw >= N_NODES) return;
    int beg = g_offsets[gw], end = g_offsets[gw + 1];

    float ald[4];
#pragma unroll
    for (int h = 0; h < 4; h++) ald[h] = g_ald1[gw * 4 + h];

    float mx[4] = {-1e30f, -1e30f, -1e30f, -1e30f};
    for (int i = beg + lane; i < end; i += 32) {
        int s = g_src_sorted[i];
#pragma unroll
        for (int h = 0; h < 4; h++) {
            float e = lrelu(g_als1[s * 4 + h] + ald[h]);
            mx[h] = fmaxf(mx[h], e);
        }
    }
#pragma unroll
    for (int h = 0; h < 4; h++) mx[h] = warpMax(mx[h]);

    float sm[4] = {0, 0, 0, 0};
    for (int i = beg + lane; i < end; i += 32) {
        int s = g_src_sorted[i];
        float4 ex4;
        float* exv = (float*)&ex4;
#pragma unroll
        for (int h = 0; h < 4; h++) {
            float e = lrelu(g_als1[s * 4 + h] + ald[h]);
            float ex = __expf(e - mx[h]);
            exv[h] = ex;
            sm[h] += ex;
        }
        ((float4*)g_alpha1)[i] = ex4;
    }
#pragma unroll
    for (int h = 0; h < 4; h++) sm[h] = warpSum(sm[h]);
    float inv[4];
#pragma unroll
    for (int h = 0; h < 4; h++) inv[h] = 1.f / sm[h];
    __syncwarp();

    float acc[16];
#pragma unroll
    for (int j = 0; j < 16; j++) acc[j] = 0.f;
    int i = beg;
    for (; i + 1 < end; i += 2) {
        int s0 = g_src_sorted[i], s1 = g_src_sorted[i + 1];
        float4 a0 = ((const float4*)g_alpha1)[i];
        float4 a1 = ((const float4*)g_alpha1)[i + 1];
        const float* h0 = g_h1 + (size_t)s0 * D1;
        const float* h1p = g_h1 + (size_t)s1 * D1;
#pragma unroll
        for (int j = 0; j < 16; j++) {
            float aa0 = (j < 4) ? a0.x : (j < 8) ? a0.y : (j < 12) ? a0.z : a0.w;
            float aa1 = (j < 4) ? a1.x : (j < 8) ? a1.y : (j < 12) ? a1.z : a1.w;
            int c = lane + 32 * j;
            acc[j] = fmaf(aa0, h0[c], acc[j]);
            acc[j] = fmaf(aa1, h1p[c], acc[j]);
        }
    }
    if (i < end) {
        int s0 = g_src_sorted[i];
        float4 a0 = ((const float4*)g_alpha1)[i];
        const float* h0 = g_h1 + (size_t)s0 * D1;
#pragma unroll
        for (int j = 0; j < 16; j++) {
            float aa0 = (j < 4) ? a0.x : (j < 8) ? a0.y : (j < 12) ? a0.z : a0.w;
            acc[j] = fmaf(aa0, h0[lane + 32 * j], acc[j]);
        }
    }
#pragma unroll
    for (int j = 0; j < 16; j++) {
        int c = lane + 32 * j;
        float v = fmaxf(acc[j] * inv[j >> 2] + b1[c], 0.f);
        g_out1[(size_t)gw * D1 + c] = v;
    }
}

// ---------------- GAT layer 2 -------------------------------------------------------
__global__ __launch_bounds__(256) void gat_agg2(const float* __restrict__ b2) {
    int gw = (blockIdx.x * blockDim.x + threadIdx.x) >> 5;
    int lane = threadIdx.x & 31;
    if (gw >= N_NODES) return;
    int beg = g_offsets[gw], end = g_offsets[gw + 1];
    float ald = g_ald2[gw];

    float mx = -1e30f;
    for (int i = beg + lane; i < end; i += 32)
        mx = fmaxf(mx, lrelu(g_als2[g_src_sorted[i]] + ald));
    mx = warpMax(mx);

    float sm = 0.f;
    for (int i = beg + lane; i < end; i += 32) {
        float e = lrelu(g_als2[g_src_sorted[i]] + ald);
        float ex = __expf(e - mx);
        g_alpha2[i] = ex;
        sm += ex;
    }
    sm = warpSum(sm);
    float inv = 1.f / sm;
    __syncwarp();

    float acc[4] = {0, 0, 0, 0};
    int i = beg;
    for (; i + 1 < end; i += 2) {
        int s0 = g_src_sorted[i], s1 = g_src_sorted[i + 1];
        float a0 = g_alpha2[i], a1 = g_alpha2[i + 1];
        const float* h0 = g_h2 + (size_t)s0 * HID;
        const float* h1p = g_h2 + (size_t)s1 * HID;
#pragma unroll
        for (int j = 0; j < 4; j++) {
            int c = lane + 32 * j;
            acc[j] = fmaf(a0, h0[c], acc[j]);
            acc[j] = fmaf(a1, h1p[c], acc[j]);
        }
    }
    if (i < end) {
        int s0 = g_src_sorted[i];
        float a0 = g_alpha2[i];
        const float* h0 = g_h2 + (size_t)s0 * HID;
#pragma unroll
        for (int j = 0; j < 4; j++)
            acc[j] = fmaf(a0, h0[lane + 32 * j], acc[j]);
    }
#pragma unroll
    for (int j = 0; j < 4; j++) {
        int c = lane + 32 * j;
        float v = acc[j] * inv + b2[c];
        g_out2[(size_t)gw * HID + c] = fmaxf(v, 0.f);
    }
}

// ---------------- global mean pool --------------------------------------------------
__global__ void pool_kernel(const int* __restrict__ batch) {
    int gw = (blockIdx.x * blockDim.x + threadIdx.x) >> 5;
    int lane = threadIdx.x & 31;
    if (gw >= N_NODES) return;
    int g = batch[gw];
#pragma unroll
    for (int j = 0; j < 4; j++) {
        int c = lane + 32 * j;
        atomicAdd(&g_pool[g * HID + c], g_out2[(size_t)gw * HID + c]);
    }
    if (lane == 0) atomicAdd(&g_cnt[g], 1);
}

// ---------------- MLP head --------------------------------------------------------------
__global__ __launch_bounds__(1024) void mlp_kernel(
    const float* __restrict__ fc1_w, const float* __restrict__ fc1_b,
    const float* __restrict__ fc2_w, const float* __restrict__ fc2_b,
    float* __restrict__ out)
{
    __shared__ float pooled[NUM_GRAPHS * HID];
    __shared__ float z[NUM_GRAPHS * 64];
    int tid = threadIdx.x;
    for (int i = tid; i < NUM_GRAPHS * HID; i += blockDim.x) {
        int g = i / HID;
        float c = fmaxf((float)g_cnt[g], 1.f);
        pooled[i] = g_pool[i] / c;
    }
    __syncthreads();
    for (int i = tid; i < NUM_GRAPHS * 64; i += blockDim.x) {
        int g = i >> 6, j = i & 63;
        float acc = fc1_b[j];
        for (int k = 0; k < HID; k++)
            acc = fmaf(pooled[g * HID + k], fc1_w[k * 64 + j], acc);
        z[i] = fmaxf(acc, 0.f);
    }
    __syncthreads();
    for (int i = tid; i < NUM_GRAPHS * NUM_CLASSES; i += blockDim.x) {
        int g = i / NUM_CLASSES, c = i % NUM_CLASSES;
        float acc = fc2_b[c];
        for (int j = 0; j < 64; j++)
            acc = fmaf(z[g * 64 + j], fc2_w[j * NUM_CLASSES + c], acc);
        out[i] = acc;
    }
}

// ---------------- launch ------------------------------------------------------------------
extern "C" void kernel_launch(void* const* d_in, const int* in_sizes, int n_in,
                              void* d_out, int out_size) {
    const float* x       = (const float*)d_in[0];
    const int*   ei      = (const int*)  d_in[1];
    const int*   batch   = (const int*)  d_in[2];
    const float* W1      = (const float*)d_in[3];
    const float* a_src1  = (const float*)d_in[4];
    const float* a_dst1  = (const float*)d_in[5];
    const float* b1      = (const float*)d_in[6];
    const float* W2      = (const float*)d_in[7];
    const float* a_src2  = (const float*)d_in[8];
    const float* a_dst2  = (const float*)d_in[9];
    const float* b2      = (const float*)d_in[10];
    const float* fc1_w   = (const float*)d_in[11];
    const float* fc1_b   = (const float*)d_in[12];
    const float* fc2_w   = (const float*)d_in[13];
    const float* fc2_b   = (const float*)d_in[14];
    float* out = (float*)d_out;

    static float* p_h1 = nullptr;
    static float* p_h2 = nullptr;
    static float* p_out1 = nullptr;
    static __nv_bfloat16 *p_b1h, *p_b1l, *p_b2h, *p_b2l;
    static bool inited = false;
    if (!inited) {
        cudaGetSymbolAddress((void**)&p_h1,   g_h1);
        cudaGetSymbolAddress((void**)&p_h2,   g_h2);
        cudaGetSymbolAddress((void**)&p_out1, g_out1);
        cudaGetSymbolAddress((void**)&p_b1h,  g_b1h);
        cudaGetSymbolAddress((void**)&p_b1l,  g_b1l);
        cudaGetSymbolAddress((void**)&p_b2h,  g_b2h);
        cudaGetSymbolAddress((void**)&p_b2l,  g_b2l);
        cudaFuncSetAttribute(gemm_tc, cudaFuncAttributeMaxDynamicSharedMemorySize, 132096);
        inited = true;
    }

    // prep: weight split + CSR build
    cvt_w_kernel<<<(D1 * KP1 + HID * D1 + 255) / 256, 256>>>(W1, W2);
    zero_kernel<<<(N_NODES + 255) / 256, 256>>>();
    hist_kernel<<<(E_TOT + 255) / 256, 256>>>(ei);
    scan_kernel<<<1, 1024>>>();
    scatter_kernel<<<(E_TOT + 255) / 256, 256>>>(ei);

    // GEMM1: h1 = x @ W1   [50000x814]@[814x512], fused fp32->bf16x3 split
    {
        dim3 grid(D1 / 128, (N_NODES + 127) / 128);
        gemm_tc  <<<grid, 128, 132096>>>(x, p_b1h, p_b1l, p_h1, N_NODES, IN_CH, IN_CH, KP1, D1);
        gemm_simt<<<grid, 256>>>        (x, p_b1h, p_b1l, p_h1, N_NODES, IN_CH, IN_CH, KP1, D1);
    }

    att_coef1<<<(N_NODES * 32 + 255) / 256, 256>>>(a_src1, a_dst1);
    gat_agg1<<<(N_NODES * 32 + 255) / 256, 256>>>(b1);

    // GEMM2: h2 = out1 @ W2   [50000x512]@[512x128]
    {
        dim3 grid(HID / 128, (N_NODES + 127) / 128);
        gemm_tc  <<<grid, 128, 132096>>>(p_out1, p_b2h, p_b2l, p_h2, N_NODES, D1, D1, D1, HID);
        gemm_simt<<<grid, 256>>>        (p_out1, p_b2h, p_b2l, p_h2, N_NODES, D1, D1, D1, HID);
    }
    att_coef2<<<(N_NODES * 32 + 255) / 256, 256>>>(a_src2, a_dst2);
    gat_agg2<<<(N_NODES * 32 + 255) / 256, 256>>>(b2);

    pool_kernel<<<(N_NODES * 32 + 255) / 256, 256>>>(batch);
    mlp_kernel<<<1, 1024>>>(fc1_w, fc1_b, fc2_w, fc2_b, out);
}

// round 6
// speedup vs baseline: 1.6300x; 1.6300x over previous
#include <cuda_runtime.h>
#include <cuda_bf16.h>
#include <cstdint>
#include <math.h>

#define N_NODES 50000
#define N_EDGES 400000
#define E_TOT   450000
#define IN_CH   814
#define KP1     832          /* 814 padded to 13*64 */
#define HID     128
#define HEADS1  4
#define D1      (HEADS1*HID) /* 512 */
#define NUM_CLASSES 46
#define NUM_GRAPHS  64
#define NEG_SLOPE   0.2f
#define SCAN_NB  196         /* 196*256 >= 50000 */

#if defined(__CUDA_ARCH_FEAT_SM103_ALL) || defined(__CUDA_ARCH_FEAT_SM100_ALL)
#define HAS_TC 1
#else
#define HAS_TC 0
#endif

// ---------------- scratch ------------------------------------------------------
__device__ float g_h1[N_NODES * D1];
__device__ float g_h2[N_NODES * HID];
__device__ float g_out2[N_NODES * HID];
__device__ __nv_bfloat16 g_xh[N_NODES * KP1];
__device__ __nv_bfloat16 g_xl[N_NODES * KP1];
__device__ __nv_bfloat16 g_o1h[N_NODES * D1];
__device__ __nv_bfloat16 g_o1l[N_NODES * D1];
__device__ __nv_bfloat16 g_b1h[D1 * KP1];
__device__ __nv_bfloat16 g_b1l[D1 * KP1];
__device__ __nv_bfloat16 g_b2h[HID * D1];
__device__ __nv_bfloat16 g_b2l[HID * D1];
__device__ float g_als1[N_NODES * HEADS1];
__device__ float g_ald1[N_NODES * HEADS1];
__device__ float g_als2[N_NODES];
__device__ float g_ald2[N_NODES];
__device__ int   g_counts[N_NODES];
__device__ int   g_offsets[N_NODES + 1];
__device__ int   g_cursor[N_NODES];
__device__ int   g_bsum[SCAN_NB];
__device__ int   g_src_sorted[E_TOT];
__device__ float g_alpha1[E_TOT * HEADS1];
__device__ float g_alpha2[E_TOT];
__device__ float g_pool[NUM_GRAPHS * HID];
__device__ int   g_cnt[NUM_GRAPHS];

// ---------------- PTX helpers ----------------------------------------------------
#if HAS_TC
__device__ __forceinline__ uint32_t smem_u32(const void* p) {
    uint32_t a;
    asm("{ .reg .u64 t; cvta.to.shared.u64 t, %1; cvt.u32.u64 %0, t; }" : "=r"(a) : "l"(p));
    return a;
}
__device__ __forceinline__ uint32_t elect_one() {
    uint32_t pred;
    asm volatile("{ .reg .pred p; elect.sync _|p, 0xFFFFFFFF; selp.b32 %0, 1, 0, p; }" : "=r"(pred));
    return pred;
}
#define MBAR_INIT(a, n)  asm volatile("mbarrier.init.shared.b64 [%0], %1;" :: "r"(a), "r"((uint32_t)(n)) : "memory")
#define MBAR_WAIT(a, ph) do { \
    uint32_t _m = (a), _p = (ph), _d; \
    asm volatile("{ .reg .pred p; mbarrier.try_wait.parity.acquire.cta.shared::cta.b64 p, [%1], %2; selp.b32 %0,1,0,p; }" \
        : "=r"(_d) : "r"(_m), "r"(_p) : "memory"); \
    if (!_d) { \
        asm volatile("{ .reg .pred P1;\nWL_%=:\nmbarrier.try_wait.parity.acquire.cta.shared::cta.b64 P1, [%0], %1, 0x989680;\n@P1 bra.uni WD_%=;\nbra.uni WL_%=;\nWD_%=:\n}" \
            :: "r"(_m), "r"(_p) : "memory"); \
    } } while (0)
#define TC_ALLOC(sa, n)   asm volatile("tcgen05.alloc.cta_group::1.sync.aligned.shared::cta.b32 [%0], %1;" :: "r"(sa), "r"((uint32_t)(n)) : "memory")
#define TC_DEALLOC(t, n)  asm volatile("tcgen05.dealloc.cta_group::1.sync.aligned.b32 %0, %1;" :: "r"(t), "r"((uint32_t)(n)))
#define TC_RELINQ()       asm volatile("tcgen05.relinquish_alloc_permit.cta_group::1.sync.aligned;")
#define TC_COMMIT(a)      asm volatile("tcgen05.commit.cta_group::1.mbarrier::arrive::one.shared::cluster.b64 [%0];" :: "r"(a) : "memory")
#define TC_FENCE_AFTER()  asm volatile("tcgen05.fence::after_thread_sync;" ::: "memory")
#define TC_FENCE_BEFORE() asm volatile("tcgen05.fence::before_thread_sync;" ::: "memory")
#define TC_WAIT_LD()      asm volatile("tcgen05.wait::ld.sync.aligned;" ::: "memory")
#define FENCE_ASYNC()     asm volatile("fence.proxy.async.shared::cta;" ::: "memory")
#define CP16(dst, src)    asm volatile("cp.async.ca.shared.global [%0], [%1], 16;" :: "r"(dst), "l"(src))
#define CP_COMMIT()       asm volatile("cp.async.commit_group;" ::: "memory")
#define CP_WAIT0()        asm volatile("cp.async.wait_group 0;" ::: "memory")

__device__ __forceinline__ void mma_f16_ss(uint32_t d, uint64_t ad, uint64_t bd,
                                           uint32_t idesc, bool accum) {
    uint32_t en = accum ? 1u : 0u, z = 0u;
    asm volatile(
        "{ .reg .pred p; setp.ne.u32 p, %5, 0;\n\t"
        "tcgen05.mma.cta_group::1.kind::f16 [%0], %1, %2, %3, {%4,%4,%4,%4}, p; }"
        :: "r"(d), "l"(ad), "l"(bd), "r"(idesc), "r"(z), "r"(en) : "memory");
}
__device__ __forceinline__ void tmem_ld32(uint32_t* r, uint32_t addr) {
    asm volatile(
        "tcgen05.ld.sync.aligned.32x32b.x32.b32 "
        "{%0,%1,%2,%3,%4,%5,%6,%7,%8,%9,%10,%11,%12,%13,%14,%15,"
        "%16,%17,%18,%19,%20,%21,%22,%23,%24,%25,%26,%27,%28,%29,%30,%31}, [%32];"
        : "=r"(r[0]), "=r"(r[1]), "=r"(r[2]), "=r"(r[3]), "=r"(r[4]), "=r"(r[5]), "=r"(r[6]), "=r"(r[7]),
          "=r"(r[8]), "=r"(r[9]), "=r"(r[10]), "=r"(r[11]), "=r"(r[12]), "=r"(r[13]), "=r"(r[14]), "=r"(r[15]),
          "=r"(r[16]), "=r"(r[17]), "=r"(r[18]), "=r"(r[19]), "=r"(r[20]), "=r"(r[21]), "=r"(r[22]), "=r"(r[23]),
          "=r"(r[24]), "=r"(r[25]), "=r"(r[26]), "=r"(r[27]), "=r"(r[28]), "=r"(r[29]), "=r"(r[30]), "=r"(r[31])
        : "r"(addr));
}
#define DESC_SW128(addr) ((uint64_t(2) << 61) | (uint64_t(1) << 46) | (uint64_t(64) << 32) \
                          | (uint64_t(1) << 16) | ((uint64_t)((addr) >> 4) & 0x3FFF))

// 256-thread tile load: thread t covers row r=t>>1, half h=t&1 (64B), 4x cp.async 16B
__device__ __forceinline__ void load_tile_async(uint32_t dstBase, const __nv_bfloat16* rowSrc,
                                                int half) {
    const char* src = (const char*)rowSrc + half * 64;
    int r = threadIdx.x >> 1;
#pragma unroll
    for (int i = 0; i < 4; i++) {
        uint32_t byte = r * 128 + half * 64 + i * 16;
        uint32_t a = dstBase + (byte ^ ((byte >> 3) & 0x70));
        CP16(a, src + i * 16);
    }
}
#endif // HAS_TC

// ------------- tcgen05 bf16x3 GEMM: C[M,N] = A[M,kp] @ B^T --------------------------
// Ah/Al [M,kp] bf16, Bh/Bl [N,kp] bf16. D = Ah*Bh + Al*Bh + Ah*Bl via 3 K-segments.
__global__ void __launch_bounds__(256)
gemm_tc(const __nv_bfloat16* __restrict__ Ah, const __nv_bfloat16* __restrict__ Al,
        const __nv_bfloat16* __restrict__ Bh, const __nv_bfloat16* __restrict__ Bl,
        float* __restrict__ C, int M, int ldc, int kp)
{
#if HAS_TC
    extern __shared__ char dsm[];
    uint32_t sb = smem_u32(dsm);
    uint32_t base = (sb + 1023) & ~1023u;
    const uint32_t TM_PTR = base;
    const uint32_t MBAR   = base + 8;
    const uint32_t A0 = base + 1024, A1 = A0 + 16384;
    const uint32_t B0 = A0 + 32768,  B1 = A0 + 49152;

    int tid = threadIdx.x, wid = tid >> 5, lane = tid & 31;
    int m0 = blockIdx.y * 128, n0 = blockIdx.x * 128;
    int half = tid & 1, r = tid >> 1;

    if (wid == 0) { TC_ALLOC(TM_PTR, 128); TC_RELINQ(); }
    if (tid == 0) MBAR_INIT(MBAR, 1);
    __syncthreads();
    uint32_t tmem;
    asm volatile("ld.shared.b32 %0, [%1];" : "=r"(tmem) : "r"(TM_PTR));

    const int nck = kp >> 6;
    const int NC = 3 * nck;

    int arow = m0 + r; if (arow >= M) arow = M - 1;
    const __nv_bfloat16* aH = Ah + (size_t)arow * kp;
    const __nv_bfloat16* aL = Al + (size_t)arow * kp;
    const __nv_bfloat16* bH = Bh + (size_t)(n0 + r) * kp;
    const __nv_bfloat16* bL = Bl + (size_t)(n0 + r) * kp;

    const uint32_t IDESC = 0x8200490u;  // fp32 acc, bf16 a/b, N=128, M=128

    // prologue: chunk 0 into buffer 0
    load_tile_async(A0, aH, half);
    load_tile_async(B0, bH, half);
    CP_COMMIT();

    for (int c = 0; c < NC; c++) {
        uint32_t aBase = (c & 1) ? A1 : A0;
        uint32_t bBase = (c & 1) ? B1 : B0;
        CP_WAIT0();
        __syncthreads();
        FENCE_ASYNC();
        if (wid == 0 && elect_one()) {
            uint64_t ad = DESC_SW128(aBase);
            uint64_t bd = DESC_SW128(bBase);
#pragma unroll
            for (int k = 0; k < 4; k++)
                mma_f16_ss(tmem, ad + 2 * k, bd + 2 * k, IDESC, !(c == 0 && k == 0));
            TC_COMMIT(MBAR);
        }
        if (c + 1 < NC) {
            int cn = c + 1;
            int seg = cn / nck;
            int kc = (cn - seg * nck) << 6;
            const __nv_bfloat16* sa = (seg == 1) ? aL : aH;
            const __nv_bfloat16* sbp = (seg == 2) ? bL : bH;
            uint32_t aB2 = (cn & 1) ? A1 : A0;
            uint32_t bB2 = (cn & 1) ? B1 : B0;
            load_tile_async(aB2, sa + kc, half);
            load_tile_async(bB2, sbp + kc, half);
            CP_COMMIT();
        }
        MBAR_WAIT(MBAR, c & 1);
        __syncthreads();
    }

    TC_FENCE_AFTER();
    // epilogue: warps 0-3 read their 32-row subpartitions (4 N-batches of 32)
    if (wid < 4) {
#pragma unroll
        for (int nb = 0; nb < 4; nb++) {
            uint32_t rg[32];
            tmem_ld32(rg, tmem + nb * 32);
            TC_WAIT_LD();
            int row = m0 + wid * 32 + lane;
            if (row < M) {
                float4* dst = (float4*)(C + (size_t)row * ldc + n0 + nb * 32);
#pragma unroll
                for (int i = 0; i < 8; i++)
                    dst[i] = make_float4(__uint_as_float(rg[4 * i]), __uint_as_float(rg[4 * i + 1]),
                                         __uint_as_float(rg[4 * i + 2]), __uint_as_float(rg[4 * i + 3]));
            }
        }
        TC_FENCE_BEFORE();
    }
    __syncthreads();
    if (wid == 0) TC_DEALLOC(tmem, 128);
#endif
}

// ---------------- SIMT fallback (active only when !HAS_TC) ---------------------
__global__ __launch_bounds__(256) void gemm_simt(
    const __nv_bfloat16* __restrict__ Ah, const __nv_bfloat16* __restrict__ Al,
    const __nv_bfloat16* __restrict__ Bh, const __nv_bfloat16* __restrict__ Bl,
    float* __restrict__ C, int M, int ldc, int kp)
{
#if !HAS_TC
    __shared__ float As[8][128];
    __shared__ float Bs[8][128];
    int tid = threadIdx.x;
    int tx = tid & 15, ty = tid >> 4;
    int rowBase = blockIdx.y * 128;
    int colBase = blockIdx.x * 128;
    int N = gridDim.x * 128;

    float acc[8][8];
#pragma unroll
    for (int i = 0; i < 8; i++)
#pragma unroll
        for (int j = 0; j < 8; j++) acc[i][j] = 0.f;

    for (int k0 = 0; k0 < kp; k0 += 8) {
#pragma unroll
        for (int i = 0; i < 4; i++) {
            int idx = tid + 256 * i;
            int rr = idx >> 3, cc = idx & 7;
            int gr = rowBase + rr;
            float v = 0.f;
            if (gr < M) {
                size_t o = (size_t)gr * kp + k0 + cc;
                v = __bfloat162float(Ah[o]) + __bfloat162float(Al[o]);
            }
            As[cc][rr] = v;
        }
#pragma unroll
        for (int i = 0; i < 4; i++) {
            int idx = tid + 256 * i;
            int nl = idx >> 3, kk = idx & 7;
            int gn = colBase + nl;
            float v = 0.f;
            if (gn < N) {
                size_t o = (size_t)gn * kp + k0 + kk;
                v = __bfloat162float(Bh[o]) + __bfloat162float(Bl[o]);
            }
            Bs[kk][nl] = v;
        }
        __syncthreads();
#pragma unroll
        for (int kk = 0; kk < 8; kk++) {
            float a[8], b[8];
#pragma unroll
            for (int i = 0; i < 8; i++) a[i] = As[kk][ty * 8 + i];
#pragma unroll
            for (int j = 0; j < 8; j++) b[j] = Bs[kk][tx * 8 + j];
#pragma unroll
            for (int i = 0; i < 8; i++)
#pragma unroll
                for (int j = 0; j < 8; j++) acc[i][j] = fmaf(a[i], b[j], acc[i][j]);
        }
        __syncthreads();
    }
#pragma unroll
    for (int i = 0; i < 8; i++) {
        int gr = rowBase + ty * 8 + i;
        if (gr >= M) continue;
#pragma unroll
        for (int j = 0; j < 8; j++)
            C[(size_t)gr * ldc + colBase + tx * 8 + j] = acc[i][j];
    }
#endif
}

// ---------------- conversions ------------------------------------------------
__global__ void cvt_w_kernel(const float* __restrict__ W1, const float* __restrict__ W2) {
    int idx = blockIdx.x * blockDim.x + threadIdx.x;
    const int n1 = D1 * KP1;
    if (idx < n1) {
        int n = idx / KP1, k = idx - n * KP1;
        float v = (k < IN_CH) ? W1[(size_t)k * D1 + n] : 0.f;
        __nv_bfloat16 hi = __float2bfloat16(v);
        g_b1h[idx] = hi;
        g_b1l[idx] = __float2bfloat16(v - __bfloat162float(hi));
        return;
    }
    int j = idx - n1;
    if (j < HID * D1) {
        int n = j / D1, k = j - n * D1;
        float v = W2[(size_t)k * HID + n];
        __nv_bfloat16 hi = __float2bfloat16(v);
        g_b2h[j] = hi;
        g_b2l[j] = __float2bfloat16(v - __bfloat162float(hi));
    }
}

__global__ void cvt_x_kernel(const float* __restrict__ x) {
    int idx = blockIdx.x * blockDim.x + threadIdx.x;
    if (idx >= N_NODES * KP1) return;
    int row = idx / KP1, k = idx - row * KP1;
    float v = (k < IN_CH) ? x[(size_t)row * IN_CH + k] : 0.f;
    __nv_bfloat16 hi = __float2bfloat16(v);
    g_xh[idx] = hi;
    g_xl[idx] = __float2bfloat16(v - __bfloat162float(hi));
}

// ---------------- misc helpers -----------------------------------------------
__device__ __forceinline__ float warpMax(float v) {
#pragma unroll
    for (int o = 16; o > 0; o >>= 1) v = fmaxf(v, __shfl_xor_sync(0xffffffffu, v, o));
    return v;
}
__device__ __forceinline__ float warpSum(float v) {
#pragma unroll
    for (int o = 16; o > 0; o >>= 1) v += __shfl_xor_sync(0xffffffffu, v, o);
    return v;
}
__device__ __forceinline__ float lrelu(float x) { return x > 0.f ? x : NEG_SLOPE * x; }

__global__ void zero_kernel() {
    int i = blockIdx.x * blockDim.x + threadIdx.x;
    if (i < N_NODES) g_counts[i] = 0;
    if (i < NUM_GRAPHS * HID) g_pool[i] = 0.f;
    if (i < NUM_GRAPHS) g_cnt[i] = 0;
}

__global__ void hist_kernel(const int* __restrict__ ei) {
    int e = blockIdx.x * blockDim.x + threadIdx.x;
    if (e >= E_TOT) return;
    int dst = (e < N_EDGES) ? ei[N_EDGES + e] : (e - N_EDGES);
    atomicAdd(&g_counts[dst], 1);
}

// ------- multi-block exclusive scan over g_counts (3 stages) -------------------
__global__ void scan1_kernel() {
    __shared__ int sh[256];
    int b = blockIdx.x, tid = threadIdx.x;
    int i = b * 256 + tid;
    int v = (i < N_NODES) ? g_counts[i] : 0;
    sh[tid] = v;
    __syncthreads();
#pragma unroll
    for (int o = 1; o < 256; o <<= 1) {
        int t = (tid >= o) ? sh[tid - o] : 0;
        __syncthreads();
        sh[tid] += t;
        __syncthreads();
    }
    if (i < N_NODES) g_offsets[i] = sh[tid] - v;       // local exclusive
    if (tid == 255) g_bsum[b] = sh[255];
}

__global__ void scan2_kernel() {
    __shared__ int sh[SCAN_NB];
    int tid = threadIdx.x;
    int v = (tid < SCAN_NB) ? g_bsum[tid] : 0;
    if (tid < SCAN_NB) sh[tid] = v;
    __syncthreads();
    for (int o = 1; o < SCAN_NB; o <<= 1) {
        int t = (tid >= o && tid < SCAN_NB) ? sh[tid - o] : 0;
        __syncthreads();
        if (tid < SCAN_NB) sh[tid] += t;
        __syncthreads();
    }
    if (tid < SCAN_NB) g_bsum[tid] = sh[tid] - v;      // exclusive block offsets
    if (tid == 0) g_offsets[N_NODES] = E_TOT;
}

__global__ void scan3_kernel() {
    int b = blockIdx.x, tid = threadIdx.x;
    int i = b * 256 + tid;
    if (i >= N_NODES) return;
    int off = g_offsets[i] + g_bsum[b];
    g_offsets[i] = off;
    g_cursor[i] = off;
}

__global__ void scatter_kernel(const int* __restrict__ ei) {
    int e = blockIdx.x * blockDim.x + threadIdx.x;
    if (e >= E_TOT) return;
    int src, dst;
    if (e < N_EDGES) { src = ei[e]; dst = ei[N_EDGES + e]; }
    else             { src = e - N_EDGES; dst = src; }
    int pos = atomicAdd(&g_cursor[dst], 1);
    g_src_sorted[pos] = src;
}

// ---------------- attention coefficients ---------------------------------------
__global__ void att_coef1(const float* __restrict__ a_src, const float* __restrict__ a_dst) {
    int gw = (blockIdx.x * blockDim.x + threadIdx.x) >> 5;
    int lane = threadIdx.x & 31;
    if (gw >= N_NODES) return;
    const float* row = g_h1 + (size_t)gw * D1;
    float s[4] = {0, 0, 0, 0}, d[4] = {0, 0, 0, 0};
#pragma unroll
    for (int j = 0; j < 16; j++) {
        int c = lane + 32 * j;
        float v = row[c];
        s[j >> 2] = fmaf(v, a_src[c], s[j >> 2]);
        d[j >> 2] = fmaf(v, a_dst[c], d[j >> 2]);
    }
#pragma unroll
    for (int h = 0; h < 4; h++) { s[h] = warpSum(s[h]); d[h] = warpSum(d[h]); }
    if (lane == 0) {
#pragma unroll
        for (int h = 0; h < 4; h++) {
            g_als1[gw * 4 + h] = s[h];
            g_ald1[gw * 4 + h] = d[h];
        }
    }
}

__global__ void att_coef2(const float* __restrict__ a_src, const float* __restrict__ a_dst) {
    int gw = (blockIdx.x * blockDim.x + threadIdx.x) >> 5;
    int lane = threadIdx.x & 31;
    if (gw >= N_NODES) return;
    const float* row = g_h2 + (size_t)gw * HID;
    float s = 0.f, d = 0.f;
#pragma unroll
    for (int j = 0; j < 4; j++) {
        int c = lane + 32 * j;
        float v = row[c];
        s = fmaf(v, a_src[c], s);
        d = fmaf(v, a_dst[c], d);
    }
    s = warpSum(s); d = warpSum(d);
    if (lane == 0) { g_als2[gw] = s; g_ald2[gw] = d; }
}

// ---------------- GAT layer 1 softmax + aggregate (warp per dst node) ------------
// epilogue writes bf16 hi/lo split of relu(out) for the tensor-core GEMM2.
__global__ __launch_bounds__(256) void gat_agg1(const float* __restrict__ b1) {
    int gw = (blockIdx.x * blockDim.x + threadIdx.x) >> 5;
    int lane = threadIdx.x & 31;
    if (gw >= N_NODES) return;
    int beg = g_offsets[gw], end = g_offsets[gw + 1];

    float ald[4];
#pragma unroll
    for (int h = 0; h < 4; h++) ald[h] = g_ald1[gw * 4 + h];

    float mx[4] = {-1e30f, -1e30f, -1e30f, -1e30f};
    for (int i = beg + lane; i < end; i += 32) {
        int s = g_src_sorted[i];
#pragma unroll
        for (int h = 0; h < 4; h++) {
            float e = lrelu(g_als1[s * 4 + h] + ald[h]);
            mx[h] = fmaxf(mx[h], e);
        }
    }
#pragma unroll
    for (int h = 0; h < 4; h++) mx[h] = warpMax(mx[h]);

    float sm[4] = {0, 0, 0, 0};
    for (int i = beg + lane; i < end; i += 32) {
        int s = g_src_sorted[i];
        float4 ex4;
        float* exv = (float*)&ex4;
#pragma unroll
        for (int h = 0; h < 4; h++) {
            float e = lrelu(g_als1[s * 4 + h] + ald[h]);
            float ex = __expf(e - mx[h]);
            exv[h] = ex;
            sm[h] += ex;
        }
        ((float4*)g_alpha1)[i] = ex4;
    }
#pragma unroll
    for (int h = 0; h < 4; h++) sm[h] = warpSum(sm[h]);
    float inv[4];
#pragma unroll
    for (int h = 0; h < 4; h++) inv[h] = 1.f / sm[h];
    __syncwarp();

    float acc[16];
#pragma unroll
    for (int j = 0; j < 16; j++) acc[j] = 0.f;
    int i = beg;
    for (; i + 1 < end; i += 2) {
        int s0 = g_src_sorted[i], s1 = g_src_sorted[i + 1];
        float4 a0 = ((const float4*)g_alpha1)[i];
        float4 a1 = ((const float4*)g_alpha1)[i + 1];
        const float* h0 = g_h1 + (size_t)s0 * D1;
        const float* h1p = g_h1 + (size_t)s1 * D1;
#pragma unroll
        for (int j = 0; j < 16; j++) {
            float aa0 = (j < 4) ? a0.x : (j < 8) ? a0.y : (j < 12) ? a0.z : a0.w;
            float aa1 = (j < 4) ? a1.x : (j < 8) ? a1.y : (j < 12) ? a1.z : a1.w;
            int c = lane + 32 * j;
            acc[j] = fmaf(aa0, h0[c], acc[j]);
            acc[j] = fmaf(aa1, h1p[c], acc[j]);
        }
    }
    if (i < end) {
        int s0 = g_src_sorted[i];
        float4 a0 = ((const float4*)g_alpha1)[i];
        const float* h0 = g_h1 + (size_t)s0 * D1;
#pragma unroll
        for (int j = 0; j < 16; j++) {
            float aa0 = (j < 4) ? a0.x : (j < 8) ? a0.y : (j < 12) ? a0.z : a0.w;
            acc[j] = fmaf(aa0, h0[lane + 32 * j], acc[j]);
        }
    }
#pragma unroll
    for (int j = 0; j < 16; j++) {
        int c = lane + 32 * j;
        float v = fmaxf(acc[j] * inv[j >> 2] + b1[c], 0.f);
        __nv_bfloat16 hi = __float2bfloat16(v);
        g_o1h[(size_t)gw * D1 + c] = hi;
        g_o1l[(size_t)gw * D1 + c] = __float2bfloat16(v - __bfloat162float(hi));
    }
}

// ---------------- GAT layer 2 ----------------------------------------------------
__global__ __launch_bounds__(256) void gat_agg2(const float* __restrict__ b2) {
    int gw = (blockIdx.x * blockDim.x + threadIdx.x) >> 5;
    int lane = threadIdx.x & 31;
    if (gw >= N_NODES) return;
    int beg = g_offsets[gw], end = g_offsets[gw + 1];
    float ald = g_ald2[gw];

    float mx = -1e30f;
    for (int i = beg + lane; i < end; i += 32)
        mx = fmaxf(mx, lrelu(g_als2[g_src_sorted[i]] + ald));
    mx = warpMax(mx);

    float sm = 0.f;
    for (int i = beg + lane; i < end; i += 32) {
        float e = lrelu(g_als2[g_src_sorted[i]] + ald);
        float ex = __expf(e - mx);
        g_alpha2[i] = ex;
        sm += ex;
    }
    sm = warpSum(sm);
    float inv = 1.f / sm;
    __syncwarp();

    float acc[4] = {0, 0, 0, 0};
    int i = beg;
    for (; i + 1 < end; i += 2) {
        int s0 = g_src_sorted[i], s1 = g_src_sorted[i + 1];
        float a0 = g_alpha2[i], a1 = g_alpha2[i + 1];
        const float* h0 = g_h2 + (size_t)s0 * HID;
        const float* h1p = g_h2 + (size_t)s1 * HID;
#pragma unroll
        for (int j = 0; j < 4; j++) {
            int c = lane + 32 * j;
            acc[j] = fmaf(a0, h0[c], acc[j]);
            acc[j] = fmaf(a1, h1p[c], acc[j]);
        }
    }
    if (i < end) {
        int s0 = g_src_sorted[i];
        float a0 = g_alpha2[i];
        const float* h0 = g_h2 + (size_t)s0 * HID;
#pragma unroll
        for (int j = 0; j < 4; j++)
            acc[j] = fmaf(a0, h0[lane + 32 * j], acc[j]);
    }
#pragma unroll
    for (int j = 0; j < 4; j++) {
        int c = lane + 32 * j;
        float v = acc[j] * inv + b2[c];
        g_out2[(size_t)gw * HID + c] = fmaxf(v, 0.f);
    }
}

// ---------------- global mean pool -----------------------------------------------
__global__ void pool_kernel(const int* __restrict__ batch) {
    int gw = (blockIdx.x * blockDim.x + threadIdx.x) >> 5;
    int lane = threadIdx.x & 31;
    if (gw >= N_NODES) return;
    int g = batch[gw];
#pragma unroll
    for (int j = 0; j < 4; j++) {
        int c = lane + 32 * j;
        atomicAdd(&g_pool[g * HID + c], g_out2[(size_t)gw * HID + c]);
    }
    if (lane == 0) atomicAdd(&g_cnt[g], 1);
}

// ---------------- MLP head ---------------------------------------------------------
__global__ __launch_bounds__(1024) void mlp_kernel(
    const float* __restrict__ fc1_w, const float* __restrict__ fc1_b,
    const float* __restrict__ fc2_w, const float* __restrict__ fc2_b,
    float* __restrict__ out)
{
    __shared__ float pooled[NUM_GRAPHS * HID];
    __shared__ float z[NUM_GRAPHS * 64];
    int tid = threadIdx.x;
    for (int i = tid; i < NUM_GRAPHS * HID; i += blockDim.x) {
        int g = i / HID;
        float c = fmaxf((float)g_cnt[g], 1.f);
        pooled[i] = g_pool[i] / c;
    }
    __syncthreads();
    for (int i = tid; i < NUM_GRAPHS * 64; i += blockDim.x) {
        int g = i >> 6, j = i & 63;
        float acc = fc1_b[j];
        for (int k = 0; k < HID; k++)
            acc = fmaf(pooled[g * HID + k], fc1_w[k * 64 + j], acc);
        z[i] = fmaxf(acc, 0.f);
    }
    __syncthreads();
    for (int i = tid; i < NUM_GRAPHS * NUM_CLASSES; i += blockDim.x) {
        int g = i / NUM_CLASSES, c = i % NUM_CLASSES;
        float acc = fc2_b[c];
        for (int j = 0; j < 64; j++)
            acc = fmaf(z[g * 64 + j], fc2_w[j * NUM_CLASSES + c], acc);
        out[i] = acc;
    }
}

// ---------------- launch -------------------------------------------------------------
extern "C" void kernel_launch(void* const* d_in, const int* in_sizes, int n_in,
                              void* d_out, int out_size) {
    const float* x       = (const float*)d_in[0];
    const int*   ei      = (const int*)  d_in[1];
    const int*   batch   = (const int*)  d_in[2];
    const float* W1      = (const float*)d_in[3];
    const float* a_src1  = (const float*)d_in[4];
    const float* a_dst1  = (const float*)d_in[5];
    const float* b1      = (const float*)d_in[6];
    const float* W2      = (const float*)d_in[7];
    const float* a_src2  = (const float*)d_in[8];
    const float* a_dst2  = (const float*)d_in[9];
    const float* b2      = (const float*)d_in[10];
    const float* fc1_w   = (const float*)d_in[11];
    const float* fc1_b   = (const float*)d_in[12];
    const float* fc2_w   = (const float*)d_in[13];
    const float* fc2_b   = (const float*)d_in[14];
    float* out = (float*)d_out;

    static float* p_h1 = nullptr;
    static float* p_h2 = nullptr;
    static __nv_bfloat16 *p_xh, *p_xl, *p_o1h, *p_o1l, *p_b1h, *p_b1l, *p_b2h, *p_b2l;
    static bool inited = false;
    if (!inited) {
        cudaGetSymbolAddress((void**)&p_h1,  g_h1);
        cudaGetSymbolAddress((void**)&p_h2,  g_h2);
        cudaGetSymbolAddress((void**)&p_xh,  g_xh);
        cudaGetSymbolAddress((void**)&p_xl,  g_xl);
        cudaGetSymbolAddress((void**)&p_o1h, g_o1h);
        cudaGetSymbolAddress((void**)&p_o1l, g_o1l);
        cudaGetSymbolAddress((void**)&p_b1h, g_b1h);
        cudaGetSymbolAddress((void**)&p_b1l, g_b1l);
        cudaGetSymbolAddress((void**)&p_b2h, g_b2h);
        cudaGetSymbolAddress((void**)&p_b2l, g_b2l);
        cudaFuncSetAttribute(gemm_tc, cudaFuncAttributeMaxDynamicSharedMemorySize, 66560);
        inited = true;
    }

    // conversions + CSR prep
    cvt_w_kernel<<<(D1 * KP1 + HID * D1 + 255) / 256, 256>>>(W1, W2);
    cvt_x_kernel<<<(N_NODES * KP1 + 255) / 256, 256>>>(x);
    zero_kernel<<<(N_NODES + 255) / 256, 256>>>();
    hist_kernel<<<(E_TOT + 255) / 256, 256>>>(ei);
    scan1_kernel<<<SCAN_NB, 256>>>();
    scan2_kernel<<<1, 256>>>();
    scan3_kernel<<<SCAN_NB, 256>>>();
    scatter_kernel<<<(E_TOT + 255) / 256, 256>>>(ei);

    // GEMM1: h1 = x @ W1  [50000x814]@[814x512]
    {
        dim3 grid(D1 / 128, (N_NODES + 127) / 128);
        gemm_tc  <<<grid, 256, 66560>>>(p_xh, p_xl, p_b1h, p_b1l, p_h1, N_NODES, D1, KP1);
        gemm_simt<<<grid, 256>>>       (p_xh, p_xl, p_b1h, p_b1l, p_h1, N_NODES, D1, KP1);
    }

    att_coef1<<<(N_NODES * 32 + 255) / 256, 256>>>(a_src1, a_dst1);
    gat_agg1<<<(N_NODES * 32 + 255) / 256, 256>>>(b1);

    // GEMM2: h2 = out1 @ W2  [50000x512]@[512x128]
    {
        dim3 grid(HID / 128, (N_NODES + 127) / 128);
        gemm_tc  <<<grid, 256, 66560>>>(p_o1h, p_o1l, p_b2h, p_b2l, p_h2, N_NODES, HID, D1);
        gemm_simt<<<grid, 256>>>       (p_o1h, p_o1l, p_b2h, p_b2l, p_h2, N_NODES, HID, D1);
    }
    att_coef2<<<(N_NODES * 32 + 255) / 256, 256>>>(a_src2, a_dst2);
    gat_agg2<<<(N_NODES * 32 + 255) / 256, 256>>>(b2);

    pool_kernel<<<(N_NODES * 32 + 255) / 256, 256>>>(batch);
    mlp_kernel<<<1, 1024>>>(fc1_w, fc1_b, fc2_w, fc2_b, out);
}

// round 7
// speedup vs baseline: 1.7134x; 1.0511x over previous
#include <cuda_runtime.h>
#include <cuda_bf16.h>
#include <cstdint>
#include <math.h>

#define N_NODES 50000
#define N_EDGES 400000
#define E_TOT   450000
#define IN_CH   814
#define KP1     832          /* 814 padded to 13*64 */
#define HID     128
#define HEADS1  4
#define D1      (HEADS1*HID) /* 512 */
#define NUM_CLASSES 46
#define NUM_GRAPHS  64
#define NEG_SLOPE   0.2f
#define SCAN_NB  196

#if defined(__CUDA_ARCH_FEAT_SM103_ALL) || defined(__CUDA_ARCH_FEAT_SM100_ALL)
#define HAS_TC 1
#else
#define HAS_TC 0
#endif

// ---------------- scratch ------------------------------------------------------
__device__ float g_h1[N_NODES * D1];
__device__ float g_h2[N_NODES * HID];
__device__ float g_out2[N_NODES * HID];
__device__ __nv_bfloat16 g_xh[N_NODES * KP1];
__device__ __nv_bfloat16 g_xl[N_NODES * KP1];
__device__ __nv_bfloat16 g_o1h[N_NODES * D1];
__device__ __nv_bfloat16 g_o1l[N_NODES * D1];
__device__ __nv_bfloat16 g_b1h[D1 * KP1];
__device__ __nv_bfloat16 g_b1l[D1 * KP1];
__device__ __nv_bfloat16 g_b2h[HID * D1];
__device__ __nv_bfloat16 g_b2l[HID * D1];
__device__ float g_als1[N_NODES * HEADS1];
__device__ float g_ald1[N_NODES * HEADS1];
__device__ float g_als2[N_NODES];
__device__ float g_ald2[N_NODES];
__device__ int   g_counts[N_NODES];
__device__ int   g_offsets[N_NODES + 1];
__device__ int   g_cursor[N_NODES];
__device__ int   g_bsum[SCAN_NB];
__device__ int   g_src_sorted[E_TOT];
__device__ float g_alpha1[E_TOT * HEADS1];
__device__ float g_alpha2[E_TOT];
__device__ float g_pool[NUM_GRAPHS * HID];
__device__ int   g_cnt[NUM_GRAPHS];

// ---------------- PTX helpers ----------------------------------------------------
#if HAS_TC
__device__ __forceinline__ uint32_t smem_u32(const void* p) {
    uint32_t a;
    asm("{ .reg .u64 t; cvta.to.shared.u64 t, %1; cvt.u32.u64 %0, t; }" : "=r"(a) : "l"(p));
    return a;
}
__device__ __forceinline__ uint32_t elect_one() {
    uint32_t pred;
    asm volatile("{ .reg .pred p; elect.sync _|p, 0xFFFFFFFF; selp.b32 %0, 1, 0, p; }" : "=r"(pred));
    return pred;
}
#define MBAR_INIT(a, n)  asm volatile("mbarrier.init.shared.b64 [%0], %1;" :: "r"(a), "r"((uint32_t)(n)) : "memory")
#define MBAR_WAIT(a, ph) do { \
    uint32_t _m = (a), _p = (ph), _d; \
    asm volatile("{ .reg .pred p; mbarrier.try_wait.parity.acquire.cta.shared::cta.b64 p, [%1], %2; selp.b32 %0,1,0,p; }" \
        : "=r"(_d) : "r"(_m), "r"(_p) : "memory"); \
    if (!_d) { \
        asm volatile("{ .reg .pred P1;\nWL_%=:\nmbarrier.try_wait.parity.acquire.cta.shared::cta.b64 P1, [%0], %1, 0x989680;\n@P1 bra.uni WD_%=;\nbra.uni WL_%=;\nWD_%=:\n}" \
            :: "r"(_m), "r"(_p) : "memory"); \
    } } while (0)
#define TC_ALLOC(sa, n)   asm volatile("tcgen05.alloc.cta_group::1.sync.aligned.shared::cta.b32 [%0], %1;" :: "r"(sa), "r"((uint32_t)(n)) : "memory")
#define TC_DEALLOC(t, n)  asm volatile("tcgen05.dealloc.cta_group::1.sync.aligned.b32 %0, %1;" :: "r"(t), "r"((uint32_t)(n)))
#define TC_RELINQ()       asm volatile("tcgen05.relinquish_alloc_permit.cta_group::1.sync.aligned;")
#define TC_COMMIT(a)      asm volatile("tcgen05.commit.cta_group::1.mbarrier::arrive::one.shared::cluster.b64 [%0];" :: "r"(a) : "memory")
#define TC_FENCE_AFTER()  asm volatile("tcgen05.fence::after_thread_sync;" ::: "memory")
#define TC_FENCE_BEFORE() asm volatile("tcgen05.fence::before_thread_sync;" ::: "memory")
#define TC_WAIT_LD()      asm volatile("tcgen05.wait::ld.sync.aligned;" ::: "memory")
#define FENCE_ASYNC()     asm volatile("fence.proxy.async.shared::cta;" ::: "memory")
#define CP16(dst, src)    asm volatile("cp.async.ca.shared.global [%0], [%1], 16;" :: "r"(dst), "l"(src))
#define CP_COMMIT()       asm volatile("cp.async.commit_group;" ::: "memory")
#define CP_WAIT0()        asm volatile("cp.async.wait_group 0;" ::: "memory")

__device__ __forceinline__ void mma_f16_ss(uint32_t d, uint64_t ad, uint64_t bd,
                                           uint32_t idesc, bool accum) {
    uint32_t en = accum ? 1u : 0u, z = 0u;
    asm volatile(
        "{ .reg .pred p; setp.ne.u32 p, %5, 0;\n\t"
        "tcgen05.mma.cta_group::1.kind::f16 [%0], %1, %2, %3, {%4,%4,%4,%4}, p; }"
        :: "r"(d), "l"(ad), "l"(bd), "r"(idesc), "r"(z), "r"(en) : "memory");
}
__device__ __forceinline__ void tmem_ld32(uint32_t* r, uint32_t addr) {
    asm volatile(
        "tcgen05.ld.sync.aligned.32x32b.x32.b32 "
        "{%0,%1,%2,%3,%4,%5,%6,%7,%8,%9,%10,%11,%12,%13,%14,%15,"
        "%16,%17,%18,%19,%20,%21,%22,%23,%24,%25,%26,%27,%28,%29,%30,%31}, [%32];"
        : "=r"(r[0]), "=r"(r[1]), "=r"(r[2]), "=r"(r[3]), "=r"(r[4]), "=r"(r[5]), "=r"(r[6]), "=r"(r[7]),
          "=r"(r[8]), "=r"(r[9]), "=r"(r[10]), "=r"(r[11]), "=r"(r[12]), "=r"(r[13]), "=r"(r[14]), "=r"(r[15]),
          "=r"(r[16]), "=r"(r[17]), "=r"(r[18]), "=r"(r[19]), "=r"(r[20]), "=r"(r[21]), "=r"(r[22]), "=r"(r[23]),
          "=r"(r[24]), "=r"(r[25]), "=r"(r[26]), "=r"(r[27]), "=r"(r[28]), "=r"(r[29]), "=r"(r[30]), "=r"(r[31])
        : "r"(addr));
}
#define DESC_SW128(addr) ((uint64_t(2) << 61) | (uint64_t(1) << 46) | (uint64_t(64) << 32) \
                          | (uint64_t(1) << 16) | ((uint64_t)((addr) >> 4) & 0x3FFF))

// 256-thread tile load: thread t covers row r=t>>1, half h=t&1 (64B), 4x cp.async 16B
__device__ __forceinline__ void load_tile_async(uint32_t dstBase, const __nv_bfloat16* rowSrc,
                                                int half) {
    const char* src = (const char*)rowSrc + half * 64;
    int r = threadIdx.x >> 1;
#pragma unroll
    for (int i = 0; i < 4; i++) {
        uint32_t byte = r * 128 + half * 64 + i * 16;
        uint32_t a = dstBase + (byte ^ ((byte >> 3) & 0x70));
        CP16(a, src + i * 16);
    }
}
#endif // HAS_TC

// -------- tcgen05 bf16x3 GEMM, single K-pass, fused attention-coef epilogue --------
// Ah/Al [M,kp], Bh/Bl [N,kp]. Per 64-K chunk: D += Ah*Bh + Al*Bh + Ah*Bl (12 MMAs).
// Epilogue also computes als/ald = dot(C_row_headcols, asrc/adst) since each
// N-block (128 cols) is exactly one attention head.
__global__ void __launch_bounds__(256)
gemm_tc(const __nv_bfloat16* __restrict__ Ah, const __nv_bfloat16* __restrict__ Al,
        const __nv_bfloat16* __restrict__ Bh, const __nv_bfloat16* __restrict__ Bl,
        float* __restrict__ C, int M, int ldc, int kp,
        const float* __restrict__ asrc, const float* __restrict__ adst,
        float* __restrict__ als, float* __restrict__ ald, int nheads)
{
#if HAS_TC
    extern __shared__ char dsm[];
    uint32_t sb = smem_u32(dsm);
    uint32_t base = (sb + 1023) & ~1023u;
    const uint32_t TM_PTR = base;
    const uint32_t MBAR   = base + 8;
    const uint32_t T0 = base + 1024;       // AH@0 AL@16K BH@32K BL@48K ; buf stride 64K
    const uint32_t BUFSZ = 65536;

    int tid = threadIdx.x, wid = tid >> 5, lane = tid & 31;
    int m0 = blockIdx.y * 128, n0 = blockIdx.x * 128;
    int half = tid & 1, r = tid >> 1;

    if (wid == 0) { TC_ALLOC(TM_PTR, 128); TC_RELINQ(); }
    if (tid == 0) MBAR_INIT(MBAR, 1);
    __syncthreads();
    uint32_t tmem;
    asm volatile("ld.shared.b32 %0, [%1];" : "=r"(tmem) : "r"(TM_PTR));

    const int NCK = kp >> 6;

    int arow = m0 + r; if (arow >= M) arow = M - 1;
    const __nv_bfloat16* aHrow = Ah + (size_t)arow * kp;
    const __nv_bfloat16* aLrow = Al + (size_t)arow * kp;
    const __nv_bfloat16* bHrow = Bh + (size_t)(n0 + r) * kp;
    const __nv_bfloat16* bLrow = Bl + (size_t)(n0 + r) * kp;

    const uint32_t IDESC = 0x8200490u;  // fp32 acc, bf16 a/b, N=128, M=128

    // prologue: chunk 0 into buffer 0
    load_tile_async(T0,         aHrow, half);
    load_tile_async(T0 + 16384, aLrow, half);
    load_tile_async(T0 + 32768, bHrow, half);
    load_tile_async(T0 + 49152, bLrow, half);
    CP_COMMIT();

    for (int c = 0; c < NCK; c++) {
        uint32_t buf = T0 + (c & 1) * BUFSZ;
        CP_WAIT0();
        __syncthreads();
        FENCE_ASYNC();
        if (wid == 0 && elect_one()) {
            uint64_t dAH = DESC_SW128(buf);
            uint64_t dAL = DESC_SW128(buf + 16384);
            uint64_t dBH = DESC_SW128(buf + 32768);
            uint64_t dBL = DESC_SW128(buf + 49152);
#pragma unroll
            for (int k = 0; k < 4; k++) mma_f16_ss(tmem, dAH + 2 * k, dBH + 2 * k, IDESC, !(c == 0 && k == 0));
#pragma unroll
            for (int k = 0; k < 4; k++) mma_f16_ss(tmem, dAL + 2 * k, dBH + 2 * k, IDESC, true);
#pragma unroll
            for (int k = 0; k < 4; k++) mma_f16_ss(tmem, dAH + 2 * k, dBL + 2 * k, IDESC, true);
            TC_COMMIT(MBAR);
        }
        if (c + 1 < NCK) {
            uint32_t nb = T0 + ((c + 1) & 1) * BUFSZ;
            int kc = (c + 1) << 6;
            load_tile_async(nb,         aHrow + kc, half);
            load_tile_async(nb + 16384, aLrow + kc, half);
            load_tile_async(nb + 32768, bHrow + kc, half);
            load_tile_async(nb + 49152, bLrow + kc, half);
            CP_COMMIT();
        }
        MBAR_WAIT(MBAR, c & 1);
        __syncthreads();
    }

    TC_FENCE_AFTER();
    // epilogue: warps 0-3 read 32-row subpartitions; fused attention dots
    if (wid < 4) {
        int row = m0 + wid * 32 + lane;
        int head = blockIdx.x;
        float s = 0.f, d = 0.f;
#pragma unroll
        for (int nb = 0; nb < 4; nb++) {
            uint32_t rg[32];
            tmem_ld32(rg, tmem + nb * 32);
            TC_WAIT_LD();
            if (row < M) {
                float4* dst = (float4*)(C + (size_t)row * ldc + n0 + nb * 32);
#pragma unroll
                for (int i = 0; i < 8; i++)
                    dst[i] = make_float4(__uint_as_float(rg[4 * i]), __uint_as_float(rg[4 * i + 1]),
                                         __uint_as_float(rg[4 * i + 2]), __uint_as_float(rg[4 * i + 3]));
            }
#pragma unroll
            for (int i = 0; i < 32; i++) {
                float v = __uint_as_float(rg[i]);
                int col = head * 128 + nb * 32 + i;
                s = fmaf(v, __ldg(&asrc[col]), s);
                d = fmaf(v, __ldg(&adst[col]), d);
            }
        }
        if (row < M) {
            als[(size_t)row * nheads + head] = s;
            ald[(size_t)row * nheads + head] = d;
        }
        TC_FENCE_BEFORE();
    }
    __syncthreads();
    if (wid == 0) TC_DEALLOC(tmem, 128);
#endif
}

// ---------------- SIMT fallback (active only when !HAS_TC) ---------------------
__global__ __launch_bounds__(256) void gemm_simt(
    const __nv_bfloat16* __restrict__ Ah, const __nv_bfloat16* __restrict__ Al,
    const __nv_bfloat16* __restrict__ Bh, const __nv_bfloat16* __restrict__ Bl,
    float* __restrict__ C, int M, int ldc, int kp)
{
#if !HAS_TC
    __shared__ float As[8][128];
    __shared__ float Bs[8][128];
    int tid = threadIdx.x;
    int tx = tid & 15, ty = tid >> 4;
    int rowBase = blockIdx.y * 128;
    int colBase = blockIdx.x * 128;
    int N = gridDim.x * 128;

    float acc[8][8];
#pragma unroll
    for (int i = 0; i < 8; i++)
#pragma unroll
        for (int j = 0; j < 8; j++) acc[i][j] = 0.f;

    for (int k0 = 0; k0 < kp; k0 += 8) {
#pragma unroll
        for (int i = 0; i < 4; i++) {
            int idx = tid + 256 * i;
            int rr = idx >> 3, cc = idx & 7;
            int gr = rowBase + rr;
            float v = 0.f;
            if (gr < M) {
                size_t o = (size_t)gr * kp + k0 + cc;
                v = __bfloat162float(Ah[o]) + __bfloat162float(Al[o]);
            }
            As[cc][rr] = v;
        }
#pragma unroll
        for (int i = 0; i < 4; i++) {
            int idx = tid + 256 * i;
            int nl = idx >> 3, kk = idx & 7;
            int gn = colBase + nl;
            float v = 0.f;
            if (gn < N) {
                size_t o = (size_t)gn * kp + k0 + kk;
                v = __bfloat162float(Bh[o]) + __bfloat162float(Bl[o]);
            }
            Bs[kk][nl] = v;
        }
        __syncthreads();
#pragma unroll
        for (int kk = 0; kk < 8; kk++) {
            float a[8], b[8];
#pragma unroll
            for (int i = 0; i < 8; i++) a[i] = As[kk][ty * 8 + i];
#pragma unroll
            for (int j = 0; j < 8; j++) b[j] = Bs[kk][tx * 8 + j];
#pragma unroll
            for (int i = 0; i < 8; i++)
#pragma unroll
                for (int j = 0; j < 8; j++) acc[i][j] = fmaf(a[i], b[j], acc[i][j]);
        }
        __syncthreads();
    }
#pragma unroll
    for (int i = 0; i < 8; i++) {
        int gr = rowBase + ty * 8 + i;
        if (gr >= M) continue;
#pragma unroll
        for (int j = 0; j < 8; j++)
            C[(size_t)gr * ldc + colBase + tx * 8 + j] = acc[i][j];
    }
#endif
}

// ---------------- conversions ------------------------------------------------
__global__ void cvt_w_kernel(const float* __restrict__ W1, const float* __restrict__ W2) {
    int idx = blockIdx.x * blockDim.x + threadIdx.x;
    const int n1 = D1 * KP1;
    if (idx < n1) {
        int n = idx / KP1, k = idx - n * KP1;
        float v = (k < IN_CH) ? W1[(size_t)k * D1 + n] : 0.f;
        __nv_bfloat16 hi = __float2bfloat16(v);
        g_b1h[idx] = hi;
        g_b1l[idx] = __float2bfloat16(v - __bfloat162float(hi));
        return;
    }
    int j = idx - n1;
    if (j < HID * D1) {
        int n = j / D1, k = j - n * D1;
        float v = W2[(size_t)k * HID + n];
        __nv_bfloat16 hi = __float2bfloat16(v);
        g_b2h[j] = hi;
        g_b2l[j] = __float2bfloat16(v - __bfloat162float(hi));
    }
}

__global__ void cvt_x_kernel(const float* __restrict__ x) {
    int idx = blockIdx.x * blockDim.x + threadIdx.x;
    if (idx >= N_NODES * KP1) return;
    int row = idx / KP1, k = idx - row * KP1;
    float v = (k < IN_CH) ? x[(size_t)row * IN_CH + k] : 0.f;
    __nv_bfloat16 hi = __float2bfloat16(v);
    g_xh[idx] = hi;
    g_xl[idx] = __float2bfloat16(v - __bfloat162float(hi));
}

// ---------------- misc helpers -----------------------------------------------
__device__ __forceinline__ float warpMax(float v) {
#pragma unroll
    for (int o = 16; o > 0; o >>= 1) v = fmaxf(v, __shfl_xor_sync(0xffffffffu, v, o));
    return v;
}
__device__ __forceinline__ float warpSum(float v) {
#pragma unroll
    for (int o = 16; o > 0; o >>= 1) v += __shfl_xor_sync(0xffffffffu, v, o);
    return v;
}
__device__ __forceinline__ float lrelu(float x) { return x > 0.f ? x : NEG_SLOPE * x; }

__global__ void zero_kernel() {
    int i = blockIdx.x * blockDim.x + threadIdx.x;
    if (i < N_NODES) g_counts[i] = 0;
    if (i < NUM_GRAPHS * HID) g_pool[i] = 0.f;
    if (i < NUM_GRAPHS) g_cnt[i] = 0;
}

__global__ void hist_kernel(const int* __restrict__ ei) {
    int e = blockIdx.x * blockDim.x + threadIdx.x;
    if (e >= E_TOT) return;
    int dst = (e < N_EDGES) ? ei[N_EDGES + e] : (e - N_EDGES);
    atomicAdd(&g_counts[dst], 1);
}

// ------- multi-block exclusive scan over g_counts (3 stages) -------------------
__global__ void scan1_kernel() {
    __shared__ int sh[256];
    int b = blockIdx.x, tid = threadIdx.x;
    int i = b * 256 + tid;
    int v = (i < N_NODES) ? g_counts[i] : 0;
    sh[tid] = v;
    __syncthreads();
#pragma unroll
    for (int o = 1; o < 256; o <<= 1) {
        int t = (tid >= o) ? sh[tid - o] : 0;
        __syncthreads();
        sh[tid] += t;
        __syncthreads();
    }
    if (i < N_NODES) g_offsets[i] = sh[tid] - v;
    if (tid == 255) g_bsum[b] = sh[255];
}

__global__ void scan2_kernel() {
    __shared__ int sh[SCAN_NB];
    int tid = threadIdx.x;
    int v = (tid < SCAN_NB) ? g_bsum[tid] : 0;
    if (tid < SCAN_NB) sh[tid] = v;
    __syncthreads();
    for (int o = 1; o < SCAN_NB; o <<= 1) {
        int t = (tid >= o && tid < SCAN_NB) ? sh[tid - o] : 0;
        __syncthreads();
        if (tid < SCAN_NB) sh[tid] += t;
        __syncthreads();
    }
    if (tid < SCAN_NB) g_bsum[tid] = sh[tid] - v;
    if (tid == 0) g_offsets[N_NODES] = E_TOT;
}

__global__ void scan3_kernel() {
    int b = blockIdx.x, tid = threadIdx.x;
    int i = b * 256 + tid;
    if (i >= N_NODES) return;
    int off = g_offsets[i] + g_bsum[b];
    g_offsets[i] = off;
    g_cursor[i] = off;
}

__global__ void scatter_kernel(const int* __restrict__ ei) {
    int e = blockIdx.x * blockDim.x + threadIdx.x;
    if (e >= E_TOT) return;
    int src, dst;
    if (e < N_EDGES) { src = ei[e]; dst = ei[N_EDGES + e]; }
    else             { src = e - N_EDGES; dst = src; }
    int pos = atomicAdd(&g_cursor[dst], 1);
    g_src_sorted[pos] = src;
}

// ---------------- attention coefficients (fallback only; TC path fuses into GEMM) --
__global__ void att_coef1(const float* __restrict__ a_src, const float* __restrict__ a_dst) {
#if !HAS_TC
    int gw = (blockIdx.x * blockDim.x + threadIdx.x) >> 5;
    int lane = threadIdx.x & 31;
    if (gw >= N_NODES) return;
    const float* row = g_h1 + (size_t)gw * D1;
    float s[4] = {0, 0, 0, 0}, d[4] = {0, 0, 0, 0};
#pragma unroll
    for (int j = 0; j < 16; j++) {
        int c = lane + 32 * j;
        float v = row[c];
        s[j >> 2] = fmaf(v, a_src[c], s[j >> 2]);
        d[j >> 2] = fmaf(v, a_dst[c], d[j >> 2]);
    }
#pragma unroll
    for (int h = 0; h < 4; h++) { s[h] = warpSum(s[h]); d[h] = warpSum(d[h]); }
    if (lane == 0) {
#pragma unroll
        for (int h = 0; h < 4; h++) {
            g_als1[gw * 4 + h] = s[h];
            g_ald1[gw * 4 + h] = d[h];
        }
    }
#endif
}

__global__ void att_coef2(const float* __restrict__ a_src, const float* __restrict__ a_dst) {
#if !HAS_TC
    int gw = (blockIdx.x * blockDim.x + threadIdx.x) >> 5;
    int lane = threadIdx.x & 31;
    if (gw >= N_NODES) return;
    const float* row = g_h2 + (size_t)gw * HID;
    float s = 0.f, d = 0.f;
#pragma unroll
    for (int j = 0; j < 4; j++) {
        int c = lane + 32 * j;
        float v = row[c];
        s = fmaf(v, a_src[c], s);
        d = fmaf(v, a_dst[c], d);
    }
    s = warpSum(s); d = warpSum(d);
    if (lane == 0) { g_als2[gw] = s; g_ald2[gw] = d; }
#endif
}

// ---------------- GAT layer 1 softmax + aggregate (warp per dst node) ------------
__global__ __launch_bounds__(256) void gat_agg1(const float* __restrict__ b1) {
    int gw = (blockIdx.x * blockDim.x + threadIdx.x) >> 5;
    int lane = threadIdx.x & 31;
    if (gw >= N_NODES) return;
    int beg = g_offsets[gw], end = g_offsets[gw + 1];

    float ald[4];
#pragma unroll
    for (int h = 0; h < 4; h++) ald[h] = g_ald1[gw * 4 + h];

    float mx[4] = {-1e30f, -1e30f, -1e30f, -1e30f};
    for (int i = beg + lane; i < end; i += 32) {
        int s = g_src_sorted[i];
#pragma unroll
        for (int h = 0; h < 4; h++) {
            float e = lrelu(g_als1[s * 4 + h] + ald[h]);
            mx[h] = fmaxf(mx[h], e);
        }
    }
#pragma unroll
    for (int h = 0; h < 4; h++) mx[h] = warpMax(mx[h]);

    float sm[4] = {0, 0, 0, 0};
    for (int i = beg + lane; i < end; i += 32) {
        int s = g_src_sorted[i];
        float4 ex4;
        float* exv = (float*)&ex4;
#pragma unroll
        for (int h = 0; h < 4; h++) {
            float e = lrelu(g_als1[s * 4 + h] + ald[h]);
            float ex = __expf(e - mx[h]);
            exv[h] = ex;
            sm[h] += ex;
        }
        ((float4*)g_alpha1)[i] = ex4;
    }
#pragma unroll
    for (int h = 0; h < 4; h++) sm[h] = warpSum(sm[h]);
    float inv[4];
#pragma unroll
    for (int h = 0; h < 4; h++) inv[h] = 1.f / sm[h];
    __syncwarp();

    float acc[16];
#pragma unroll
    for (int j = 0; j < 16; j++) acc[j] = 0.f;
    int i = beg;
    for (; i + 3 < end; i += 4) {
        int s0 = g_src_sorted[i],     s1 = g_src_sorted[i + 1];
        int s2 = g_src_sorted[i + 2], s3 = g_src_sorted[i + 3];
        float4 a0 = ((const float4*)g_alpha1)[i];
        float4 a1 = ((const float4*)g_alpha1)[i + 1];
        float4 a2 = ((const float4*)g_alpha1)[i + 2];
        float4 a3 = ((const float4*)g_alpha1)[i + 3];
        const float* h0 = g_h1 + (size_t)s0 * D1;
        const float* h1p = g_h1 + (size_t)s1 * D1;
        const float* h2p = g_h1 + (size_t)s2 * D1;
        const float* h3p = g_h1 + (size_t)s3 * D1;
#pragma unroll
        for (int j = 0; j < 16; j++) {
            int c = lane + 32 * j;
            float aa0 = (j < 4) ? a0.x : (j < 8) ? a0.y : (j < 12) ? a0.z : a0.w;
            float aa1 = (j < 4) ? a1.x : (j < 8) ? a1.y : (j < 12) ? a1.z : a1.w;
            float aa2 = (j < 4) ? a2.x : (j < 8) ? a2.y : (j < 12) ? a2.z : a2.w;
            float aa3 = (j < 4) ? a3.x : (j < 8) ? a3.y : (j < 12) ? a3.z : a3.w;
            acc[j] = fmaf(aa0, h0[c], acc[j]);
            acc[j] = fmaf(aa1, h1p[c], acc[j]);
            acc[j] = fmaf(aa2, h2p[c], acc[j]);
            acc[j] = fmaf(aa3, h3p[c], acc[j]);
        }
    }
    for (; i < end; i++) {
        int s0 = g_src_sorted[i];
        float4 a0 = ((const float4*)g_alpha1)[i];
        const float* h0 = g_h1 + (size_t)s0 * D1;
#pragma unroll
        for (int j = 0; j < 16; j++) {
            float aa0 = (j < 4) ? a0.x : (j < 8) ? a0.y : (j < 12) ? a0.z : a0.w;
            acc[j] = fmaf(aa0, h0[lane + 32 * j], acc[j]);
        }
    }
#pragma unroll
    for (int j = 0; j < 16; j++) {
        int c = lane + 32 * j;
        float v = fmaxf(acc[j] * inv[j >> 2] + b1[c], 0.f);
        __nv_bfloat16 hi = __float2bfloat16(v);
        g_o1h[(size_t)gw * D1 + c] = hi;
        g_o1l[(size_t)gw * D1 + c] = __float2bfloat16(v - __bfloat162float(hi));
    }
}

// ---------------- GAT layer 2 ----------------------------------------------------
__global__ __launch_bounds__(256) void gat_agg2(const float* __restrict__ b2) {
    int gw = (blockIdx.x * blockDim.x + threadIdx.x) >> 5;
    int lane = threadIdx.x & 31;
    if (gw >= N_NODES) return;
    int beg = g_offsets[gw], end = g_offsets[gw + 1];
    float ald = g_ald2[gw];

    float mx = -1e30f;
    for (int i = beg + lane; i < end; i += 32)
        mx = fmaxf(mx, lrelu(g_als2[g_src_sorted[i]] + ald));
    mx = warpMax(mx);

    float sm = 0.f;
    for (int i = beg + lane; i < end; i += 32) {
        float e = lrelu(g_als2[g_src_sorted[i]] + ald);
        float ex = __expf(e - mx);
        g_alpha2[i] = ex;
        sm += ex;
    }
    sm = warpSum(sm);
    float inv = 1.f / sm;
    __syncwarp();

    float acc[4] = {0, 0, 0, 0};
    int i = beg;
    for (; i + 3 < end; i += 4) {
        int s0 = g_src_sorted[i],     s1 = g_src_sorted[i + 1];
        int s2 = g_src_sorted[i + 2], s3 = g_src_sorted[i + 3];
        float a0 = g_alpha2[i],     a1 = g_alpha2[i + 1];
        float a2 = g_alpha2[i + 2], a3 = g_alpha2[i + 3];
        const float* h0 = g_h2 + (size_t)s0 * HID;
        const float* h1p = g_h2 + (size_t)s1 * HID;
        const float* h2p = g_h2 + (size_t)s2 * HID;
        const float* h3p = g_h2 + (size_t)s3 * HID;
#pragma unroll
        for (int j = 0; j < 4; j++) {
            int c = lane + 32 * j;
            acc[j] = fmaf(a0, h0[c], acc[j]);
            acc[j] = fmaf(a1, h1p[c], acc[j]);
            acc[j] = fmaf(a2, h2p[c], acc[j]);
            acc[j] = fmaf(a3, h3p[c], acc[j]);
        }
    }
    for (; i < end; i++) {
        int s0 = g_src_sorted[i];
        float a0 = g_alpha2[i];
        const float* h0 = g_h2 + (size_t)s0 * HID;
#pragma unroll
        for (int j = 0; j < 4; j++)
            acc[j] = fmaf(a0, h0[lane + 32 * j], acc[j]);
    }
#pragma unroll
    for (int j = 0; j < 4; j++) {
        int c = lane + 32 * j;
        float v = acc[j] * inv + b2[c];
        g_out2[(size_t)gw * HID + c] = fmaxf(v, 0.f);
    }
}

// ---------------- global mean pool -----------------------------------------------
__global__ void pool_kernel(const int* __restrict__ batch) {
    int gw = (blockIdx.x * blockDim.x + threadIdx.x) >> 5;
    int lane = threadIdx.x & 31;
    if (gw >= N_NODES) return;
    int g = batch[gw];
#pragma unroll
    for (int j = 0; j < 4; j++) {
        int c = lane + 32 * j;
        atomicAdd(&g_pool[g * HID + c], g_out2[(size_t)gw * HID + c]);
    }
    if (lane == 0) atomicAdd(&g_cnt[g], 1);
}

// ---------------- MLP head ---------------------------------------------------------
__global__ __launch_bounds__(1024) void mlp_kernel(
    const float* __restrict__ fc1_w, const float* __restrict__ fc1_b,
    const float* __restrict__ fc2_w, const float* __restrict__ fc2_b,
    float* __restrict__ out)
{
    __shared__ float pooled[NUM_GRAPHS * HID];
    __shared__ float z[NUM_GRAPHS * 64];
    int tid = threadIdx.x;
    for (int i = tid; i < NUM_GRAPHS * HID; i += blockDim.x) {
        int g = i / HID;
        float c = fmaxf((float)g_cnt[g], 1.f);
        pooled[i] = g_pool[i] / c;
    }
    __syncthreads();
    for (int i = tid; i < NUM_GRAPHS * 64; i += blockDim.x) {
        int g = i >> 6, j = i & 63;
        float acc = fc1_b[j];
        for (int k = 0; k < HID; k++)
            acc = fmaf(pooled[g * HID + k], fc1_w[k * 64 + j], acc);
        z[i] = fmaxf(acc, 0.f);
    }
    __syncthreads();
    for (int i = tid; i < NUM_GRAPHS * NUM_CLASSES; i += blockDim.x) {
        int g = i / NUM_CLASSES, c = i % NUM_CLASSES;
        float acc = fc2_b[c];
        for (int j = 0; j < 64; j++)
            acc = fmaf(z[g * 64 + j], fc2_w[j * NUM_CLASSES + c], acc);
        out[i] = acc;
    }
}

// ---------------- launch -------------------------------------------------------------
extern "C" void kernel_launch(void* const* d_in, const int* in_sizes, int n_in,
                              void* d_out, int out_size) {
    const float* x       = (const float*)d_in[0];
    const int*   ei      = (const int*)  d_in[1];
    const int*   batch   = (const int*)  d_in[2];
    const float* W1      = (const float*)d_in[3];
    const float* a_src1  = (const float*)d_in[4];
    const float* a_dst1  = (const float*)d_in[5];
    const float* b1      = (const float*)d_in[6];
    const float* W2      = (const float*)d_in[7];
    const float* a_src2  = (const float*)d_in[8];
    const float* a_dst2  = (const float*)d_in[9];
    const float* b2      = (const float*)d_in[10];
    const float* fc1_w   = (const float*)d_in[11];
    const float* fc1_b   = (const float*)d_in[12];
    const float* fc2_w   = (const float*)d_in[13];
    const float* fc2_b   = (const float*)d_in[14];
    float* out = (float*)d_out;

    static float *p_h1, *p_h2, *p_als1, *p_ald1, *p_als2, *p_ald2;
    static __nv_bfloat16 *p_xh, *p_xl, *p_o1h, *p_o1l, *p_b1h, *p_b1l, *p_b2h, *p_b2l;
    static bool inited = false;
    if (!inited) {
        cudaGetSymbolAddress((void**)&p_h1,   g_h1);
        cudaGetSymbolAddress((void**)&p_h2,   g_h2);
        cudaGetSymbolAddress((void**)&p_als1, g_als1);
        cudaGetSymbolAddress((void**)&p_ald1, g_ald1);
        cudaGetSymbolAddress((void**)&p_als2, g_als2);
        cudaGetSymbolAddress((void**)&p_ald2, g_ald2);
        cudaGetSymbolAddress((void**)&p_xh,  g_xh);
        cudaGetSymbolAddress((void**)&p_xl,  g_xl);
        cudaGetSymbolAddress((void**)&p_o1h, g_o1h);
        cudaGetSymbolAddress((void**)&p_o1l, g_o1l);
        cudaGetSymbolAddress((void**)&p_b1h, g_b1h);
        cudaGetSymbolAddress((void**)&p_b1l, g_b1l);
        cudaGetSymbolAddress((void**)&p_b2h, g_b2h);
        cudaGetSymbolAddress((void**)&p_b2l, g_b2l);
        cudaFuncSetAttribute(gemm_tc, cudaFuncAttributeMaxDynamicSharedMemorySize, 132096);
        inited = true;
    }

    // conversions + CSR prep
    cvt_w_kernel<<<(D1 * KP1 + HID * D1 + 255) / 256, 256>>>(W1, W2);
    cvt_x_kernel<<<(N_NODES * KP1 + 255) / 256, 256>>>(x);
    zero_kernel<<<(N_NODES + 255) / 256, 256>>>();
    hist_kernel<<<(E_TOT + 255) / 256, 256>>>(ei);
    scan1_kernel<<<SCAN_NB, 256>>>();
    scan2_kernel<<<1, 256>>>();
    scan3_kernel<<<SCAN_NB, 256>>>();
    scatter_kernel<<<(E_TOT + 255) / 256, 256>>>(ei);

    // GEMM1: h1 = x @ W1  [50000x814]@[814x512] + fused attention coefs
    {
        dim3 grid(D1 / 128, (N_NODES + 127) / 128);
        gemm_tc<<<grid, 256, 132096>>>(p_xh, p_xl, p_b1h, p_b1l, p_h1, N_NODES, D1, KP1,
                                       a_src1, a_dst1, p_als1, p_ald1, HEADS1);
        gemm_simt<<<grid, 256>>>(p_xh, p_xl, p_b1h, p_b1l, p_h1, N_NODES, D1, KP1);
        att_coef1<<<(N_NODES * 32 + 255) / 256, 256>>>(a_src1, a_dst1);  // no-op on TC path
    }

    gat_agg1<<<(N_NODES * 32 + 255) / 256, 256>>>(b1);

    // GEMM2: h2 = out1 @ W2  [50000x512]@[512x128] + fused attention coefs
    {
        dim3 grid(HID / 128, (N_NODES + 127) / 128);
        gemm_tc<<<grid, 256, 132096>>>(p_o1h, p_o1l, p_b2h, p_b2l, p_h2, N_NODES, HID, D1,
                                       a_src2, a_dst2, p_als2, p_ald2, 1);
        gemm_simt<<<grid, 256>>>(p_o1h, p_o1l, p_b2h, p_b2l, p_h2, N_NODES, HID, D1);
        att_coef2<<<(N_NODES * 32 + 255) / 256, 256>>>(a_src2, a_dst2);  // no-op on TC path
    }
    gat_agg2<<<(N_NODES * 32 + 255) / 256, 256>>>(b2);

    pool_kernel<<<(N_NODES * 32 + 255) / 256, 256>>>(batch);
    mlp_kernel<<<1, 1024>>>(fc1_w, fc1_b, fc2_w, fc2_b, out);
}

// round 8
// speedup vs baseline: 1.8472x; 1.0781x over previous
#include <cuda_runtime.h>
#include <cuda_bf16.h>
#include <cstdint>
#include <math.h>

#define N_NODES 50000
#define N_EDGES 400000
#define E_TOT   450000
#define IN_CH   814
#define KP1     832          /* 814 padded to 13*64 */
#define HID     128
#define HEADS1  4
#define D1      (HEADS1*HID) /* 512 */
#define NUM_CLASSES 46
#define NUM_GRAPHS  64
#define NEG_SLOPE   0.2f
#define SCAN_NB  196

#if defined(__CUDA_ARCH_FEAT_SM103_ALL) || defined(__CUDA_ARCH_FEAT_SM100_ALL)
#define HAS_TC 1
#else
#define HAS_TC 0
#endif

// ---------------- scratch ------------------------------------------------------
__device__ float g_h1[N_NODES * D1];
__device__ float g_h2[N_NODES * HID];
__device__ float g_out2[N_NODES * HID];
__device__ __nv_bfloat16 g_xh[N_NODES * KP1];
__device__ __nv_bfloat16 g_xl[N_NODES * KP1];
__device__ __nv_bfloat16 g_o1h[N_NODES * D1];
__device__ __nv_bfloat16 g_o1l[N_NODES * D1];
__device__ __nv_bfloat16 g_b1h[D1 * KP1];
__device__ __nv_bfloat16 g_b1l[D1 * KP1];
__device__ __nv_bfloat16 g_b2h[HID * D1];
__device__ __nv_bfloat16 g_b2l[HID * D1];
__device__ float g_als1[N_NODES * HEADS1];
__device__ float g_ald1[N_NODES * HEADS1];
__device__ float g_als2[N_NODES];
__device__ float g_ald2[N_NODES];
__device__ int   g_counts[N_NODES];
__device__ int   g_offsets[N_NODES + 1];
__device__ int   g_cursor[N_NODES];
__device__ int   g_bsum[SCAN_NB];
__device__ int   g_src_sorted[E_TOT];
__device__ float g_alpha1[E_TOT * HEADS1];
__device__ float g_alpha2[E_TOT];
__device__ float g_pool[NUM_GRAPHS * HID];
__device__ int   g_cnt[NUM_GRAPHS];

// ---------------- PTX helpers ----------------------------------------------------
#if HAS_TC
__device__ __forceinline__ uint32_t smem_u32(const void* p) {
    uint32_t a;
    asm("{ .reg .u64 t; cvta.to.shared.u64 t, %1; cvt.u32.u64 %0, t; }" : "=r"(a) : "l"(p));
    return a;
}
__device__ __forceinline__ uint32_t elect_one() {
    uint32_t pred;
    asm volatile("{ .reg .pred p; elect.sync _|p, 0xFFFFFFFF; selp.b32 %0, 1, 0, p; }" : "=r"(pred));
    return pred;
}
#define MBAR_INIT(a, n)  asm volatile("mbarrier.init.shared.b64 [%0], %1;" :: "r"(a), "r"((uint32_t)(n)) : "memory")
#define MBAR_WAIT(a, ph) do { \
    uint32_t _m = (a), _p = (ph), _d; \
    asm volatile("{ .reg .pred p; mbarrier.try_wait.parity.acquire.cta.shared::cta.b64 p, [%1], %2; selp.b32 %0,1,0,p; }" \
        : "=r"(_d) : "r"(_m), "r"(_p) : "memory"); \
    if (!_d) { \
        asm volatile("{ .reg .pred P1;\nWL_%=:\nmbarrier.try_wait.parity.acquire.cta.shared::cta.b64 P1, [%0], %1, 0x989680;\n@P1 bra.uni WD_%=;\nbra.uni WL_%=;\nWD_%=:\n}" \
            :: "r"(_m), "r"(_p) : "memory"); \
    } } while (0)
#define TC_ALLOC(sa, n)   asm volatile("tcgen05.alloc.cta_group::1.sync.aligned.shared::cta.b32 [%0], %1;" :: "r"(sa), "r"((uint32_t)(n)) : "memory")
#define TC_DEALLOC(t, n)  asm volatile("tcgen05.dealloc.cta_group::1.sync.aligned.b32 %0, %1;" :: "r"(t), "r"((uint32_t)(n)))
#define TC_RELINQ()       asm volatile("tcgen05.relinquish_alloc_permit.cta_group::1.sync.aligned;")
#define TC_COMMIT(a)      asm volatile("tcgen05.commit.cta_group::1.mbarrier::arrive::one.shared::cluster.b64 [%0];" :: "r"(a) : "memory")
#define TC_FENCE_AFTER()  asm volatile("tcgen05.fence::after_thread_sync;" ::: "memory")
#define TC_FENCE_BEFORE() asm volatile("tcgen05.fence::before_thread_sync;" ::: "memory")
#define TC_WAIT_LD()      asm volatile("tcgen05.wait::ld.sync.aligned;" ::: "memory")
#define FENCE_ASYNC()     asm volatile("fence.proxy.async.shared::cta;" ::: "memory")
#define CP16(dst, src)    asm volatile("cp.async.ca.shared.global [%0], [%1], 16;" :: "r"(dst), "l"(src))
#define CP_COMMIT()       asm volatile("cp.async.commit_group;" ::: "memory")
#define CP_WAIT0()        asm volatile("cp.async.wait_group 0;" ::: "memory")

__device__ __forceinline__ void mma_f16_ss(uint32_t d, uint64_t ad, uint64_t bd,
                                           uint32_t idesc, bool accum) {
    uint32_t en = accum ? 1u : 0u, z = 0u;
    asm volatile(
        "{ .reg .pred p; setp.ne.u32 p, %5, 0;\n\t"
        "tcgen05.mma.cta_group::1.kind::f16 [%0], %1, %2, %3, {%4,%4,%4,%4}, p; }"
        :: "r"(d), "l"(ad), "l"(bd), "r"(idesc), "r"(z), "r"(en) : "memory");
}
__device__ __forceinline__ void tmem_ld32(uint32_t* r, uint32_t addr) {
    asm volatile(
        "tcgen05.ld.sync.aligned.32x32b.x32.b32 "
        "{%0,%1,%2,%3,%4,%5,%6,%7,%8,%9,%10,%11,%12,%13,%14,%15,"
        "%16,%17,%18,%19,%20,%21,%22,%23,%24,%25,%26,%27,%28,%29,%30,%31}, [%32];"
        : "=r"(r[0]), "=r"(r[1]), "=r"(r[2]), "=r"(r[3]), "=r"(r[4]), "=r"(r[5]), "=r"(r[6]), "=r"(r[7]),
          "=r"(r[8]), "=r"(r[9]), "=r"(r[10]), "=r"(r[11]), "=r"(r[12]), "=r"(r[13]), "=r"(r[14]), "=r"(r[15]),
          "=r"(r[16]), "=r"(r[17]), "=r"(r[18]), "=r"(r[19]), "=r"(r[20]), "=r"(r[21]), "=r"(r[22]), "=r"(r[23]),
          "=r"(r[24]), "=r"(r[25]), "=r"(r[26]), "=r"(r[27]), "=r"(r[28]), "=r"(r[29]), "=r"(r[30]), "=r"(r[31])
        : "r"(addr));
}
#define DESC_SW128(addr) ((uint64_t(2) << 61) | (uint64_t(1) << 46) | (uint64_t(64) << 32) \
                          | (uint64_t(1) << 16) | ((uint64_t)((addr) >> 4) & 0x3FFF))

// load one 64-col bf16 row-slice into SW128 tile at the given row, half h (64B)
__device__ __forceinline__ void load_row_async(uint32_t dstBase, const __nv_bfloat16* src,
                                               int row, int half) {
    const char* s = (const char*)src + half * 64;
#pragma unroll
    for (int i = 0; i < 4; i++) {
        uint32_t byte = row * 128 + half * 64 + i * 16;
        uint32_t a = dstBase + (byte ^ ((byte >> 3) & 0x70));
        CP16(a, s + i * 16);
    }
}
#endif // HAS_TC

// -------- tcgen05 bf16x3 GEMM (templated N-tile), fused attention-coef epilogue ----
// Ah/Al [M,kp], Bh/Bl [N,kp]. Per 64-K chunk: D += Ah*Bh + Al*Bh + Ah*Bl (12 MMAs).
template <int NT>
__global__ void __launch_bounds__(256)
gemm_tc(const __nv_bfloat16* __restrict__ Ah, const __nv_bfloat16* __restrict__ Al,
        const __nv_bfloat16* __restrict__ Bh, const __nv_bfloat16* __restrict__ Bl,
        float* __restrict__ C, int M, int ldc, int kp,
        const float* __restrict__ asrc, const float* __restrict__ adst,
        float* __restrict__ als, float* __restrict__ ald, int nheads)
{
#if HAS_TC
    extern __shared__ char dsm[];
    uint32_t sb = smem_u32(dsm);
    uint32_t base = (sb + 1023) & ~1023u;
    const uint32_t TM_PTR = base;
    const uint32_t MBAR   = base + 8;
    const uint32_t T0 = base + 1024;
    constexpr uint32_t ATILE = 16384;            // 128 rows x 128B
    constexpr uint32_t BTILE = NT * 128;         // NT rows x 128B
    constexpr uint32_t OFF_AL = ATILE;
    constexpr uint32_t OFF_BH = 2 * ATILE;
    constexpr uint32_t OFF_BL = 2 * ATILE + BTILE;
    constexpr uint32_t BUFSZ  = 2 * ATILE + 2 * BTILE;

    int tid = threadIdx.x, wid = tid >> 5, lane = tid & 31;
    int m0 = blockIdx.y * 128, n0 = blockIdx.x * NT;
    int half = tid & 1, r = tid >> 1;

    if (wid == 0) { TC_ALLOC(TM_PTR, NT); TC_RELINQ(); }
    if (tid == 0) MBAR_INIT(MBAR, 1);
    __syncthreads();
    uint32_t tmem;
    asm volatile("ld.shared.b32 %0, [%1];" : "=r"(tmem) : "r"(TM_PTR));

    const int NCK = kp >> 6;

    int arow = m0 + r; if (arow >= M) arow = M - 1;
    const __nv_bfloat16* aHrow = Ah + (size_t)arow * kp;
    const __nv_bfloat16* aLrow = Al + (size_t)arow * kp;
    const __nv_bfloat16* bH0 = Bh + (size_t)(n0 + r) * kp;
    const __nv_bfloat16* bL0 = Bl + (size_t)(n0 + r) * kp;
    const __nv_bfloat16* bH1 = (NT == 256) ? Bh + (size_t)(n0 + 128 + r) * kp : bH0;
    const __nv_bfloat16* bL1 = (NT == 256) ? Bl + (size_t)(n0 + 128 + r) * kp : bL0;

    const uint32_t IDESC = 0x8000490u | ((NT / 8) << 17);

    // prologue: chunk 0 into buffer 0
    load_row_async(T0,          aHrow, r, half);
    load_row_async(T0 + OFF_AL, aLrow, r, half);
    load_row_async(T0 + OFF_BH, bH0, r, half);
    load_row_async(T0 + OFF_BL, bL0, r, half);
    if (NT == 256) {
        load_row_async(T0 + OFF_BH, bH1, r + 128, half);
        load_row_async(T0 + OFF_BL, bL1, r + 128, half);
    }
    CP_COMMIT();

    for (int c = 0; c < NCK; c++) {
        uint32_t buf = T0 + (c & 1) * BUFSZ;
        CP_WAIT0();
        __syncthreads();
        FENCE_ASYNC();
        if (wid == 0 && elect_one()) {
            uint64_t dAH = DESC_SW128(buf);
            uint64_t dAL = DESC_SW128(buf + OFF_AL);
            uint64_t dBH = DESC_SW128(buf + OFF_BH);
            uint64_t dBL = DESC_SW128(buf + OFF_BL);
#pragma unroll
            for (int k = 0; k < 4; k++) mma_f16_ss(tmem, dAH + 2 * k, dBH + 2 * k, IDESC, !(c == 0 && k == 0));
#pragma unroll
            for (int k = 0; k < 4; k++) mma_f16_ss(tmem, dAL + 2 * k, dBH + 2 * k, IDESC, true);
#pragma unroll
            for (int k = 0; k < 4; k++) mma_f16_ss(tmem, dAH + 2 * k, dBL + 2 * k, IDESC, true);
            TC_COMMIT(MBAR);
        }
        if (c + 1 < NCK) {
            uint32_t nb = T0 + ((c + 1) & 1) * BUFSZ;
            int kc = (c + 1) << 6;
            load_row_async(nb,          aHrow + kc, r, half);
            load_row_async(nb + OFF_AL, aLrow + kc, r, half);
            load_row_async(nb + OFF_BH, bH0 + kc, r, half);
            load_row_async(nb + OFF_BL, bL0 + kc, r, half);
            if (NT == 256) {
                load_row_async(nb + OFF_BH, bH1 + kc, r + 128, half);
                load_row_async(nb + OFF_BL, bL1 + kc, r + 128, half);
            }
            CP_COMMIT();
        }
        MBAR_WAIT(MBAR, c & 1);
        __syncthreads();
    }

    TC_FENCE_AFTER();
    // epilogue: warps 0-3 read 32-row subpartitions; fused attention dots per head
    if (wid < 4) {
        int row = m0 + wid * 32 + lane;
#pragma unroll
        for (int hloc = 0; hloc < NT / 128; hloc++) {
            float s = 0.f, d = 0.f;
#pragma unroll
            for (int nb = 0; nb < 4; nb++) {
                int batch = hloc * 4 + nb;
                uint32_t rg[32];
                tmem_ld32(rg, tmem + batch * 32);
                TC_WAIT_LD();
                if (row < M) {
                    float4* dst = (float4*)(C + (size_t)row * ldc + n0 + batch * 32);
#pragma unroll
                    for (int i = 0; i < 8; i++)
                        dst[i] = make_float4(__uint_as_float(rg[4 * i]), __uint_as_float(rg[4 * i + 1]),
                                             __uint_as_float(rg[4 * i + 2]), __uint_as_float(rg[4 * i + 3]));
                }
#pragma unroll
                for (int i = 0; i < 32; i++) {
                    float v = __uint_as_float(rg[i]);
                    int col = n0 + batch * 32 + i;
                    s = fmaf(v, __ldg(&asrc[col]), s);
                    d = fmaf(v, __ldg(&adst[col]), d);
                }
            }
            if (row < M) {
                int head = n0 / 128 + hloc;
                als[(size_t)row * nheads + head] = s;
                ald[(size_t)row * nheads + head] = d;
            }
        }
        TC_FENCE_BEFORE();
    }
    __syncthreads();
    if (wid == 0) TC_DEALLOC(tmem, NT);
#endif
}

// ---------------- SIMT fallback (active only when !HAS_TC) ---------------------
__global__ __launch_bounds__(256) void gemm_simt(
    const __nv_bfloat16* __restrict__ Ah, const __nv_bfloat16* __restrict__ Al,
    const __nv_bfloat16* __restrict__ Bh, const __nv_bfloat16* __restrict__ Bl,
    float* __restrict__ C, int M, int ldc, int kp)
{
#if !HAS_TC
    __shared__ float As[8][128];
    __shared__ float Bs[8][128];
    int tid = threadIdx.x;
    int tx = tid & 15, ty = tid >> 4;
    int rowBase = blockIdx.y * 128;
    int colBase = blockIdx.x * 128;
    int N = gridDim.x * 128;

    float acc[8][8];
#pragma unroll
    for (int i = 0; i < 8; i++)
#pragma unroll
        for (int j = 0; j < 8; j++) acc[i][j] = 0.f;

    for (int k0 = 0; k0 < kp; k0 += 8) {
#pragma unroll
        for (int i = 0; i < 4; i++) {
            int idx = tid + 256 * i;
            int rr = idx >> 3, cc = idx & 7;
            int gr = rowBase + rr;
            float v = 0.f;
            if (gr < M) {
                size_t o = (size_t)gr * kp + k0 + cc;
                v = __bfloat162float(Ah[o]) + __bfloat162float(Al[o]);
            }
            As[cc][rr] = v;
        }
#pragma unroll
        for (int i = 0; i < 4; i++) {
            int idx = tid + 256 * i;
            int nl = idx >> 3, kk = idx & 7;
            int gn = colBase + nl;
            float v = 0.f;
            if (gn < N) {
                size_t o = (size_t)gn * kp + k0 + kk;
                v = __bfloat162float(Bh[o]) + __bfloat162float(Bl[o]);
            }
            Bs[kk][nl] = v;
        }
        __syncthreads();
#pragma unroll
        for (int kk = 0; kk < 8; kk++) {
            float a[8], b[8];
#pragma unroll
            for (int i = 0; i < 8; i++) a[i] = As[kk][ty * 8 + i];
#pragma unroll
            for (int j = 0; j < 8; j++) b[j] = Bs[kk][tx * 8 + j];
#pragma unroll
            for (int i = 0; i < 8; i++)
#pragma unroll
                for (int j = 0; j < 8; j++) acc[i][j] = fmaf(a[i], b[j], acc[i][j]);
        }
        __syncthreads();
    }
#pragma unroll
    for (int i = 0; i < 8; i++) {
        int gr = rowBase + ty * 8 + i;
        if (gr >= M) continue;
#pragma unroll
        for (int j = 0; j < 8; j++)
            C[(size_t)gr * ldc + colBase + tx * 8 + j] = acc[i][j];
    }
#endif
}

// ---------------- conversions ------------------------------------------------
__global__ void cvt_w_kernel(const float* __restrict__ W1, const float* __restrict__ W2) {
    int idx = blockIdx.x * blockDim.x + threadIdx.x;
    const int n1 = D1 * KP1;
    if (idx < n1) {
        int n = idx / KP1, k = idx - n * KP1;
        float v = (k < IN_CH) ? W1[(size_t)k * D1 + n] : 0.f;
        __nv_bfloat16 hi = __float2bfloat16(v);
        g_b1h[idx] = hi;
        g_b1l[idx] = __float2bfloat16(v - __bfloat162float(hi));
        return;
    }
    int j = idx - n1;
    if (j < HID * D1) {
        int n = j / D1, k = j - n * D1;
        float v = W2[(size_t)k * HID + n];
        __nv_bfloat16 hi = __float2bfloat16(v);
        g_b2h[j] = hi;
        g_b2l[j] = __float2bfloat16(v - __bfloat162float(hi));
    }
}

__global__ void cvt_x_kernel(const float* __restrict__ x) {
    int idx = blockIdx.x * blockDim.x + threadIdx.x;
    if (idx >= N_NODES * KP1) return;
    int row = idx / KP1, k = idx - row * KP1;
    float v = (k < IN_CH) ? x[(size_t)row * IN_CH + k] : 0.f;
    __nv_bfloat16 hi = __float2bfloat16(v);
    g_xh[idx] = hi;
    g_xl[idx] = __float2bfloat16(v - __bfloat162float(hi));
}

// ---------------- misc helpers -----------------------------------------------
__device__ __forceinline__ float warpMax(float v) {
#pragma unroll
    for (int o = 16; o > 0; o >>= 1) v = fmaxf(v, __shfl_xor_sync(0xffffffffu, v, o));
    return v;
}
__device__ __forceinline__ float warpSum(float v) {
#pragma unroll
    for (int o = 16; o > 0; o >>= 1) v += __shfl_xor_sync(0xffffffffu, v, o);
    return v;
}
__device__ __forceinline__ float lrelu(float x) { return x > 0.f ? x : NEG_SLOPE * x; }

__global__ void zero_kernel() {
    int i = blockIdx.x * blockDim.x + threadIdx.x;
    if (i < N_NODES) g_counts[i] = 0;
    if (i < NUM_GRAPHS * HID) g_pool[i] = 0.f;
    if (i < NUM_GRAPHS) g_cnt[i] = 0;
}

__global__ void hist_kernel(const int* __restrict__ ei) {
    int e = blockIdx.x * blockDim.x + threadIdx.x;
    if (e >= E_TOT) return;
    int dst = (e < N_EDGES) ? ei[N_EDGES + e] : (e - N_EDGES);
    atomicAdd(&g_counts[dst], 1);
}

// ------- multi-block exclusive scan over g_counts (3 stages) -------------------
__global__ void scan1_kernel() {
    __shared__ int sh[256];
    int b = blockIdx.x, tid = threadIdx.x;
    int i = b * 256 + tid;
    int v = (i < N_NODES) ? g_counts[i] : 0;
    sh[tid] = v;
    __syncthreads();
#pragma unroll
    for (int o = 1; o < 256; o <<= 1) {
        int t = (tid >= o) ? sh[tid - o] : 0;
        __syncthreads();
        sh[tid] += t;
        __syncthreads();
    }
    if (i < N_NODES) g_offsets[i] = sh[tid] - v;
    if (tid == 255) g_bsum[b] = sh[255];
}

__global__ void scan2_kernel() {
    __shared__ int sh[SCAN_NB];
    int tid = threadIdx.x;
    int v = (tid < SCAN_NB) ? g_bsum[tid] : 0;
    if (tid < SCAN_NB) sh[tid] = v;
    __syncthreads();
    for (int o = 1; o < SCAN_NB; o <<= 1) {
        int t = (tid >= o && tid < SCAN_NB) ? sh[tid - o] : 0;
        __syncthreads();
        if (tid < SCAN_NB) sh[tid] += t;
        __syncthreads();
    }
    if (tid < SCAN_NB) g_bsum[tid] = sh[tid] - v;
    if (tid == 0) g_offsets[N_NODES] = E_TOT;
}

__global__ void scan3_kernel() {
    int b = blockIdx.x, tid = threadIdx.x;
    int i = b * 256 + tid;
    if (i >= N_NODES) return;
    int off = g_offsets[i] + g_bsum[b];
    g_offsets[i] = off;
    g_cursor[i] = off;
}

__global__ void scatter_kernel(const int* __restrict__ ei) {
    int e = blockIdx.x * blockDim.x + threadIdx.x;
    if (e >= E_TOT) return;
    int src, dst;
    if (e < N_EDGES) { src = ei[e]; dst = ei[N_EDGES + e]; }
    else             { src = e - N_EDGES; dst = src; }
    int pos = atomicAdd(&g_cursor[dst], 1);
    g_src_sorted[pos] = src;
}

// ---------------- attention coefficients (fallback only; TC path fuses into GEMM) --
__global__ void att_coef1(const float* __restrict__ a_src, const float* __restrict__ a_dst) {
#if !HAS_TC
    int gw = (blockIdx.x * blockDim.x + threadIdx.x) >> 5;
    int lane = threadIdx.x & 31;
    if (gw >= N_NODES) return;
    const float* row = g_h1 + (size_t)gw * D1;
    float s[4] = {0, 0, 0, 0}, d[4] = {0, 0, 0, 0};
#pragma unroll
    for (int j = 0; j < 16; j++) {
        int c = lane + 32 * j;
        float v = row[c];
        s[j >> 2] = fmaf(v, a_src[c], s[j >> 2]);
        d[j >> 2] = fmaf(v, a_dst[c], d[j >> 2]);
    }
#pragma unroll
    for (int h = 0; h < 4; h++) { s[h] = warpSum(s[h]); d[h] = warpSum(d[h]); }
    if (lane == 0) {
#pragma unroll
        for (int h = 0; h < 4; h++) {
            g_als1[gw * 4 + h] = s[h];
            g_ald1[gw * 4 + h] = d[h];
        }
    }
#endif
}

__global__ void att_coef2(const float* __restrict__ a_src, const float* __restrict__ a_dst) {
#if !HAS_TC
    int gw = (blockIdx.x * blockDim.x + threadIdx.x) >> 5;
    int lane = threadIdx.x & 31;
    if (gw >= N_NODES) return;
    const float* row = g_h2 + (size_t)gw * HID;
    float s = 0.f, d = 0.f;
#pragma unroll
    for (int j = 0; j < 4; j++) {
        int c = lane + 32 * j;
        float v = row[c];
        s = fmaf(v, a_src[c], s);
        d = fmaf(v, a_dst[c], d);
    }
    s = warpSum(s); d = warpSum(d);
    if (lane == 0) { g_als2[gw] = s; g_ald2[gw] = d; }
#endif
}

// ---------------- GAT layer 1 softmax + aggregate (warp per dst node) ------------
__global__ __launch_bounds__(256) void gat_agg1(const float* __restrict__ b1) {
    int gw = (blockIdx.x * blockDim.x + threadIdx.x) >> 5;
    int lane = threadIdx.x & 31;
    if (gw >= N_NODES) return;
    int beg = g_offsets[gw], end = g_offsets[gw + 1];

    float ald[4];
#pragma unroll
    for (int h = 0; h < 4; h++) ald[h] = g_ald1[gw * 4 + h];

    float mx[4] = {-1e30f, -1e30f, -1e30f, -1e30f};
    for (int i = beg + lane; i < end; i += 32) {
        int s = g_src_sorted[i];
#pragma unroll
        for (int h = 0; h < 4; h++) {
            float e = lrelu(g_als1[s * 4 + h] + ald[h]);
            mx[h] = fmaxf(mx[h], e);
        }
    }
#pragma unroll
    for (int h = 0; h < 4; h++) mx[h] = warpMax(mx[h]);

    float sm[4] = {0, 0, 0, 0};
    for (int i = beg + lane; i < end; i += 32) {
        int s = g_src_sorted[i];
        float4 ex4;
        float* exv = (float*)&ex4;
#pragma unroll
        for (int h = 0; h < 4; h++) {
            float e = lrelu(g_als1[s * 4 + h] + ald[h]);
            float ex = __expf(e - mx[h]);
            exv[h] = ex;
            sm[h] += ex;
        }
        ((float4*)g_alpha1)[i] = ex4;
    }
#pragma unroll
    for (int h = 0; h < 4; h++) sm[h] = warpSum(sm[h]);
    float inv[4];
#pragma unroll
    for (int h = 0; h < 4; h++) inv[h] = 1.f / sm[h];
    __syncwarp();

    float acc[16];
#pragma unroll
    for (int j = 0; j < 16; j++) acc[j] = 0.f;
    int i = beg;
    for (; i + 3 < end; i += 4) {
        int s0 = g_src_sorted[i],     s1 = g_src_sorted[i + 1];
        int s2 = g_src_sorted[i + 2], s3 = g_src_sorted[i + 3];
        float4 a0 = ((const float4*)g_alpha1)[i];
        float4 a1 = ((const float4*)g_alpha1)[i + 1];
        float4 a2 = ((const float4*)g_alpha1)[i + 2];
        float4 a3 = ((const float4*)g_alpha1)[i + 3];
        const float* h0 = g_h1 + (size_t)s0 * D1;
        const float* h1p = g_h1 + (size_t)s1 * D1;
        const float* h2p = g_h1 + (size_t)s2 * D1;
        const float* h3p = g_h1 + (size_t)s3 * D1;
#pragma unroll
        for (int j = 0; j < 16; j++) {
            int c = lane + 32 * j;
            float aa0 = (j < 4) ? a0.x : (j < 8) ? a0.y : (j < 12) ? a0.z : a0.w;
            float aa1 = (j < 4) ? a1.x : (j < 8) ? a1.y : (j < 12) ? a1.z : a1.w;
            float aa2 = (j < 4) ? a2.x : (j < 8) ? a2.y : (j < 12) ? a2.z : a2.w;
            float aa3 = (j < 4) ? a3.x : (j < 8) ? a3.y : (j < 12) ? a3.z : a3.w;
            acc[j] = fmaf(aa0, h0[c], acc[j]);
            acc[j] = fmaf(aa1, h1p[c], acc[j]);
            acc[j] = fmaf(aa2, h2p[c], acc[j]);
            acc[j] = fmaf(aa3, h3p[c], acc[j]);
        }
    }
    for (; i < end; i++) {
        int s0 = g_src_sorted[i];
        float4 a0 = ((const float4*)g_alpha1)[i];
        const float* h0 = g_h1 + (size_t)s0 * D1;
#pragma unroll
        for (int j = 0; j < 16; j++) {
            float aa0 = (j < 4) ? a0.x : (j < 8) ? a0.y : (j < 12) ? a0.z : a0.w;
            acc[j] = fmaf(aa0, h0[lane + 32 * j], acc[j]);
        }
    }
#pragma unroll
    for (int j = 0; j < 16; j++) {
        int c = lane + 32 * j;
        float v = fmaxf(acc[j] * inv[j >> 2] + b1[c], 0.f);
        __nv_bfloat16 hi = __float2bfloat16(v);
        g_o1h[(size_t)gw * D1 + c] = hi;
        g_o1l[(size_t)gw * D1 + c] = __float2bfloat16(v - __bfloat162float(hi));
    }
}

// ---------------- GAT layer 2 ----------------------------------------------------
__global__ __launch_bounds__(256) void gat_agg2(const float* __restrict__ b2) {
    int gw = (blockIdx.x * blockDim.x + threadIdx.x) >> 5;
    int lane = threadIdx.x & 31;
    if (gw >= N_NODES) return;
    int beg = g_offsets[gw], end = g_offsets[gw + 1];
    float ald = g_ald2[gw];

    float mx = -1e30f;
    for (int i = beg + lane; i < end; i += 32)
        mx = fmaxf(mx, lrelu(g_als2[g_src_sorted[i]] + ald));
    mx = warpMax(mx);

    float sm = 0.f;
    for (int i = beg + lane; i < end; i += 32) {
        float e = lrelu(g_als2[g_src_sorted[i]] + ald);
        float ex = __expf(e - mx);
        g_alpha2[i] = ex;
        sm += ex;
    }
    sm = warpSum(sm);
    float inv = 1.f / sm;
    __syncwarp();

    float acc[4] = {0, 0, 0, 0};
    int i = beg;
    for (; i + 3 < end; i += 4) {
        int s0 = g_src_sorted[i],     s1 = g_src_sorted[i + 1];
        int s2 = g_src_sorted[i + 2], s3 = g_src_sorted[i + 3];
        float a0 = g_alpha2[i],     a1 = g_alpha2[i + 1];
        float a2 = g_alpha2[i + 2], a3 = g_alpha2[i + 3];
        const float* h0 = g_h2 + (size_t)s0 * HID;
        const float* h1p = g_h2 + (size_t)s1 * HID;
        const float* h2p = g_h2 + (size_t)s2 * HID;
        const float* h3p = g_h2 + (size_t)s3 * HID;
#pragma unroll
        for (int j = 0; j < 4; j++) {
            int c = lane + 32 * j;
            acc[j] = fmaf(a0, h0[c], acc[j]);
            acc[j] = fmaf(a1, h1p[c], acc[j]);
            acc[j] = fmaf(a2, h2p[c], acc[j]);
            acc[j] = fmaf(a3, h3p[c], acc[j]);
        }
    }
    for (; i < end; i++) {
        int s0 = g_src_sorted[i];
        float a0 = g_alpha2[i];
        const float* h0 = g_h2 + (size_t)s0 * HID;
#pragma unroll
        for (int j = 0; j < 4; j++)
            acc[j] = fmaf(a0, h0[lane + 32 * j], acc[j]);
    }
#pragma unroll
    for (int j = 0; j < 4; j++) {
        int c = lane + 32 * j;
        float v = acc[j] * inv + b2[c];
        g_out2[(size_t)gw * HID + c] = fmaxf(v, 0.f);
    }
}

// ---------------- global mean pool -----------------------------------------------
__global__ void pool_kernel(const int* __restrict__ batch) {
    int gw = (blockIdx.x * blockDim.x + threadIdx.x) >> 5;
    int lane = threadIdx.x & 31;
    if (gw >= N_NODES) return;
    int g = batch[gw];
#pragma unroll
    for (int j = 0; j < 4; j++) {
        int c = lane + 32 * j;
        atomicAdd(&g_pool[g * HID + c], g_out2[(size_t)gw * HID + c]);
    }
    if (lane == 0) atomicAdd(&g_cnt[g], 1);
}

// ---------------- MLP head ---------------------------------------------------------
__global__ __launch_bounds__(1024) void mlp_kernel(
    const float* __restrict__ fc1_w, const float* __restrict__ fc1_b,
    const float* __restrict__ fc2_w, const float* __restrict__ fc2_b,
    float* __restrict__ out)
{
    __shared__ float pooled[NUM_GRAPHS * HID];
    __shared__ float z[NUM_GRAPHS * 64];
    int tid = threadIdx.x;
    for (int i = tid; i < NUM_GRAPHS * HID; i += blockDim.x) {
        int g = i / HID;
        float c = fmaxf((float)g_cnt[g], 1.f);
        pooled[i] = g_pool[i] / c;
    }
    __syncthreads();
    for (int i = tid; i < NUM_GRAPHS * 64; i += blockDim.x) {
        int g = i >> 6, j = i & 63;
        float acc = fc1_b[j];
        for (int k = 0; k < HID; k++)
            acc = fmaf(pooled[g * HID + k], fc1_w[k * 64 + j], acc);
        z[i] = fmaxf(acc, 0.f);
    }
    __syncthreads();
    for (int i = tid; i < NUM_GRAPHS * NUM_CLASSES; i += blockDim.x) {
        int g = i / NUM_CLASSES, c = i % NUM_CLASSES;
        float acc = fc2_b[c];
        for (int j = 0; j < 64; j++)
            acc = fmaf(z[g * 64 + j], fc2_w[j * NUM_CLASSES + c], acc);
        out[i] = acc;
    }
}

// ---------------- launch -------------------------------------------------------------
extern "C" void kernel_launch(void* const* d_in, const int* in_sizes, int n_in,
                              void* d_out, int out_size) {
    const float* x       = (const float*)d_in[0];
    const int*   ei      = (const int*)  d_in[1];
    const int*   batch   = (const int*)  d_in[2];
    const float* W1      = (const float*)d_in[3];
    const float* a_src1  = (const float*)d_in[4];
    const float* a_dst1  = (const float*)d_in[5];
    const float* b1      = (const float*)d_in[6];
    const float* W2      = (const float*)d_in[7];
    const float* a_src2  = (const float*)d_in[8];
    const float* a_dst2  = (const float*)d_in[9];
    const float* b2      = (const float*)d_in[10];
    const float* fc1_w   = (const float*)d_in[11];
    const float* fc1_b   = (const float*)d_in[12];
    const float* fc2_w   = (const float*)d_in[13];
    const float* fc2_b   = (const float*)d_in[14];
    float* out = (float*)d_out;

    static float *p_h1, *p_h2, *p_als1, *p_ald1, *p_als2, *p_ald2;
    static __nv_bfloat16 *p_xh, *p_xl, *p_o1h, *p_o1l, *p_b1h, *p_b1l, *p_b2h, *p_b2l;
    static bool inited = false;
    if (!inited) {
        cudaGetSymbolAddress((void**)&p_h1,   g_h1);
        cudaGetSymbolAddress((void**)&p_h2,   g_h2);
        cudaGetSymbolAddress((void**)&p_als1, g_als1);
        cudaGetSymbolAddress((void**)&p_ald1, g_ald1);
        cudaGetSymbolAddress((void**)&p_als2, g_als2);
        cudaGetSymbolAddress((void**)&p_ald2, g_ald2);
        cudaGetSymbolAddress((void**)&p_xh,  g_xh);
        cudaGetSymbolAddress((void**)&p_xl,  g_xl);
        cudaGetSymbolAddress((void**)&p_o1h, g_o1h);
        cudaGetSymbolAddress((void**)&p_o1l, g_o1l);
        cudaGetSymbolAddress((void**)&p_b1h, g_b1h);
        cudaGetSymbolAddress((void**)&p_b1l, g_b1l);
        cudaGetSymbolAddress((void**)&p_b2h, g_b2h);
        cudaGetSymbolAddress((void**)&p_b2l, g_b2l);
        cudaFuncSetAttribute(gemm_tc<256>, cudaFuncAttributeMaxDynamicSharedMemorySize, 199680);
        cudaFuncSetAttribute(gemm_tc<128>, cudaFuncAttributeMaxDynamicSharedMemorySize, 133632);
        inited = true;
    }

    // index 0..2: conversions (GEMM1 deps only)
    cvt_w_kernel<<<(D1 * KP1 + HID * D1 + 255) / 256, 256>>>(W1, W2);
    cvt_x_kernel<<<(N_NODES * KP1 + 255) / 256, 256>>>(x);
    zero_kernel<<<(N_NODES + 255) / 256, 256>>>();

    // index 3: GEMM1 (profiled by ncu -s5-c1): h1 = x @ W1 + fused attention coefs
    {
        dim3 grid(D1 / 256, (N_NODES + 127) / 128);
        gemm_tc<256><<<grid, 256, 199680>>>(p_xh, p_xl, p_b1h, p_b1l, p_h1, N_NODES, D1, KP1,
                                            a_src1, a_dst1, p_als1, p_ald1, HEADS1);
    }
    {
        dim3 grid(D1 / 128, (N_NODES + 127) / 128);
        gemm_simt<<<grid, 256>>>(p_xh, p_xl, p_b1h, p_b1l, p_h1, N_NODES, D1, KP1);
        att_coef1<<<(N_NODES * 32 + 255) / 256, 256>>>(a_src1, a_dst1);  // no-op on TC path
    }

    // CSR build (needed before gat_agg1)
    hist_kernel<<<(E_TOT + 255) / 256, 256>>>(ei);
    scan1_kernel<<<SCAN_NB, 256>>>();
    scan2_kernel<<<1, 256>>>();
    scan3_kernel<<<SCAN_NB, 256>>>();
    scatter_kernel<<<(E_TOT + 255) / 256, 256>>>(ei);

    gat_agg1<<<(N_NODES * 32 + 255) / 256, 256>>>(b1);

    // GEMM2: h2 = out1 @ W2  [50000x512]@[512x128] + fused attention coefs
    {
        dim3 grid(HID / 128, (N_NODES + 127) / 128);
        gemm_tc<128><<<grid, 256, 133632>>>(p_o1h, p_o1l, p_b2h, p_b2l, p_h2, N_NODES, HID, D1,
                                            a_src2, a_dst2, p_als2, p_ald2, 1);
        gemm_simt<<<grid, 256>>>(p_o1h, p_o1l, p_b2h, p_b2l, p_h2, N_NODES, HID, D1);
        att_coef2<<<(N_NODES * 32 + 255) / 256, 256>>>(a_src2, a_dst2);  // no-op on TC path
    }
    gat_agg2<<<(N_NODES * 32 + 255) / 256, 256>>>(b2);

    pool_kernel<<<(N_NODES * 32 + 255) / 256, 256>>>(batch);
    mlp_kernel<<<1, 1024>>>(fc1_w, fc1_b, fc2_w, fc2_b, out);
}

// round 9
// speedup vs baseline: 2.0450x; 1.1071x over previous
#include <cuda_runtime.h>
#include <cuda_bf16.h>
#include <cstdint>
#include <math.h>

#define N_NODES 50000
#define ROWS_PAD 50048       /* 391*128 */
#define RB_CNT  391
#define N_EDGES 400000
#define E_TOT   450000
#define IN_CH   814
#define KP1     832          /* 13*64 */
#define NCK1    13
#define HID     128
#define HEADS1  4
#define D1      (HEADS1*HID) /* 512 */
#define NCK2    8
#define NUM_CLASSES 46
#define NUM_GRAPHS  64
#define NEG_SLOPE   0.2f
#define SCAN_NB  196

#if defined(__CUDA_ARCH_FEAT_SM103_ALL) || defined(__CUDA_ARCH_FEAT_SM100_ALL)
#define HAS_TC 1
#else
#define HAS_TC 0
#endif

// ---------------- scratch (tiled operands: 16KB SW128 tiles, chunk-contiguous) ----
__device__ float g_h1[N_NODES * D1];
__device__ float g_h2[N_NODES * HID];
__device__ float g_out2[N_NODES * HID];
__device__ __nv_bfloat16 g_xh[ROWS_PAD * KP1];     // A1 tiles [rb][chunk][16KB]
__device__ __nv_bfloat16 g_xl[ROWS_PAD * KP1];
__device__ __nv_bfloat16 g_o1h[ROWS_PAD * D1];     // A2 tiles
__device__ __nv_bfloat16 g_o1l[ROWS_PAD * D1];
__device__ __nv_bfloat16 g_b1h[D1 * KP1];          // B1 tiles [nb][chunk][16KB]
__device__ __nv_bfloat16 g_b1l[D1 * KP1];
__device__ __nv_bfloat16 g_b2h[HID * D1];          // B2 tiles
__device__ __nv_bfloat16 g_b2l[HID * D1];
__device__ float g_als1[N_NODES * HEADS1];
__device__ float g_ald1[N_NODES * HEADS1];
__device__ float g_als2[N_NODES];
__device__ float g_ald2[N_NODES];
__device__ int   g_counts[N_NODES];
__device__ int   g_offsets[N_NODES + 1];
__device__ int   g_cursor[N_NODES];
__device__ int   g_bsum[SCAN_NB];
__device__ int   g_src_sorted[E_TOT];
__device__ float g_alpha1[E_TOT * HEADS1];
__device__ float g_alpha2[E_TOT];
__device__ float g_pool[NUM_GRAPHS * HID];
__device__ int   g_cnt[NUM_GRAPHS];

// tiled byte-offset: tile = (row>>7)*nck + (k>>6); within: SW128 of (row&127)*128+(k&63)*2
__device__ __forceinline__ size_t tidx(int row, int k, int nck) {
    uint32_t byte = ((uint32_t)(row & 127)) * 128u + (uint32_t)(k & 63) * 2u;
    byte ^= (byte >> 3) & 0x70u;
    return ((size_t)((row >> 7) * nck + (k >> 6)) << 14) + byte;
}

// ---------------- PTX helpers ----------------------------------------------------
#if HAS_TC
__device__ __forceinline__ uint32_t smem_u32(const void* p) {
    uint32_t a;
    asm("{ .reg .u64 t; cvta.to.shared.u64 t, %1; cvt.u32.u64 %0, t; }" : "=r"(a) : "l"(p));
    return a;
}
__device__ __forceinline__ uint32_t elect_one() {
    uint32_t pred;
    asm volatile("{ .reg .pred p; elect.sync _|p, 0xFFFFFFFF; selp.b32 %0, 1, 0, p; }" : "=r"(pred));
    return pred;
}
#define MBAR_INIT(a, n)  asm volatile("mbarrier.init.shared.b64 [%0], %1;" :: "r"(a), "r"((uint32_t)(n)) : "memory")
#define MBAR_EXPECT(a, b) asm volatile("mbarrier.arrive.expect_tx.shared.b64 _, [%0], %1;" :: "r"(a), "r"((uint32_t)(b)) : "memory")
#define MBAR_WAIT(a, ph) do { \
    uint32_t _m = (a), _p = (ph), _d; \
    asm volatile("{ .reg .pred p; mbarrier.try_wait.parity.acquire.cta.shared::cta.b64 p, [%1], %2; selp.b32 %0,1,0,p; }" \
        : "=r"(_d) : "r"(_m), "r"(_p) : "memory"); \
    if (!_d) { \
        asm volatile("{ .reg .pred P1;\nWL_%=:\nmbarrier.try_wait.parity.acquire.cta.shared::cta.b64 P1, [%0], %1, 0x989680;\n@P1 bra.uni WD_%=;\nbra.uni WL_%=;\nWD_%=:\n}" \
            :: "r"(_m), "r"(_p) : "memory"); \
    } } while (0)
#define TC_ALLOC(sa, n)   asm volatile("tcgen05.alloc.cta_group::1.sync.aligned.shared::cta.b32 [%0], %1;" :: "r"(sa), "r"((uint32_t)(n)) : "memory")
#define TC_DEALLOC(t, n)  asm volatile("tcgen05.dealloc.cta_group::1.sync.aligned.b32 %0, %1;" :: "r"(t), "r"((uint32_t)(n)))
#define TC_RELINQ()       asm volatile("tcgen05.relinquish_alloc_permit.cta_group::1.sync.aligned;")
#define TC_COMMIT(a)      asm volatile("tcgen05.commit.cta_group::1.mbarrier::arrive::one.shared::cluster.b64 [%0];" :: "r"(a) : "memory")
#define TC_FENCE_AFTER()  asm volatile("tcgen05.fence::after_thread_sync;" ::: "memory")
#define TC_FENCE_BEFORE() asm volatile("tcgen05.fence::before_thread_sync;" ::: "memory")
#define TC_WAIT_LD()      asm volatile("tcgen05.wait::ld.sync.aligned;" ::: "memory")
#define BULK_CP(dst, src, sz, mbar) \
    asm volatile("cp.async.bulk.shared::cta.global.mbarrier::complete_tx::bytes [%0], [%1], %2, [%3];" \
                 :: "r"(dst), "l"(src), "r"((uint32_t)(sz)), "r"(mbar) : "memory")

__device__ __forceinline__ void mma_f16_ss(uint32_t d, uint64_t ad, uint64_t bd,
                                           uint32_t idesc, bool accum) {
    uint32_t en = accum ? 1u : 0u, z = 0u;
    asm volatile(
        "{ .reg .pred p; setp.ne.u32 p, %5, 0;\n\t"
        "tcgen05.mma.cta_group::1.kind::f16 [%0], %1, %2, %3, {%4,%4,%4,%4}, p; }"
        :: "r"(d), "l"(ad), "l"(bd), "r"(idesc), "r"(z), "r"(en) : "memory");
}
__device__ __forceinline__ void tmem_ld32(uint32_t* r, uint32_t addr) {
    asm volatile(
        "tcgen05.ld.sync.aligned.32x32b.x32.b32 "
        "{%0,%1,%2,%3,%4,%5,%6,%7,%8,%9,%10,%11,%12,%13,%14,%15,"
        "%16,%17,%18,%19,%20,%21,%22,%23,%24,%25,%26,%27,%28,%29,%30,%31}, [%32];"
        : "=r"(r[0]), "=r"(r[1]), "=r"(r[2]), "=r"(r[3]), "=r"(r[4]), "=r"(r[5]), "=r"(r[6]), "=r"(r[7]),
          "=r"(r[8]), "=r"(r[9]), "=r"(r[10]), "=r"(r[11]), "=r"(r[12]), "=r"(r[13]), "=r"(r[14]), "=r"(r[15]),
          "=r"(r[16]), "=r"(r[17]), "=r"(r[18]), "=r"(r[19]), "=r"(r[20]), "=r"(r[21]), "=r"(r[22]), "=r"(r[23]),
          "=r"(r[24]), "=r"(r[25]), "=r"(r[26]), "=r"(r[27]), "=r"(r[28]), "=r"(r[29]), "=r"(r[30]), "=r"(r[31])
        : "r"(addr));
}
#define DESC_SW128(addr) ((uint64_t(2) << 61) | (uint64_t(1) << 46) | (uint64_t(64) << 32) \
                          | (uint64_t(1) << 16) | ((uint64_t)((addr) >> 4) & 0x3FFF))
#endif // HAS_TC

// -------- tcgen05 bf16x3 GEMM, TMA-bulk tile loads, fused attention epilogue -------
// Tiled operands; per 64-K chunk: D += Ah*Bh + Al*Bh + Ah*Bl (12 MMAs, one commit).
template <int NT>
__global__ void __launch_bounds__(256)
gemm_tc(const __nv_bfloat16* __restrict__ Ah, const __nv_bfloat16* __restrict__ Al,
        const __nv_bfloat16* __restrict__ Bh, const __nv_bfloat16* __restrict__ Bl,
        float* __restrict__ C, int M, int ldc, int kp,
        const float* __restrict__ asrc, const float* __restrict__ adst,
        float* __restrict__ als, float* __restrict__ ald, int nheads)
{
#if HAS_TC
    extern __shared__ char dsm[];
    uint32_t sb = smem_u32(dsm);
    uint32_t base = (sb + 1023) & ~1023u;
    const uint32_t TM_PTR = base;
    const uint32_t MMABAR = base + 8;
    const uint32_t LBAR0  = base + 16;
    const uint32_t LBAR1  = base + 24;
    const uint32_t T0 = base + 1024;
    constexpr uint32_t ATILE = 16384;
    constexpr uint32_t BTILE = NT * 128;
    constexpr uint32_t OFF_AL = ATILE;
    constexpr uint32_t OFF_BH = 2 * ATILE;
    constexpr uint32_t OFF_BL = 2 * ATILE + BTILE;
    constexpr uint32_t BUFSZ  = 2 * ATILE + 2 * BTILE;
    constexpr uint32_t LOADB  = BUFSZ;

    int tid = threadIdx.x, wid = tid >> 5, lane = tid & 31;
    int rb = blockIdx.y;
    int m0 = rb * 128, n0 = blockIdx.x * NT;
    int nb0 = n0 >> 7;
    const int nck = kp >> 6;

    if (wid == 0) { TC_ALLOC(TM_PTR, NT); TC_RELINQ(); }
    if (tid == 0) {
        MBAR_INIT(MMABAR, 1);
        MBAR_INIT(LBAR0, 1);
        MBAR_INIT(LBAR1, 1);
    }
    __syncthreads();
    uint32_t tmem;
    asm volatile("ld.shared.b32 %0, [%1];" : "=r"(tmem) : "r"(TM_PTR));

    const char* cAh = (const char*)Ah;
    const char* cAl = (const char*)Al;
    const char* cBh = (const char*)Bh;
    const char* cBl = (const char*)Bl;

    const uint32_t IDESC = 0x8000490u | ((NT / 8) << 17);

    // issue loads for chunk c into buffer buf (single thread)
    auto issue = [&](int c, uint32_t buf, uint32_t lbar) {
        MBAR_EXPECT(lbar, LOADB);
        size_t aoff = ((size_t)(rb * nck + c)) << 14;
        BULK_CP(buf,          cAh + aoff, 16384, lbar);
        BULK_CP(buf + OFF_AL, cAl + aoff, 16384, lbar);
        size_t b0off = ((size_t)(nb0 * nck + c)) << 14;
        BULK_CP(buf + OFF_BH, cBh + b0off, 16384, lbar);
        BULK_CP(buf + OFF_BL, cBl + b0off, 16384, lbar);
        if (NT == 256) {
            size_t b1off = ((size_t)((nb0 + 1) * nck + c)) << 14;
            BULK_CP(buf + OFF_BH + 16384, cBh + b1off, 16384, lbar);
            BULK_CP(buf + OFF_BL + 16384, cBl + b1off, 16384, lbar);
        }
    };

    if (tid == 0) issue(0, T0, LBAR0);

    for (int c = 0; c < nck; c++) {
        uint32_t buf = T0 + (c & 1) * BUFSZ;
        MBAR_WAIT((c & 1) ? LBAR1 : LBAR0, (c >> 1) & 1);
        if (wid == 0 && elect_one()) {
            uint64_t dAH = DESC_SW128(buf);
            uint64_t dAL = DESC_SW128(buf + OFF_AL);
            uint64_t dBH = DESC_SW128(buf + OFF_BH);
            uint64_t dBL = DESC_SW128(buf + OFF_BL);
#pragma unroll
            for (int k = 0; k < 4; k++) mma_f16_ss(tmem, dAH + 2 * k, dBH + 2 * k, IDESC, !(c == 0 && k == 0));
#pragma unroll
            for (int k = 0; k < 4; k++) mma_f16_ss(tmem, dAL + 2 * k, dBH + 2 * k, IDESC, true);
#pragma unroll
            for (int k = 0; k < 4; k++) mma_f16_ss(tmem, dAH + 2 * k, dBL + 2 * k, IDESC, true);
            TC_COMMIT(MMABAR);
        }
        if (tid == 0 && c + 1 < nck)
            issue(c + 1, T0 + ((c + 1) & 1) * BUFSZ, ((c + 1) & 1) ? LBAR1 : LBAR0);
        MBAR_WAIT(MMABAR, c & 1);
    }

    TC_FENCE_AFTER();
    // epilogue: warps 0-3 read 32-row subpartitions; fused attention dots per head
    if (wid < 4) {
        int row = m0 + wid * 32 + lane;
#pragma unroll
        for (int hloc = 0; hloc < NT / 128; hloc++) {
            float s = 0.f, d = 0.f;
#pragma unroll
            for (int nb = 0; nb < 4; nb++) {
                int batch = hloc * 4 + nb;
                uint32_t rg[32];
                tmem_ld32(rg, tmem + batch * 32);
                TC_WAIT_LD();
                if (row < M) {
                    float4* dst = (float4*)(C + (size_t)row * ldc + n0 + batch * 32);
#pragma unroll
                    for (int i = 0; i < 8; i++)
                        dst[i] = make_float4(__uint_as_float(rg[4 * i]), __uint_as_float(rg[4 * i + 1]),
                                             __uint_as_float(rg[4 * i + 2]), __uint_as_float(rg[4 * i + 3]));
                }
#pragma unroll
                for (int i = 0; i < 32; i++) {
                    float v = __uint_as_float(rg[i]);
                    int col = n0 + batch * 32 + i;
                    s = fmaf(v, __ldg(&asrc[col]), s);
                    d = fmaf(v, __ldg(&adst[col]), d);
                }
            }
            if (row < M) {
                int head = n0 / 128 + hloc;
                als[(size_t)row * nheads + head] = s;
                ald[(size_t)row * nheads + head] = d;
            }
        }
        TC_FENCE_BEFORE();
    }
    __syncthreads();
    if (wid == 0) TC_DEALLOC(tmem, NT);
#endif
}

// ---------------- SIMT fallback (active only when !HAS_TC; reads tiled layout) -----
__global__ __launch_bounds__(256) void gemm_simt(
    const __nv_bfloat16* __restrict__ Ah, const __nv_bfloat16* __restrict__ Al,
    const __nv_bfloat16* __restrict__ Bh, const __nv_bfloat16* __restrict__ Bl,
    float* __restrict__ C, int M, int ldc, int kp)
{
#if !HAS_TC
    __shared__ float As[8][128];
    __shared__ float Bs[8][128];
    int tid = threadIdx.x;
    int tx = tid & 15, ty = tid >> 4;
    int rowBase = blockIdx.y * 128;
    int colBase = blockIdx.x * 128;
    int nck = kp >> 6;

    float acc[8][8];
#pragma unroll
    for (int i = 0; i < 8; i++)
#pragma unroll
        for (int j = 0; j < 8; j++) acc[i][j] = 0.f;

    for (int k0 = 0; k0 < kp; k0 += 8) {
#pragma unroll
        for (int i = 0; i < 4; i++) {
            int idx = tid + 256 * i;
            int rr = idx >> 3, cc = idx & 7;
            int gr = rowBase + rr;
            size_t o = tidx(gr, k0 + cc, nck);
            float v = __bfloat162float(*(const __nv_bfloat16*)((const char*)Ah + o))
                    + __bfloat162float(*(const __nv_bfloat16*)((const char*)Al + o));
            As[cc][rr] = v;
        }
#pragma unroll
        for (int i = 0; i < 4; i++) {
            int idx = tid + 256 * i;
            int nl = idx >> 3, kk = idx & 7;
            size_t o = tidx(colBase + nl, k0 + kk, nck);
            Bs[kk][nl] = __bfloat162float(*(const __nv_bfloat16*)((const char*)Bh + o))
                       + __bfloat162float(*(const __nv_bfloat16*)((const char*)Bl + o));
        }
        __syncthreads();
#pragma unroll
        for (int kk = 0; kk < 8; kk++) {
            float a[8], b[8];
#pragma unroll
            for (int i = 0; i < 8; i++) a[i] = As[kk][ty * 8 + i];
#pragma unroll
            for (int j = 0; j < 8; j++) b[j] = Bs[kk][tx * 8 + j];
#pragma unroll
            for (int i = 0; i < 8; i++)
#pragma unroll
                for (int j = 0; j < 8; j++) acc[i][j] = fmaf(a[i], b[j], acc[i][j]);
        }
        __syncthreads();
    }
#pragma unroll
    for (int i = 0; i < 8; i++) {
        int gr = rowBase + ty * 8 + i;
        if (gr >= M) continue;
#pragma unroll
        for (int j = 0; j < 8; j++)
            C[(size_t)gr * ldc + colBase + tx * 8 + j] = acc[i][j];
    }
#endif
}

// ---------------- conversions (write tiled+swizzled) ---------------------------
__global__ void cvt_w_kernel(const float* __restrict__ W1, const float* __restrict__ W2) {
    int idx = blockIdx.x * blockDim.x + threadIdx.x;
    const int n1 = D1 * KP1;
    if (idx < n1) {
        int n = idx / KP1, k = idx - n * KP1;
        float v = (k < IN_CH) ? W1[(size_t)k * D1 + n] : 0.f;
        __nv_bfloat16 hi = __float2bfloat16(v);
        size_t o = tidx(n, k, NCK1);
        *(__nv_bfloat16*)((char*)g_b1h + o) = hi;
        *(__nv_bfloat16*)((char*)g_b1l + o) = __float2bfloat16(v - __bfloat162float(hi));
        return;
    }
    int j = idx - n1;
    if (j < HID * D1) {
        int n = j / D1, k = j - n * D1;
        float v = W2[(size_t)k * HID + n];
        __nv_bfloat16 hi = __float2bfloat16(v);
        size_t o = tidx(n, k, NCK2);
        *(__nv_bfloat16*)((char*)g_b2h + o) = hi;
        *(__nv_bfloat16*)((char*)g_b2l + o) = __float2bfloat16(v - __bfloat162float(hi));
    }
}

__global__ void cvt_x_kernel(const float* __restrict__ x) {
    int idx = blockIdx.x * blockDim.x + threadIdx.x;
    if (idx >= ROWS_PAD * KP1) return;
    int row = idx / KP1, k = idx - row * KP1;
    float v = (row < N_NODES && k < IN_CH) ? x[(size_t)row * IN_CH + k] : 0.f;
    __nv_bfloat16 hi = __float2bfloat16(v);
    size_t o = tidx(row, k, NCK1);
    *(__nv_bfloat16*)((char*)g_xh + o) = hi;
    *(__nv_bfloat16*)((char*)g_xl + o) = __float2bfloat16(v - __bfloat162float(hi));
}

// ---------------- misc helpers -----------------------------------------------
__device__ __forceinline__ float warpMax(float v) {
#pragma unroll
    for (int o = 16; o > 0; o >>= 1) v = fmaxf(v, __shfl_xor_sync(0xffffffffu, v, o));
    return v;
}
__device__ __forceinline__ float warpSum(float v) {
#pragma unroll
    for (int o = 16; o > 0; o >>= 1) v += __shfl_xor_sync(0xffffffffu, v, o);
    return v;
}
__device__ __forceinline__ float lrelu(float x) { return x > 0.f ? x : NEG_SLOPE * x; }

__global__ void zero_kernel() {
    int i = blockIdx.x * blockDim.x + threadIdx.x;
    if (i < N_NODES) g_counts[i] = 0;
    if (i < NUM_GRAPHS * HID) g_pool[i] = 0.f;
    if (i < NUM_GRAPHS) g_cnt[i] = 0;
}

__global__ void hist_kernel(const int* __restrict__ ei) {
    int e = blockIdx.x * blockDim.x + threadIdx.x;
    if (e >= E_TOT) return;
    int dst = (e < N_EDGES) ? ei[N_EDGES + e] : (e - N_EDGES);
    atomicAdd(&g_counts[dst], 1);
}

__global__ void scan1_kernel() {
    __shared__ int sh[256];
    int b = blockIdx.x, tid = threadIdx.x;
    int i = b * 256 + tid;
    int v = (i < N_NODES) ? g_counts[i] : 0;
    sh[tid] = v;
    __syncthreads();
#pragma unroll
    for (int o = 1; o < 256; o <<= 1) {
        int t = (tid >= o) ? sh[tid - o] : 0;
        __syncthreads();
        sh[tid] += t;
        __syncthreads();
    }
    if (i < N_NODES) g_offsets[i] = sh[tid] - v;
    if (tid == 255) g_bsum[b] = sh[255];
}

__global__ void scan2_kernel() {
    __shared__ int sh[SCAN_NB];
    int tid = threadIdx.x;
    int v = (tid < SCAN_NB) ? g_bsum[tid] : 0;
    if (tid < SCAN_NB) sh[tid] = v;
    __syncthreads();
    for (int o = 1; o < SCAN_NB; o <<= 1) {
        int t = (tid >= o && tid < SCAN_NB) ? sh[tid - o] : 0;
        __syncthreads();
        if (tid < SCAN_NB) sh[tid] += t;
        __syncthreads();
    }
    if (tid < SCAN_NB) g_bsum[tid] = sh[tid] - v;
    if (tid == 0) g_offsets[N_NODES] = E_TOT;
}

__global__ void scan3_kernel() {
    int b = blockIdx.x, tid = threadIdx.x;
    int i = b * 256 + tid;
    if (i >= N_NODES) return;
    int off = g_offsets[i] + g_bsum[b];
    g_offsets[i] = off;
    g_cursor[i] = off;
}

__global__ void scatter_kernel(const int* __restrict__ ei) {
    int e = blockIdx.x * blockDim.x + threadIdx.x;
    if (e >= E_TOT) return;
    int src, dst;
    if (e < N_EDGES) { src = ei[e]; dst = ei[N_EDGES + e]; }
    else             { src = e - N_EDGES; dst = src; }
    int pos = atomicAdd(&g_cursor[dst], 1);
    g_src_sorted[pos] = src;
}

// ---------------- attention coefficients (fallback only) ---------------------------
__global__ void att_coef1(const float* __restrict__ a_src, const float* __restrict__ a_dst) {
#if !HAS_TC
    int gw = (blockIdx.x * blockDim.x + threadIdx.x) >> 5;
    int lane = threadIdx.x & 31;
    if (gw >= N_NODES) return;
    const float* row = g_h1 + (size_t)gw * D1;
    float s[4] = {0, 0, 0, 0}, d[4] = {0, 0, 0, 0};
#pragma unroll
    for (int j = 0; j < 16; j++) {
        int c = lane + 32 * j;
        float v = row[c];
        s[j >> 2] = fmaf(v, a_src[c], s[j >> 2]);
        d[j >> 2] = fmaf(v, a_dst[c], d[j >> 2]);
    }
#pragma unroll
    for (int h = 0; h < 4; h++) { s[h] = warpSum(s[h]); d[h] = warpSum(d[h]); }
    if (lane == 0) {
#pragma unroll
        for (int h = 0; h < 4; h++) {
            g_als1[gw * 4 + h] = s[h];
            g_ald1[gw * 4 + h] = d[h];
        }
    }
#endif
}

__global__ void att_coef2(const float* __restrict__ a_src, const float* __restrict__ a_dst) {
#if !HAS_TC
    int gw = (blockIdx.x * blockDim.x + threadIdx.x) >> 5;
    int lane = threadIdx.x & 31;
    if (gw >= N_NODES) return;
    const float* row = g_h2 + (size_t)gw * HID;
    float s = 0.f, d = 0.f;
#pragma unroll
    for (int j = 0; j < 4; j++) {
        int c = lane + 32 * j;
        float v = row[c];
        s = fmaf(v, a_src[c], s);
        d = fmaf(v, a_dst[c], d);
    }
    s = warpSum(s); d = warpSum(d);
    if (lane == 0) { g_als2[gw] = s; g_ald2[gw] = d; }
#endif
}

// ---------------- GAT layer 1 softmax + aggregate (warp per dst node) ------------
// epilogue writes bf16 hi/lo split into tiled o1 layout for GEMM2's bulk loads.
__global__ __launch_bounds__(256) void gat_agg1(const float* __restrict__ b1) {
    int gw = (blockIdx.x * blockDim.x + threadIdx.x) >> 5;
    int lane = threadIdx.x & 31;
    if (gw >= N_NODES) return;
    int beg = g_offsets[gw], end = g_offsets[gw + 1];

    float ald[4];
#pragma unroll
    for (int h = 0; h < 4; h++) ald[h] = g_ald1[gw * 4 + h];

    float mx[4] = {-1e30f, -1e30f, -1e30f, -1e30f};
    for (int i = beg + lane; i < end; i += 32) {
        int s = g_src_sorted[i];
#pragma unroll
        for (int h = 0; h < 4; h++) {
            float e = lrelu(g_als1[s * 4 + h] + ald[h]);
            mx[h] = fmaxf(mx[h], e);
        }
    }
#pragma unroll
    for (int h = 0; h < 4; h++) mx[h] = warpMax(mx[h]);

    float sm[4] = {0, 0, 0, 0};
    for (int i = beg + lane; i < end; i += 32) {
        int s = g_src_sorted[i];
        float4 ex4;
        float* exv = (float*)&ex4;
#pragma unroll
        for (int h = 0; h < 4; h++) {
            float e = lrelu(g_als1[s * 4 + h] + ald[h]);
            float ex = __expf(e - mx[h]);
            exv[h] = ex;
            sm[h] += ex;
        }
        ((float4*)g_alpha1)[i] = ex4;
    }
#pragma unroll
    for (int h = 0; h < 4; h++) sm[h] = warpSum(sm[h]);
    float inv[4];
#pragma unroll
    for (int h = 0; h < 4; h++) inv[h] = 1.f / sm[h];
    __syncwarp();

    float acc[16];
#pragma unroll
    for (int j = 0; j < 16; j++) acc[j] = 0.f;
    int i = beg;
    for (; i + 3 < end; i += 4) {
        int s0 = g_src_sorted[i],     s1 = g_src_sorted[i + 1];
        int s2 = g_src_sorted[i + 2], s3 = g_src_sorted[i + 3];
        float4 a0 = ((const float4*)g_alpha1)[i];
        float4 a1 = ((const float4*)g_alpha1)[i + 1];
        float4 a2 = ((const float4*)g_alpha1)[i + 2];
        float4 a3 = ((const float4*)g_alpha1)[i + 3];
        const float* h0 = g_h1 + (size_t)s0 * D1;
        const float* h1p = g_h1 + (size_t)s1 * D1;
        const float* h2p = g_h1 + (size_t)s2 * D1;
        const float* h3p = g_h1 + (size_t)s3 * D1;
#pragma unroll
        for (int j = 0; j < 16; j++) {
            int c = lane + 32 * j;
            float aa0 = (j < 4) ? a0.x : (j < 8) ? a0.y : (j < 12) ? a0.z : a0.w;
            float aa1 = (j < 4) ? a1.x : (j < 8) ? a1.y : (j < 12) ? a1.z : a1.w;
            float aa2 = (j < 4) ? a2.x : (j < 8) ? a2.y : (j < 12) ? a2.z : a2.w;
            float aa3 = (j < 4) ? a3.x : (j < 8) ? a3.y : (j < 12) ? a3.z : a3.w;
            acc[j] = fmaf(aa0, h0[c], acc[j]);
            acc[j] = fmaf(aa1, h1p[c], acc[j]);
            acc[j] = fmaf(aa2, h2p[c], acc[j]);
            acc[j] = fmaf(aa3, h3p[c], acc[j]);
        }
    }
    for (; i < end; i++) {
        int s0 = g_src_sorted[i];
        float4 a0 = ((const float4*)g_alpha1)[i];
        const float* h0 = g_h1 + (size_t)s0 * D1;
#pragma unroll
        for (int j = 0; j < 16; j++) {
            float aa0 = (j < 4) ? a0.x : (j < 8) ? a0.y : (j < 12) ? a0.z : a0.w;
            acc[j] = fmaf(aa0, h0[lane + 32 * j], acc[j]);
        }
    }
#pragma unroll
    for (int j = 0; j < 16; j++) {
        int c = lane + 32 * j;
        float v = fmaxf(acc[j] * inv[j >> 2] + b1[c], 0.f);
        __nv_bfloat16 hi = __float2bfloat16(v);
        size_t o = tidx(gw, c, NCK2);
        *(__nv_bfloat16*)((char*)g_o1h + o) = hi;
        *(__nv_bfloat16*)((char*)g_o1l + o) = __float2bfloat16(v - __bfloat162float(hi));
    }
}

// ---------------- GAT layer 2 ----------------------------------------------------
__global__ __launch_bounds__(256) void gat_agg2(const float* __restrict__ b2) {
    int gw = (blockIdx.x * blockDim.x + threadIdx.x) >> 5;
    int lane = threadIdx.x & 31;
    if (gw >= N_NODES) return;
    int beg = g_offsets[gw], end = g_offsets[gw + 1];
    float ald = g_ald2[gw];

    float mx = -1e30f;
    for (int i = beg + lane; i < end; i += 32)
        mx = fmaxf(mx, lrelu(g_als2[g_src_sorted[i]] + ald));
    mx = warpMax(mx);

    float sm = 0.f;
    for (int i = beg + lane; i < end; i += 32) {
        float e = lrelu(g_als2[g_src_sorted[i]] + ald);
        float ex = __expf(e - mx);
        g_alpha2[i] = ex;
        sm += ex;
    }
    sm = warpSum(sm);
    float inv = 1.f / sm;
    __syncwarp();

    float acc[4] = {0, 0, 0, 0};
    int i = beg;
    for (; i + 3 < end; i += 4) {
        int s0 = g_src_sorted[i],     s1 = g_src_sorted[i + 1];
        int s2 = g_src_sorted[i + 2], s3 = g_src_sorted[i + 3];
        float a0 = g_alpha2[i],     a1 = g_alpha2[i + 1];
        float a2 = g_alpha2[i + 2], a3 = g_alpha2[i + 3];
        const float* h0 = g_h2 + (size_t)s0 * HID;
        const float* h1p = g_h2 + (size_t)s1 * HID;
        const float* h2p = g_h2 + (size_t)s2 * HID;
        const float* h3p = g_h2 + (size_t)s3 * HID;
#pragma unroll
        for (int j = 0; j < 4; j++) {
            int c = lane + 32 * j;
            acc[j] = fmaf(a0, h0[c], acc[j]);
            acc[j] = fmaf(a1, h1p[c], acc[j]);
            acc[j] = fmaf(a2, h2p[c], acc[j]);
            acc[j] = fmaf(a3, h3p[c], acc[j]);
        }
    }
    for (; i < end; i++) {
        int s0 = g_src_sorted[i];
        float a0 = g_alpha2[i];
        const float* h0 = g_h2 + (size_t)s0 * HID;
#pragma unroll
        for (int j = 0; j < 4; j++)
            acc[j] = fmaf(a0, h0[lane + 32 * j], acc[j]);
    }
#pragma unroll
    for (int j = 0; j < 4; j++) {
        int c = lane + 32 * j;
        float v = acc[j] * inv + b2[c];
        g_out2[(size_t)gw * HID + c] = fmaxf(v, 0.f);
    }
}

// ---------------- global mean pool -----------------------------------------------
__global__ void pool_kernel(const int* __restrict__ batch) {
    int gw = (blockIdx.x * blockDim.x + threadIdx.x) >> 5;
    int lane = threadIdx.x & 31;
    if (gw >= N_NODES) return;
    int g = batch[gw];
#pragma unroll
    for (int j = 0; j < 4; j++) {
        int c = lane + 32 * j;
        atomicAdd(&g_pool[g * HID + c], g_out2[(size_t)gw * HID + c]);
    }
    if (lane == 0) atomicAdd(&g_cnt[g], 1);
}

// ---------------- MLP head ---------------------------------------------------------
__global__ __launch_bounds__(1024) void mlp_kernel(
    const float* __restrict__ fc1_w, const float* __restrict__ fc1_b,
    const float* __restrict__ fc2_w, const float* __restrict__ fc2_b,
    float* __restrict__ out)
{
    __shared__ float pooled[NUM_GRAPHS * HID];
    __shared__ float z[NUM_GRAPHS * 64];
    int tid = threadIdx.x;
    for (int i = tid; i < NUM_GRAPHS * HID; i += blockDim.x) {
        int g = i / HID;
        float c = fmaxf((float)g_cnt[g], 1.f);
        pooled[i] = g_pool[i] / c;
    }
    __syncthreads();
    for (int i = tid; i < NUM_GRAPHS * 64; i += blockDim.x) {
        int g = i >> 6, j = i & 63;
        float acc = fc1_b[j];
        for (int k = 0; k < HID; k++)
            acc = fmaf(pooled[g * HID + k], fc1_w[k * 64 + j], acc);
        z[i] = fmaxf(acc, 0.f);
    }
    __syncthreads();
    for (int i = tid; i < NUM_GRAPHS * NUM_CLASSES; i += blockDim.x) {
        int g = i / NUM_CLASSES, c = i % NUM_CLASSES;
        float acc = fc2_b[c];
        for (int j = 0; j < 64; j++)
            acc = fmaf(z[g * 64 + j], fc2_w[j * NUM_CLASSES + c], acc);
        out[i] = acc;
    }
}

// ---------------- launch -------------------------------------------------------------
extern "C" void kernel_launch(void* const* d_in, const int* in_sizes, int n_in,
                              void* d_out, int out_size) {
    const float* x       = (const float*)d_in[0];
    const int*   ei      = (const int*)  d_in[1];
    const int*   batch   = (const int*)  d_in[2];
    const float* W1      = (const float*)d_in[3];
    const float* a_src1  = (const float*)d_in[4];
    const float* a_dst1  = (const float*)d_in[5];
    const float* b1      = (const float*)d_in[6];
    const float* W2      = (const float*)d_in[7];
    const float* a_src2  = (const float*)d_in[8];
    const float* a_dst2  = (const float*)d_in[9];
    const float* b2      = (const float*)d_in[10];
    const float* fc1_w   = (const float*)d_in[11];
    const float* fc1_b   = (const float*)d_in[12];
    const float* fc2_w   = (const float*)d_in[13];
    const float* fc2_b   = (const float*)d_in[14];
    float* out = (float*)d_out;

    static float *p_h1, *p_h2, *p_als1, *p_ald1, *p_als2, *p_ald2;
    static __nv_bfloat16 *p_xh, *p_xl, *p_o1h, *p_o1l, *p_b1h, *p_b1l, *p_b2h, *p_b2l;
    static bool inited = false;
    if (!inited) {
        cudaGetSymbolAddress((void**)&p_h1,   g_h1);
        cudaGetSymbolAddress((void**)&p_h2,   g_h2);
        cudaGetSymbolAddress((void**)&p_als1, g_als1);
        cudaGetSymbolAddress((void**)&p_ald1, g_ald1);
        cudaGetSymbolAddress((void**)&p_als2, g_als2);
        cudaGetSymbolAddress((void**)&p_ald2, g_ald2);
        cudaGetSymbolAddress((void**)&p_xh,  g_xh);
        cudaGetSymbolAddress((void**)&p_xl,  g_xl);
        cudaGetSymbolAddress((void**)&p_o1h, g_o1h);
        cudaGetSymbolAddress((void**)&p_o1l, g_o1l);
        cudaGetSymbolAddress((void**)&p_b1h, g_b1h);
        cudaGetSymbolAddress((void**)&p_b1l, g_b1l);
        cudaGetSymbolAddress((void**)&p_b2h, g_b2h);
        cudaGetSymbolAddress((void**)&p_b2l, g_b2l);
        cudaFuncSetAttribute(gemm_tc<256>, cudaFuncAttributeMaxDynamicSharedMemorySize, 199680);
        cudaFuncSetAttribute(gemm_tc<128>, cudaFuncAttributeMaxDynamicSharedMemorySize, 133632);
        inited = true;
    }

    // index 0..2: conversions (GEMM1 deps only)
    cvt_w_kernel<<<(D1 * KP1 + HID * D1 + 255) / 256, 256>>>(W1, W2);
    cvt_x_kernel<<<(ROWS_PAD * KP1 + 255) / 256, 256>>>(x);
    zero_kernel<<<(N_NODES + 255) / 256, 256>>>();

    // index 3: GEMM1 (profiled): h1 = x @ W1 + fused attention coefs
    {
        dim3 grid(D1 / 256, RB_CNT);
        gemm_tc<256><<<grid, 256, 199680>>>(p_xh, p_xl, p_b1h, p_b1l, p_h1, N_NODES, D1, KP1,
                                            a_src1, a_dst1, p_als1, p_ald1, HEADS1);
    }
    {
        dim3 grid(D1 / 128, RB_CNT);
        gemm_simt<<<grid, 256>>>(p_xh, p_xl, p_b1h, p_b1l, p_h1, N_NODES, D1, KP1);
        att_coef1<<<(N_NODES * 32 + 255) / 256, 256>>>(a_src1, a_dst1);  // no-op on TC path
    }

    // CSR build (needed before gat_agg1)
    hist_kernel<<<(E_TOT + 255) / 256, 256>>>(ei);
    scan1_kernel<<<SCAN_NB, 256>>>();
    scan2_kernel<<<1, 256>>>();
    scan3_kernel<<<SCAN_NB, 256>>>();
    scatter_kernel<<<(E_TOT + 255) / 256, 256>>>(ei);

    gat_agg1<<<(N_NODES * 32 + 255) / 256, 256>>>(b1);

    // GEMM2: h2 = out1 @ W2 + fused attention coefs
    {
        dim3 grid(HID / 128, RB_CNT);
        gemm_tc<128><<<grid, 256, 133632>>>(p_o1h, p_o1l, p_b2h, p_b2l, p_h2, N_NODES, HID, D1,
                                            a_src2, a_dst2, p_als2, p_ald2, 1);
        gemm_simt<<<grid, 256>>>(p_o1h, p_o1l, p_b2h, p_b2l, p_h2, N_NODES, HID, D1);
        att_coef2<<<(N_NODES * 32 + 255) / 256, 256>>>(a_src2, a_dst2);  // no-op on TC path
    }
    gat_agg2<<<(N_NODES * 32 + 255) / 256, 256>>>(b2);

    pool_kernel<<<(N_NODES * 32 + 255) / 256, 256>>>(batch);
    mlp_kernel<<<1, 1024>>>(fc1_w, fc1_b, fc2_w, fc2_b, out);
}

// round 10
// speedup vs baseline: 2.1433x; 1.0480x over previous
#include <cuda_runtime.h>
#include <cuda_bf16.h>
#include <cstdint>
#include <math.h>

#define N_NODES 50000
#define ROWS_PAD 50048       /* 391*128 */
#define RB_CNT  391
#define N_EDGES 400000
#define E_TOT   450000
#define IN_CH   814
#define KP1     832          /* 13*64 */
#define NCK1    13
#define HID     128
#define HEADS1  4
#define D1      (HEADS1*HID) /* 512 */
#define NCK2    8
#define NUM_CLASSES 46
#define NUM_GRAPHS  64
#define NEG_SLOPE   0.2f
#define SCAN_NB  196

#if defined(__CUDA_ARCH_FEAT_SM103_ALL) || defined(__CUDA_ARCH_FEAT_SM100_ALL)
#define HAS_TC 1
#else
#define HAS_TC 0
#endif

// ---------------- scratch (tiled operands: 16KB SW128 tiles, chunk-contiguous) ----
__device__ float g_h1[N_NODES * D1];
__device__ float g_h2[N_NODES * HID];
__device__ float g_out2[N_NODES * HID];
__device__ __nv_bfloat16 g_xh[ROWS_PAD * KP1];     // A1 tiles [rb][chunk][16KB]
__device__ __nv_bfloat16 g_xl[ROWS_PAD * KP1];
__device__ __nv_bfloat16 g_o1h[ROWS_PAD * D1];     // A2 tiles
__device__ __nv_bfloat16 g_o1l[ROWS_PAD * D1];
__device__ __nv_bfloat16 g_b1h[D1 * KP1];          // B1 tiles [nb][chunk][16KB]
__device__ __nv_bfloat16 g_b1l[D1 * KP1];
__device__ __nv_bfloat16 g_b2h[HID * D1];          // B2 tiles
__device__ __nv_bfloat16 g_b2l[HID * D1];
__device__ float g_als1[N_NODES * HEADS1];
__device__ float g_ald1[N_NODES * HEADS1];
__device__ float g_als2[N_NODES];
__device__ float g_ald2[N_NODES];
__device__ int   g_counts[N_NODES];
__device__ int   g_offsets[N_NODES + 1];
__device__ int   g_cursor[N_NODES];
__device__ int   g_bsum[SCAN_NB];
__device__ int   g_src_sorted[E_TOT];
__device__ float g_alpha1[E_TOT * HEADS1];
__device__ float g_alpha2[E_TOT];
__device__ float g_pool[NUM_GRAPHS * HID];
__device__ int   g_cnt[NUM_GRAPHS];

// tiled byte-offset: tile = (row>>7)*nck + (k>>6); within: SW128 of (row&127)*128+(k&63)*2
__device__ __forceinline__ size_t tidx(int row, int k, int nck) {
    uint32_t byte = ((uint32_t)(row & 127)) * 128u + (uint32_t)(k & 63) * 2u;
    byte ^= (byte >> 3) & 0x70u;
    return ((size_t)((row >> 7) * nck + (k >> 6)) << 14) + byte;
}

// ---------------- PTX helpers ----------------------------------------------------
#if HAS_TC
__device__ __forceinline__ uint32_t smem_u32(const void* p) {
    uint32_t a;
    asm("{ .reg .u64 t; cvta.to.shared.u64 t, %1; cvt.u32.u64 %0, t; }" : "=r"(a) : "l"(p));
    return a;
}
__device__ __forceinline__ uint32_t elect_one() {
    uint32_t pred;
    asm volatile("{ .reg .pred p; elect.sync _|p, 0xFFFFFFFF; selp.b32 %0, 1, 0, p; }" : "=r"(pred));
    return pred;
}
#define MBAR_INIT(a, n)  asm volatile("mbarrier.init.shared.b64 [%0], %1;" :: "r"(a), "r"((uint32_t)(n)) : "memory")
#define MBAR_EXPECT(a, b) asm volatile("mbarrier.arrive.expect_tx.shared.b64 _, [%0], %1;" :: "r"(a), "r"((uint32_t)(b)) : "memory")
#define MBAR_WAIT(a, ph) do { \
    uint32_t _m = (a), _p = (ph), _d; \
    asm volatile("{ .reg .pred p; mbarrier.try_wait.parity.acquire.cta.shared::cta.b64 p, [%1], %2; selp.b32 %0,1,0,p; }" \
        : "=r"(_d) : "r"(_m), "r"(_p) : "memory"); \
    if (!_d) { \
        asm volatile("{ .reg .pred P1;\nWL_%=:\nmbarrier.try_wait.parity.acquire.cta.shared::cta.b64 P1, [%0], %1, 0x989680;\n@P1 bra.uni WD_%=;\nbra.uni WL_%=;\nWD_%=:\n}" \
            :: "r"(_m), "r"(_p) : "memory"); \
    } } while (0)
#define TC_ALLOC(sa, n)   asm volatile("tcgen05.alloc.cta_group::1.sync.aligned.shared::cta.b32 [%0], %1;" :: "r"(sa), "r"((uint32_t)(n)) : "memory")
#define TC_DEALLOC(t, n)  asm volatile("tcgen05.dealloc.cta_group::1.sync.aligned.b32 %0, %1;" :: "r"(t), "r"((uint32_t)(n)))
#define TC_RELINQ()       asm volatile("tcgen05.relinquish_alloc_permit.cta_group::1.sync.aligned;")
#define TC_COMMIT(a)      asm volatile("tcgen05.commit.cta_group::1.mbarrier::arrive::one.shared::cluster.b64 [%0];" :: "r"(a) : "memory")
#define TC_FENCE_AFTER()  asm volatile("tcgen05.fence::after_thread_sync;" ::: "memory")
#define TC_FENCE_BEFORE() asm volatile("tcgen05.fence::before_thread_sync;" ::: "memory")
#define TC_WAIT_LD()      asm volatile("tcgen05.wait::ld.sync.aligned;" ::: "memory")
#define BULK_CP(dst, src, sz, mbar) \
    asm volatile("cp.async.bulk.shared::cta.global.mbarrier::complete_tx::bytes [%0], [%1], %2, [%3];" \
                 :: "r"(dst), "l"(src), "r"((uint32_t)(sz)), "r"(mbar) : "memory")
#define PREF_L2(src, sz) \
    asm volatile("cp.async.bulk.prefetch.L2.global [%0], %1;" :: "l"(src), "r"((uint32_t)(sz)) : "memory")

__device__ __forceinline__ void mma_f16_ss(uint32_t d, uint64_t ad, uint64_t bd,
                                           uint32_t idesc, bool accum) {
    uint32_t en = accum ? 1u : 0u, z = 0u;
    asm volatile(
        "{ .reg .pred p; setp.ne.u32 p, %5, 0;\n\t"
        "tcgen05.mma.cta_group::1.kind::f16 [%0], %1, %2, %3, {%4,%4,%4,%4}, p; }"
        :: "r"(d), "l"(ad), "l"(bd), "r"(idesc), "r"(z), "r"(en) : "memory");
}
__device__ __forceinline__ void tmem_ld32(uint32_t* r, uint32_t addr) {
    asm volatile(
        "tcgen05.ld.sync.aligned.32x32b.x32.b32 "
        "{%0,%1,%2,%3,%4,%5,%6,%7,%8,%9,%10,%11,%12,%13,%14,%15,"
        "%16,%17,%18,%19,%20,%21,%22,%23,%24,%25,%26,%27,%28,%29,%30,%31}, [%32];"
        : "=r"(r[0]), "=r"(r[1]), "=r"(r[2]), "=r"(r[3]), "=r"(r[4]), "=r"(r[5]), "=r"(r[6]), "=r"(r[7]),
          "=r"(r[8]), "=r"(r[9]), "=r"(r[10]), "=r"(r[11]), "=r"(r[12]), "=r"(r[13]), "=r"(r[14]), "=r"(r[15]),
          "=r"(r[16]), "=r"(r[17]), "=r"(r[18]), "=r"(r[19]), "=r"(r[20]), "=r"(r[21]), "=r"(r[22]), "=r"(r[23]),
          "=r"(r[24]), "=r"(r[25]), "=r"(r[26]), "=r"(r[27]), "=r"(r[28]), "=r"(r[29]), "=r"(r[30]), "=r"(r[31])
        : "r"(addr));
}
#define DESC_SW128(addr) ((uint64_t(2) << 61) | (uint64_t(1) << 46) | (uint64_t(64) << 32) \
                          | (uint64_t(1) << 16) | ((uint64_t)((addr) >> 4) & 0x3FFF))
#endif // HAS_TC

// -------- tcgen05 bf16x3 GEMM, bulk tile loads + L2 prefetch, fused epilogue -------
// Tiled operands; per 64-K chunk: D += Ah*Bh + Al*Bh + Ah*Bl (12 MMAs, one commit).
template <int NT>
__global__ void __launch_bounds__(256)
gemm_tc(const __nv_bfloat16* __restrict__ Ah, const __nv_bfloat16* __restrict__ Al,
        const __nv_bfloat16* __restrict__ Bh, const __nv_bfloat16* __restrict__ Bl,
        float* __restrict__ C, int M, int ldc, int kp,
        const float* __restrict__ asrc, const float* __restrict__ adst,
        float* __restrict__ als, float* __restrict__ ald, int nheads)
{
#if HAS_TC
    extern __shared__ char dsm[];
    uint32_t sb = smem_u32(dsm);
    uint32_t base = (sb + 1023) & ~1023u;
    const uint32_t TM_PTR = base;
    const uint32_t MMABAR = base + 8;
    const uint32_t LBAR0  = base + 16;
    const uint32_t LBAR1  = base + 24;
    const uint32_t T0 = base + 1024;
    constexpr uint32_t ATILE = 16384;
    constexpr uint32_t BTILE = NT * 128;
    constexpr uint32_t OFF_AL = ATILE;
    constexpr uint32_t OFF_BH = 2 * ATILE;
    constexpr uint32_t OFF_BL = 2 * ATILE + BTILE;
    constexpr uint32_t BUFSZ  = 2 * ATILE + 2 * BTILE;
    constexpr uint32_t LOADB  = BUFSZ;

    int tid = threadIdx.x, wid = tid >> 5, lane = tid & 31;
    int rb = blockIdx.y;
    int m0 = rb * 128, n0 = blockIdx.x * NT;
    int nb0 = n0 >> 7;
    const int nck = kp >> 6;

    if (wid == 0) { TC_ALLOC(TM_PTR, NT); TC_RELINQ(); }
    if (tid == 0) {
        MBAR_INIT(MMABAR, 1);
        MBAR_INIT(LBAR0, 1);
        MBAR_INIT(LBAR1, 1);
    }
    __syncthreads();
    uint32_t tmem;
    asm volatile("ld.shared.b32 %0, [%1];" : "=r"(tmem) : "r"(TM_PTR));

    const char* cAh = (const char*)Ah;
    const char* cAl = (const char*)Al;
    const char* cBh = (const char*)Bh;
    const char* cBl = (const char*)Bl;

    const uint32_t IDESC = 0x8000490u | ((NT / 8) << 17);

    // issue SMEM loads for chunk c into buffer buf (single thread)
    auto issue = [&](int c, uint32_t buf, uint32_t lbar) {
        MBAR_EXPECT(lbar, LOADB);
        size_t aoff = ((size_t)(rb * nck + c)) << 14;
        BULK_CP(buf,          cAh + aoff, 16384, lbar);
        BULK_CP(buf + OFF_AL, cAl + aoff, 16384, lbar);
        size_t b0off = ((size_t)(nb0 * nck + c)) << 14;
        BULK_CP(buf + OFF_BH, cBh + b0off, 16384, lbar);
        BULK_CP(buf + OFF_BL, cBl + b0off, 16384, lbar);
        if (NT == 256) {
            size_t b1off = ((size_t)((nb0 + 1) * nck + c)) << 14;
            BULK_CP(buf + OFF_BH + 16384, cBh + b1off, 16384, lbar);
            BULK_CP(buf + OFF_BL + 16384, cBl + b1off, 16384, lbar);
        }
    };
    // prefetch chunk c's tiles to L2 (DRAM->L2 runs ahead of the SMEM pipeline)
    auto pref = [&](int c) {
        size_t aoff = ((size_t)(rb * nck + c)) << 14;
        PREF_L2(cAh + aoff, 16384);
        PREF_L2(cAl + aoff, 16384);
        size_t b0off = ((size_t)(nb0 * nck + c)) << 14;
        PREF_L2(cBh + b0off, 16384);
        PREF_L2(cBl + b0off, 16384);
        if (NT == 256) {
            size_t b1off = ((size_t)((nb0 + 1) * nck + c)) << 14;
            PREF_L2(cBh + b1off, 16384);
            PREF_L2(cBl + b1off, 16384);
        }
    };

    if (tid == 0) {
        issue(0, T0, LBAR0);
        if (1 < nck) pref(1);
        if (2 < nck) pref(2);
        if (3 < nck) pref(3);
    }

    for (int c = 0; c < nck; c++) {
        uint32_t buf = T0 + (c & 1) * BUFSZ;
        MBAR_WAIT((c & 1) ? LBAR1 : LBAR0, (c >> 1) & 1);
        if (wid == 0 && elect_one()) {
            uint64_t dAH = DESC_SW128(buf);
            uint64_t dAL = DESC_SW128(buf + OFF_AL);
            uint64_t dBH = DESC_SW128(buf + OFF_BH);
            uint64_t dBL = DESC_SW128(buf + OFF_BL);
#pragma unroll
            for (int k = 0; k < 4; k++) mma_f16_ss(tmem, dAH + 2 * k, dBH + 2 * k, IDESC, !(c == 0 && k == 0));
#pragma unroll
            for (int k = 0; k < 4; k++) mma_f16_ss(tmem, dAL + 2 * k, dBH + 2 * k, IDESC, true);
#pragma unroll
            for (int k = 0; k < 4; k++) mma_f16_ss(tmem, dAH + 2 * k, dBL + 2 * k, IDESC, true);
            TC_COMMIT(MMABAR);
        }
        if (tid == 0 && c + 1 < nck) {
            issue(c + 1, T0 + ((c + 1) & 1) * BUFSZ, ((c + 1) & 1) ? LBAR1 : LBAR0);
            if (c + 4 < nck) pref(c + 4);
        }
        MBAR_WAIT(MMABAR, c & 1);
    }

    TC_FENCE_AFTER();
    // epilogue: warps 0-3 read 32-row subpartitions; fused attention dots per head
    if (wid < 4) {
        int row = m0 + wid * 32 + lane;
#pragma unroll
        for (int hloc = 0; hloc < NT / 128; hloc++) {
            float s = 0.f, d = 0.f;
#pragma unroll
            for (int nb = 0; nb < 4; nb++) {
                int batch = hloc * 4 + nb;
                uint32_t rg[32];
                tmem_ld32(rg, tmem + batch * 32);
                TC_WAIT_LD();
                if (row < M) {
                    float4* dst = (float4*)(C + (size_t)row * ldc + n0 + batch * 32);
#pragma unroll
                    for (int i = 0; i < 8; i++)
                        dst[i] = make_float4(__uint_as_float(rg[4 * i]), __uint_as_float(rg[4 * i + 1]),
                                             __uint_as_float(rg[4 * i + 2]), __uint_as_float(rg[4 * i + 3]));
                }
#pragma unroll
                for (int i = 0; i < 32; i++) {
                    float v = __uint_as_float(rg[i]);
                    int col = n0 + batch * 32 + i;
                    s = fmaf(v, __ldg(&asrc[col]), s);
                    d = fmaf(v, __ldg(&adst[col]), d);
                }
            }
            if (row < M) {
                int head = n0 / 128 + hloc;
                als[(size_t)row * nheads + head] = s;
                ald[(size_t)row * nheads + head] = d;
            }
        }
        TC_FENCE_BEFORE();
    }
    __syncthreads();
    if (wid == 0) TC_DEALLOC(tmem, NT);
#endif
}

// ---------------- SIMT fallback (active only when !HAS_TC; reads tiled layout) -----
__global__ __launch_bounds__(256) void gemm_simt(
    const __nv_bfloat16* __restrict__ Ah, const __nv_bfloat16* __restrict__ Al,
    const __nv_bfloat16* __restrict__ Bh, const __nv_bfloat16* __restrict__ Bl,
    float* __restrict__ C, int M, int ldc, int kp)
{
#if !HAS_TC
    __shared__ float As[8][128];
    __shared__ float Bs[8][128];
    int tid = threadIdx.x;
    int tx = tid & 15, ty = tid >> 4;
    int rowBase = blockIdx.y * 128;
    int colBase = blockIdx.x * 128;
    int nck = kp >> 6;

    float acc[8][8];
#pragma unroll
    for (int i = 0; i < 8; i++)
#pragma unroll
        for (int j = 0; j < 8; j++) acc[i][j] = 0.f;

    for (int k0 = 0; k0 < kp; k0 += 8) {
#pragma unroll
        for (int i = 0; i < 4; i++) {
            int idx = tid + 256 * i;
            int rr = idx >> 3, cc = idx & 7;
            int gr = rowBase + rr;
            size_t o = tidx(gr, k0 + cc, nck);
            float v = __bfloat162float(*(const __nv_bfloat16*)((const char*)Ah + o))
                    + __bfloat162float(*(const __nv_bfloat16*)((const char*)Al + o));
            As[cc][rr] = v;
        }
#pragma unroll
        for (int i = 0; i < 4; i++) {
            int idx = tid + 256 * i;
            int nl = idx >> 3, kk = idx & 7;
            size_t o = tidx(colBase + nl, k0 + kk, nck);
            Bs[kk][nl] = __bfloat162float(*(const __nv_bfloat16*)((const char*)Bh + o))
                       + __bfloat162float(*(const __nv_bfloat16*)((const char*)Bl + o));
        }
        __syncthreads();
#pragma unroll
        for (int kk = 0; kk < 8; kk++) {
            float a[8], b[8];
#pragma unroll
            for (int i = 0; i < 8; i++) a[i] = As[kk][ty * 8 + i];
#pragma unroll
            for (int j = 0; j < 8; j++) b[j] = Bs[kk][tx * 8 + j];
#pragma unroll
            for (int i = 0; i < 8; i++)
#pragma unroll
                for (int j = 0; j < 8; j++) acc[i][j] = fmaf(a[i], b[j], acc[i][j]);
        }
        __syncthreads();
    }
#pragma unroll
    for (int i = 0; i < 8; i++) {
        int gr = rowBase + ty * 8 + i;
        if (gr >= M) continue;
#pragma unroll
        for (int j = 0; j < 8; j++)
            C[(size_t)gr * ldc + colBase + tx * 8 + j] = acc[i][j];
    }
#endif
}

// ---------------- conversions (write tiled+swizzled) ---------------------------
__global__ void cvt_w_kernel(const float* __restrict__ W1, const float* __restrict__ W2) {
    int idx = blockIdx.x * blockDim.x + threadIdx.x;
    const int n1 = D1 * KP1;
    if (idx < n1) {
        int n = idx / KP1, k = idx - n * KP1;
        float v = (k < IN_CH) ? W1[(size_t)k * D1 + n] : 0.f;
        __nv_bfloat16 hi = __float2bfloat16(v);
        size_t o = tidx(n, k, NCK1);
        *(__nv_bfloat16*)((char*)g_b1h + o) = hi;
        *(__nv_bfloat16*)((char*)g_b1l + o) = __float2bfloat16(v - __bfloat162float(hi));
        return;
    }
    int j = idx - n1;
    if (j < HID * D1) {
        int n = j / D1, k = j - n * D1;
        float v = W2[(size_t)k * HID + n];
        __nv_bfloat16 hi = __float2bfloat16(v);
        size_t o = tidx(n, k, NCK2);
        *(__nv_bfloat16*)((char*)g_b2h + o) = hi;
        *(__nv_bfloat16*)((char*)g_b2l + o) = __float2bfloat16(v - __bfloat162float(hi));
    }
}

__global__ void cvt_x_kernel(const float* __restrict__ x) {
    int idx = blockIdx.x * blockDim.x + threadIdx.x;
    if (idx >= ROWS_PAD * KP1) return;
    int row = idx / KP1, k = idx - row * KP1;
    float v = (row < N_NODES && k < IN_CH) ? x[(size_t)row * IN_CH + k] : 0.f;
    __nv_bfloat16 hi = __float2bfloat16(v);
    size_t o = tidx(row, k, NCK1);
    *(__nv_bfloat16*)((char*)g_xh + o) = hi;
    *(__nv_bfloat16*)((char*)g_xl + o) = __float2bfloat16(v - __bfloat162float(hi));
}

// ---------------- misc helpers -----------------------------------------------
__device__ __forceinline__ float warpMax(float v) {
#pragma unroll
    for (int o = 16; o > 0; o >>= 1) v = fmaxf(v, __shfl_xor_sync(0xffffffffu, v, o));
    return v;
}
__device__ __forceinline__ float warpSum(float v) {
#pragma unroll
    for (int o = 16; o > 0; o >>= 1) v += __shfl_xor_sync(0xffffffffu, v, o);
    return v;
}
__device__ __forceinline__ float lrelu(float x) { return x > 0.f ? x : NEG_SLOPE * x; }

__global__ void zero_kernel() {
    int i = blockIdx.x * blockDim.x + threadIdx.x;
    if (i < N_NODES) g_counts[i] = 0;
    if (i < NUM_GRAPHS * HID) g_pool[i] = 0.f;
    if (i < NUM_GRAPHS) g_cnt[i] = 0;
}

__global__ void hist_kernel(const int* __restrict__ ei) {
    int e = blockIdx.x * blockDim.x + threadIdx.x;
    if (e >= E_TOT) return;
    int dst = (e < N_EDGES) ? ei[N_EDGES + e] : (e - N_EDGES);
    atomicAdd(&g_counts[dst], 1);
}

__global__ void scan1_kernel() {
    __shared__ int sh[256];
    int b = blockIdx.x, tid = threadIdx.x;
    int i = b * 256 + tid;
    int v = (i < N_NODES) ? g_counts[i] : 0;
    sh[tid] = v;
    __syncthreads();
#pragma unroll
    for (int o = 1; o < 256; o <<= 1) {
        int t = (tid >= o) ? sh[tid - o] : 0;
        __syncthreads();
        sh[tid] += t;
        __syncthreads();
    }
    if (i < N_NODES) g_offsets[i] = sh[tid] - v;
    if (tid == 255) g_bsum[b] = sh[255];
}

__global__ void scan2_kernel() {
    __shared__ int sh[SCAN_NB];
    int tid = threadIdx.x;
    int v = (tid < SCAN_NB) ? g_bsum[tid] : 0;
    if (tid < SCAN_NB) sh[tid] = v;
    __syncthreads();
    for (int o = 1; o < SCAN_NB; o <<= 1) {
        int t = (tid >= o && tid < SCAN_NB) ? sh[tid - o] : 0;
        __syncthreads();
        if (tid < SCAN_NB) sh[tid] += t;
        __syncthreads();
    }
    if (tid < SCAN_NB) g_bsum[tid] = sh[tid] - v;
    if (tid == 0) g_offsets[N_NODES] = E_TOT;
}

__global__ void scan3_kernel() {
    int b = blockIdx.x, tid = threadIdx.x;
    int i = b * 256 + tid;
    if (i >= N_NODES) return;
    int off = g_offsets[i] + g_bsum[b];
    g_offsets[i] = off;
    g_cursor[i] = off;
}

__global__ void scatter_kernel(const int* __restrict__ ei) {
    int e = blockIdx.x * blockDim.x + threadIdx.x;
    if (e >= E_TOT) return;
    int src, dst;
    if (e < N_EDGES) { src = ei[e]; dst = ei[N_EDGES + e]; }
    else             { src = e - N_EDGES; dst = src; }
    int pos = atomicAdd(&g_cursor[dst], 1);
    g_src_sorted[pos] = src;
}

// ---------------- attention coefficients (fallback only) ---------------------------
__global__ void att_coef1(const float* __restrict__ a_src, const float* __restrict__ a_dst) {
#if !HAS_TC
    int gw = (blockIdx.x * blockDim.x + threadIdx.x) >> 5;
    int lane = threadIdx.x & 31;
    if (gw >= N_NODES) return;
    const float* row = g_h1 + (size_t)gw * D1;
    float s[4] = {0, 0, 0, 0}, d[4] = {0, 0, 0, 0};
#pragma unroll
    for (int j = 0; j < 16; j++) {
        int c = lane + 32 * j;
        float v = row[c];
        s[j >> 2] = fmaf(v, a_src[c], s[j >> 2]);
        d[j >> 2] = fmaf(v, a_dst[c], d[j >> 2]);
    }
#pragma unroll
    for (int h = 0; h < 4; h++) { s[h] = warpSum(s[h]); d[h] = warpSum(d[h]); }
    if (lane == 0) {
#pragma unroll
        for (int h = 0; h < 4; h++) {
            g_als1[gw * 4 + h] = s[h];
            g_ald1[gw * 4 + h] = d[h];
        }
    }
#endif
}

__global__ void att_coef2(const float* __restrict__ a_src, const float* __restrict__ a_dst) {
#if !HAS_TC
    int gw = (blockIdx.x * blockDim.x + threadIdx.x) >> 5;
    int lane = threadIdx.x & 31;
    if (gw >= N_NODES) return;
    const float* row = g_h2 + (size_t)gw * HID;
    float s = 0.f, d = 0.f;
#pragma unroll
    for (int j = 0; j < 4; j++) {
        int c = lane + 32 * j;
        float v = row[c];
        s = fmaf(v, a_src[c], s);
        d = fmaf(v, a_dst[c], d);
    }
    s = warpSum(s); d = warpSum(d);
    if (lane == 0) { g_als2[gw] = s; g_ald2[gw] = d; }
#endif
}

// ---------------- GAT layer 1 softmax + aggregate (warp per dst node) ------------
__global__ __launch_bounds__(256) void gat_agg1(const float* __restrict__ b1) {
    int gw = (blockIdx.x * blockDim.x + threadIdx.x) >> 5;
    int lane = threadIdx.x & 31;
    if (gw >= N_NODES) return;
    int beg = g_offsets[gw], end = g_offsets[gw + 1];

    float ald[4];
#pragma unroll
    for (int h = 0; h < 4; h++) ald[h] = g_ald1[gw * 4 + h];

    float mx[4] = {-1e30f, -1e30f, -1e30f, -1e30f};
    for (int i = beg + lane; i < end; i += 32) {
        int s = g_src_sorted[i];
#pragma unroll
        for (int h = 0; h < 4; h++) {
            float e = lrelu(g_als1[s * 4 + h] + ald[h]);
            mx[h] = fmaxf(mx[h], e);
        }
    }
#pragma unroll
    for (int h = 0; h < 4; h++) mx[h] = warpMax(mx[h]);

    float sm[4] = {0, 0, 0, 0};
    for (int i = beg + lane; i < end; i += 32) {
        int s = g_src_sorted[i];
        float4 ex4;
        float* exv = (float*)&ex4;
#pragma unroll
        for (int h = 0; h < 4; h++) {
            float e = lrelu(g_als1[s * 4 + h] + ald[h]);
            float ex = __expf(e - mx[h]);
            exv[h] = ex;
            sm[h] += ex;
        }
        ((float4*)g_alpha1)[i] = ex4;
    }
#pragma unroll
    for (int h = 0; h < 4; h++) sm[h] = warpSum(sm[h]);
    float inv[4];
#pragma unroll
    for (int h = 0; h < 4; h++) inv[h] = 1.f / sm[h];
    __syncwarp();

    float acc[16];
#pragma unroll
    for (int j = 0; j < 16; j++) acc[j] = 0.f;
    int i = beg;
    for (; i + 3 < end; i += 4) {
        int s0 = g_src_sorted[i],     s1 = g_src_sorted[i + 1];
        int s2 = g_src_sorted[i + 2], s3 = g_src_sorted[i + 3];
        float4 a0 = ((const float4*)g_alpha1)[i];
        float4 a1 = ((const float4*)g_alpha1)[i + 1];
        float4 a2 = ((const float4*)g_alpha1)[i + 2];
        float4 a3 = ((const float4*)g_alpha1)[i + 3];
        const float* h0 = g_h1 + (size_t)s0 * D1;
        const float* h1p = g_h1 + (size_t)s1 * D1;
        const float* h2p = g_h1 + (size_t)s2 * D1;
        const float* h3p = g_h1 + (size_t)s3 * D1;
#pragma unroll
        for (int j = 0; j < 16; j++) {
            int c = lane + 32 * j;
            float aa0 = (j < 4) ? a0.x : (j < 8) ? a0.y : (j < 12) ? a0.z : a0.w;
            float aa1 = (j < 4) ? a1.x : (j < 8) ? a1.y : (j < 12) ? a1.z : a1.w;
            float aa2 = (j < 4) ? a2.x : (j < 8) ? a2.y : (j < 12) ? a2.z : a2.w;
            float aa3 = (j < 4) ? a3.x : (j < 8) ? a3.y : (j < 12) ? a3.z : a3.w;
            acc[j] = fmaf(aa0, h0[c], acc[j]);
            acc[j] = fmaf(aa1, h1p[c], acc[j]);
            acc[j] = fmaf(aa2, h2p[c], acc[j]);
            acc[j] = fmaf(aa3, h3p[c], acc[j]);
        }
    }
    for (; i < end; i++) {
        int s0 = g_src_sorted[i];
        float4 a0 = ((const float4*)g_alpha1)[i];
        const float* h0 = g_h1 + (size_t)s0 * D1;
#pragma unroll
        for (int j = 0; j < 16; j++) {
            float aa0 = (j < 4) ? a0.x : (j < 8) ? a0.y : (j < 12) ? a0.z : a0.w;
            acc[j] = fmaf(aa0, h0[lane + 32 * j], acc[j]);
        }
    }
#pragma unroll
    for (int j = 0; j < 16; j++) {
        int c = lane + 32 * j;
        float v = fmaxf(acc[j] * inv[j >> 2] + b1[c], 0.f);
        __nv_bfloat16 hi = __float2bfloat16(v);
        size_t o = tidx(gw, c, NCK2);
        *(__nv_bfloat16*)((char*)g_o1h + o) = hi;
        *(__nv_bfloat16*)((char*)g_o1l + o) = __float2bfloat16(v - __bfloat162float(hi));
    }
}

// ---------------- GAT layer 2 ----------------------------------------------------
__global__ __launch_bounds__(256) void gat_agg2(const float* __restrict__ b2) {
    int gw = (blockIdx.x * blockDim.x + threadIdx.x) >> 5;
    int lane = threadIdx.x & 31;
    if (gw >= N_NODES) return;
    int beg = g_offsets[gw], end = g_offsets[gw + 1];
    float ald = g_ald2[gw];

    float mx = -1e30f;
    for (int i = beg + lane; i < end; i += 32)
        mx = fmaxf(mx, lrelu(g_als2[g_src_sorted[i]] + ald));
    mx = warpMax(mx);

    float sm = 0.f;
    for (int i = beg + lane; i < end; i += 32) {
        float e = lrelu(g_als2[g_src_sorted[i]] + ald);
        float ex = __expf(e - mx);
        g_alpha2[i] = ex;
        sm += ex;
    }
    sm = warpSum(sm);
    float inv = 1.f / sm;
    __syncwarp();

    float acc[4] = {0, 0, 0, 0};
    int i = beg;
    for (; i + 3 < end; i += 4) {
        int s0 = g_src_sorted[i],     s1 = g_src_sorted[i + 1];
        int s2 = g_src_sorted[i + 2], s3 = g_src_sorted[i + 3];
        float a0 = g_alpha2[i],     a1 = g_alpha2[i + 1];
        float a2 = g_alpha2[i + 2], a3 = g_alpha2[i + 3];
        const float* h0 = g_h2 + (size_t)s0 * HID;
        const float* h1p = g_h2 + (size_t)s1 * HID;
        const float* h2p = g_h2 + (size_t)s2 * HID;
        const float* h3p = g_h2 + (size_t)s3 * HID;
#pragma unroll
        for (int j = 0; j < 4; j++) {
            int c = lane + 32 * j;
            acc[j] = fmaf(a0, h0[c], acc[j]);
            acc[j] = fmaf(a1, h1p[c], acc[j]);
            acc[j] = fmaf(a2, h2p[c], acc[j]);
            acc[j] = fmaf(a3, h3p[c], acc[j]);
        }
    }
    for (; i < end; i++) {
        int s0 = g_src_sorted[i];
        float a0 = g_alpha2[i];
        const float* h0 = g_h2 + (size_t)s0 * HID;
#pragma unroll
        for (int j = 0; j < 4; j++)
            acc[j] = fmaf(a0, h0[lane + 32 * j], acc[j]);
    }
#pragma unroll
    for (int j = 0; j < 4; j++) {
        int c = lane + 32 * j;
        float v = acc[j] * inv + b2[c];
        g_out2[(size_t)gw * HID + c] = fmaxf(v, 0.f);
    }
}

// ---------------- global mean pool -----------------------------------------------
__global__ void pool_kernel(const int* __restrict__ batch) {
    int gw = (blockIdx.x * blockDim.x + threadIdx.x) >> 5;
    int lane = threadIdx.x & 31;
    if (gw >= N_NODES) return;
    int g = batch[gw];
#pragma unroll
    for (int j = 0; j < 4; j++) {
        int c = lane + 32 * j;
        atomicAdd(&g_pool[g * HID + c], g_out2[(size_t)gw * HID + c]);
    }
    if (lane == 0) atomicAdd(&g_cnt[g], 1);
}

// ---------------- MLP head ---------------------------------------------------------
__global__ __launch_bounds__(1024) void mlp_kernel(
    const float* __restrict__ fc1_w, const float* __restrict__ fc1_b,
    const float* __restrict__ fc2_w, const float* __restrict__ fc2_b,
    float* __restrict__ out)
{
    __shared__ float pooled[NUM_GRAPHS * HID];
    __shared__ float z[NUM_GRAPHS * 64];
    int tid = threadIdx.x;
    for (int i = tid; i < NUM_GRAPHS * HID; i += blockDim.x) {
        int g = i / HID;
        float c = fmaxf((float)g_cnt[g], 1.f);
        pooled[i] = g_pool[i] / c;
    }
    __syncthreads();
    for (int i = tid; i < NUM_GRAPHS * 64; i += blockDim.x) {
        int g = i >> 6, j = i & 63;
        float acc = fc1_b[j];
        for (int k = 0; k < HID; k++)
            acc = fmaf(pooled[g * HID + k], fc1_w[k * 64 + j], acc);
        z[i] = fmaxf(acc, 0.f);
    }
    __syncthreads();
    for (int i = tid; i < NUM_GRAPHS * NUM_CLASSES; i += blockDim.x) {
        int g = i / NUM_CLASSES, c = i % NUM_CLASSES;
        float acc = fc2_b[c];
        for (int j = 0; j < 64; j++)
            acc = fmaf(z[g * 64 + j], fc2_w[j * NUM_CLASSES + c], acc);
        out[i] = acc;
    }
}

// ---------------- launch -------------------------------------------------------------
extern "C" void kernel_launch(void* const* d_in, const int* in_sizes, int n_in,
                              void* d_out, int out_size) {
    const float* x       = (const float*)d_in[0];
    const int*   ei      = (const int*)  d_in[1];
    const int*   batch   = (const int*)  d_in[2];
    const float* W1      = (const float*)d_in[3];
    const float* a_src1  = (const float*)d_in[4];
    const float* a_dst1  = (const float*)d_in[5];
    const float* b1      = (const float*)d_in[6];
    const float* W2      = (const float*)d_in[7];
    const float* a_src2  = (const float*)d_in[8];
    const float* a_dst2  = (const float*)d_in[9];
    const float* b2      = (const float*)d_in[10];
    const float* fc1_w   = (const float*)d_in[11];
    const float* fc1_b   = (const float*)d_in[12];
    const float* fc2_w   = (const float*)d_in[13];
    const float* fc2_b   = (const float*)d_in[14];
    float* out = (float*)d_out;

    static float *p_h1, *p_h2, *p_als1, *p_ald1, *p_als2, *p_ald2;
    static __nv_bfloat16 *p_xh, *p_xl, *p_o1h, *p_o1l, *p_b1h, *p_b1l, *p_b2h, *p_b2l;
    static bool inited = false;
    if (!inited) {
        cudaGetSymbolAddress((void**)&p_h1,   g_h1);
        cudaGetSymbolAddress((void**)&p_h2,   g_h2);
        cudaGetSymbolAddress((void**)&p_als1, g_als1);
        cudaGetSymbolAddress((void**)&p_ald1, g_ald1);
        cudaGetSymbolAddress((void**)&p_als2, g_als2);
        cudaGetSymbolAddress((void**)&p_ald2, g_ald2);
        cudaGetSymbolAddress((void**)&p_xh,  g_xh);
        cudaGetSymbolAddress((void**)&p_xl,  g_xl);
        cudaGetSymbolAddress((void**)&p_o1h, g_o1h);
        cudaGetSymbolAddress((void**)&p_o1l, g_o1l);
        cudaGetSymbolAddress((void**)&p_b1h, g_b1h);
        cudaGetSymbolAddress((void**)&p_b1l, g_b1l);
        cudaGetSymbolAddress((void**)&p_b2h, g_b2h);
        cudaGetSymbolAddress((void**)&p_b2l, g_b2l);
        cudaFuncSetAttribute(gemm_tc<256>, cudaFuncAttributeMaxDynamicSharedMemorySize, 199680);
        cudaFuncSetAttribute(gemm_tc<128>, cudaFuncAttributeMaxDynamicSharedMemorySize, 133632);
        inited = true;
    }

    // index 0..2: conversions (GEMM1 deps only)
    cvt_w_kernel<<<(D1 * KP1 + HID * D1 + 255) / 256, 256>>>(W1, W2);
    cvt_x_kernel<<<(ROWS_PAD * KP1 + 255) / 256, 256>>>(x);
    zero_kernel<<<(N_NODES + 255) / 256, 256>>>();

    // index 3: GEMM1 (profiled): h1 = x @ W1 + fused attention coefs
    {
        dim3 grid(D1 / 256, RB_CNT);
        gemm_tc<256><<<grid, 256, 199680>>>(p_xh, p_xl, p_b1h, p_b1l, p_h1, N_NODES, D1, KP1,
                                            a_src1, a_dst1, p_als1, p_ald1, HEADS1);
    }
    {
        dim3 grid(D1 / 128, RB_CNT);
        gemm_simt<<<grid, 256>>>(p_xh, p_xl, p_b1h, p_b1l, p_h1, N_NODES, D1, KP1);
        att_coef1<<<(N_NODES * 32 + 255) / 256, 256>>>(a_src1, a_dst1);  // no-op on TC path
    }

    // CSR build (needed before gat_agg1)
    hist_kernel<<<(E_TOT + 255) / 256, 256>>>(ei);
    scan1_kernel<<<SCAN_NB, 256>>>();
    scan2_kernel<<<1, 256>>>();
    scan3_kernel<<<SCAN_NB, 256>>>();
    scatter_kernel<<<(E_TOT + 255) / 256, 256>>>(ei);

    gat_agg1<<<(N_NODES * 32 + 255) / 256, 256>>>(b1);

    // GEMM2: h2 = out1 @ W2 + fused attention coefs
    {
        dim3 grid(HID / 128, RB_CNT);
        gemm_tc<128><<<grid, 256, 133632>>>(p_o1h, p_o1l, p_b2h, p_b2l, p_h2, N_NODES, HID, D1,
                                            a_src2, a_dst2, p_als2, p_ald2, 1);
        gemm_simt<<<grid, 256>>>(p_o1h, p_o1l, p_b2h, p_b2l, p_h2, N_NODES, HID, D1);
        att_coef2<<<(N_NODES * 32 + 255) / 256, 256>>>(a_src2, a_dst2);  // no-op on TC path
    }
    gat_agg2<<<(N_NODES * 32 + 255) / 256, 256>>>(b2);

    pool_kernel<<<(N_NODES * 32 + 255) / 256, 256>>>(batch);
    mlp_kernel<<<1, 1024>>>(fc1_w, fc1_b, fc2_w, fc2_b, out);
}